// round 2
// baseline (speedup 1.0000x reference)
#include <cuda_runtime.h>
#include <cstdint>

#define BB 16
#define NN 4096
#define SS 1024
#define KK 32
#define C1 67
#define CNT_BN 524288.0

// ---------------- device scratch (no allocation allowed) ----------------
__device__ __align__(16) float  g_u[BB * NN * 64];              // 16.8 MB
__device__ __align__(16) float  g_v[BB * SS * 64];              // 4.2 MB
__device__            int       g_idx[BB * SS * KK];            // 2 MB
__device__ __align__(16) float  g_y2[(size_t)BB * SS * KK * 64];// 134 MB
__device__ __align__(16) float  g_ymax[BB * SS * 128];          // 8.4 MB
__device__            double    g_stats[512];  // L1: sum@0 sq@64 | L2: 128/192 | L3: 256/384
__device__            float     g_bn[512];     // a1@0 c1@64 | a2@128 c2@192 | a3@256 c3@384

// ---------------- 0: zero stat accumulators (graph replays) ----------------
__global__ void zero_stats_kernel() {
    int t = threadIdx.x;
    if (t < 512) g_stats[t] = 0.0;
}

// ---------------- 1: farthest point sampling ----------------
__global__ void fps_kernel(const float* __restrict__ xyz, float* __restrict__ out_xyz) {
    int b = blockIdx.x;
    int tid = threadIdx.x;
    int lane = tid & 31, wid = tid >> 5;
    __shared__ float sc[3];
    __shared__ unsigned smax[16];
    __shared__ int sidx[16];

    const float* xb = xyz + (size_t)b * NN * 3;
    float px[8], py[8], pz[8], dist[8];
    int base = tid * 8;
#pragma unroll
    for (int j = 0; j < 8; j++) {
        px[j] = xb[(base + j) * 3 + 0];
        py[j] = xb[(base + j) * 3 + 1];
        pz[j] = xb[(base + j) * 3 + 2];
        dist[j] = 1e10f;
    }
    if (tid == 0) {
        sc[0] = xb[0]; sc[1] = xb[1]; sc[2] = xb[2];
        float* op = out_xyz + (size_t)b * SS * 3;
        op[0] = xb[0]; op[1] = xb[1]; op[2] = xb[2];
    }
    __syncthreads();

    for (int i = 0; i < SS - 1; i++) {
        float cx = sc[0], cy = sc[1], cz = sc[2];
        float lmax = -1.0f; int lidx = 0;
#pragma unroll
        for (int j = 0; j < 8; j++) {
            float dx = __fsub_rn(px[j], cx);
            float dy = __fsub_rn(py[j], cy);
            float dz = __fsub_rn(pz[j], cz);
            float d = __fadd_rn(__fadd_rn(__fmul_rn(dx, dx), __fmul_rn(dy, dy)),
                                __fmul_rn(dz, dz));
            float nd = fminf(dist[j], d);
            dist[j] = nd;
            if (nd > lmax) { lmax = nd; lidx = base + j; }   // first-index tie-break
        }
        unsigned mb = __float_as_uint(lmax);                 // dist >= 0 -> bit-monotone
        unsigned wm = __reduce_max_sync(0xffffffffu, mb);
        int cand = (mb == wm) ? lidx : 0x7fffffff;
        int wi = __reduce_min_sync(0xffffffffu, cand);
        if (lane == 0) { smax[wid] = wm; sidx[wid] = wi; }
        __syncthreads();
        if (wid == 0) {
            unsigned vb = (lane < 16) ? smax[lane] : 0u;
            int vi = (lane < 16) ? sidx[lane] : 0x7fffffff;
            unsigned m2 = __reduce_max_sync(0xffffffffu, vb);
            int c2 = (vb == m2) ? vi : 0x7fffffff;
            int far = __reduce_min_sync(0xffffffffu, c2);
            if (lane == 0) {
                const float* cp = xb + (size_t)far * 3;
                float nx = cp[0], ny = cp[1], nz = cp[2];
                sc[0] = nx; sc[1] = ny; sc[2] = nz;
                float* op = out_xyz + ((size_t)b * SS + i + 1) * 3;
                op[0] = nx; op[1] = ny; op[2] = nz;
            }
        }
        __syncthreads();
    }
}

// ---------------- 2: per-point conv1 partial u = W1 * [xyz; feat] ----------------
__global__ void u_kernel(const float* __restrict__ xyz, const float* __restrict__ pts,
                         const float* __restrict__ w1) {
    __shared__ __align__(16) float ws[C1][64];
    __shared__ __align__(16) float xin[64][68];
    int tid = threadIdx.x;
    int p0 = blockIdx.x * 64;
    for (int i = tid; i < C1 * 64; i += 256) {
        int o = i / C1, c = i % C1;
        ws[c][o] = w1[i];
    }
    for (int i = tid; i < 64 * C1; i += 256) {
        int p = i / C1, c = i % C1;
        int pt = p0 + p;
        xin[p][c] = (c < 3) ? xyz[(size_t)pt * 3 + c] : pts[(size_t)pt * 64 + (c - 3)];
    }
    __syncthreads();
    int wid = tid >> 5, lane = tid & 31, jb = wid * 8;
    float acc0[8], acc1[8];
#pragma unroll
    for (int j = 0; j < 8; j++) { acc0[j] = 0.f; acc1[j] = 0.f; }
    for (int c = 0; c < 64; c += 4) {
        float2 w0 = ((const float2*)ws[c + 0])[lane];
        float2 w1v = ((const float2*)ws[c + 1])[lane];
        float2 w2v = ((const float2*)ws[c + 2])[lane];
        float2 w3v = ((const float2*)ws[c + 3])[lane];
#pragma unroll
        for (int j = 0; j < 8; j++) {
            float4 h = *(const float4*)&xin[jb + j][c];
            acc0[j] = fmaf(h.x, w0.x, acc0[j]);  acc1[j] = fmaf(h.x, w0.y, acc1[j]);
            acc0[j] = fmaf(h.y, w1v.x, acc0[j]); acc1[j] = fmaf(h.y, w1v.y, acc1[j]);
            acc0[j] = fmaf(h.z, w2v.x, acc0[j]); acc1[j] = fmaf(h.z, w2v.y, acc1[j]);
            acc0[j] = fmaf(h.w, w3v.x, acc0[j]); acc1[j] = fmaf(h.w, w3v.y, acc1[j]);
        }
    }
    for (int c = 64; c < C1; c++) {
        float2 wv = ((const float2*)ws[c])[lane];
#pragma unroll
        for (int j = 0; j < 8; j++) {
            float h = xin[jb + j][c];
            acc0[j] = fmaf(h, wv.x, acc0[j]);
            acc1[j] = fmaf(h, wv.y, acc1[j]);
        }
    }
#pragma unroll
    for (int j = 0; j < 8; j++) {
        float2 st; st.x = acc0[j]; st.y = acc1[j];
        ((float2*)(g_u + (size_t)(p0 + jb + j) * 64))[lane] = st;
    }
}

// ---------------- 3: per-centroid partial v = b1 - W1[:, :3] * c ----------------
__global__ void v_kernel(const float* __restrict__ newxyz, const float* __restrict__ w1,
                         const float* __restrict__ b1) {
    int i = blockIdx.x * 256 + threadIdx.x;   // BB*SS*64 = 1048576
    int o = i & 63, g = i >> 6;
    const float* c = newxyz + (size_t)g * 3;
    const float* wr = w1 + (size_t)o * C1;
    g_v[i] = b1[o] - (wr[0] * c[0] + wr[1] * c[1] + wr[2] * c[2]);
}

// ---------------- 4: ball query (warp per centroid) ----------------
__global__ void ballq_kernel(const float* __restrict__ xyz, const float* __restrict__ newxyz) {
    int gw = blockIdx.x * 8 + (threadIdx.x >> 5);
    int lane = threadIdx.x & 31;
    int b = gw >> 10;
    const float* cp = newxyz + (size_t)gw * 3;
    float sx = cp[0], sy = cp[1], sz = cp[2];
    float sn = __fadd_rn(__fadd_rn(__fmul_rn(sx, sx), __fmul_rn(sy, sy)), __fmul_rn(sz, sz));
    const float* xb = xyz + (size_t)b * NN * 3;
    const float R2 = (float)(0.2 * 0.2);
    int cnt = 0, first = -1;
    int* op = g_idx + (size_t)gw * KK;
    for (int basep = 0; basep < NN && cnt < KK; basep += 32) {
        int n = basep + lane;
        float nx = xb[n * 3 + 0], ny = xb[n * 3 + 1], nz = xb[n * 3 + 2];
        float dn = __fadd_rn(__fadd_rn(__fmul_rn(nx, nx), __fmul_rn(ny, ny)), __fmul_rn(nz, nz));
        float dt = __fadd_rn(__fadd_rn(__fmul_rn(sx, nx), __fmul_rn(sy, ny)), __fmul_rn(sz, nz));
        float sqr = __fadd_rn(__fadd_rn(__fmul_rn(-2.0f, dt), sn), dn);
        bool ok = !(sqr > R2);
        unsigned bal = __ballot_sync(0xffffffffu, ok);
        if (first < 0 && bal) first = basep + (__ffs(bal) - 1);
        int pos = cnt + __popc(bal & ((1u << lane) - 1u));
        if (ok && pos < KK) op[pos] = n;
        cnt += __popc(bal);
    }
    for (int s = cnt + lane; s < KK; s += 32) op[s] = first;
}

// ---------------- 5: BN1 statistics over y1 = u[idx] + v ----------------
__global__ void stats1_kernel() {
    __shared__ float red[2][4][64];
    int tid = threadIdx.x;
    int o = tid & 63, q = tid >> 6;
    int inst0 = blockIdx.x * 256 + q * 64;
    float s = 0.f, ss = 0.f;
    for (int ii = 0; ii < 64; ii++) {
        int inst = inst0 + ii;
        int g = inst >> 5;
        int b = g >> 10;
        int pt = g_idx[inst];
        float y = g_u[(((size_t)b << 12) + pt) * 64 + o] + g_v[(size_t)g * 64 + o];
        s += y;
        ss = fmaf(y, y, ss);
    }
    red[0][q][o] = s; red[1][q][o] = ss;
    __syncthreads();
    if (tid < 64) {
        double ds = (double)red[0][0][tid] + red[0][1][tid] + red[0][2][tid] + red[0][3][tid];
        double dq = (double)red[1][0][tid] + red[1][1][tid] + red[1][2][tid] + red[1][3][tid];
        atomicAdd(&g_stats[0 + tid], ds);
        atomicAdd(&g_stats[64 + tid], dq);
    }
}

// ---------------- BN params: a = g*rsqrt(var+eps), c = beta - mean*a ----------------
__global__ void bnp_kernel(const float* __restrict__ gamma, const float* __restrict__ beta,
                           int nch, int stats_off, int bn_off) {
    int o = threadIdx.x;
    if (o >= nch) return;
    double mean = g_stats[stats_off + o] / CNT_BN;
    double var = g_stats[stats_off + nch + o] / CNT_BN - mean * mean;
    double a = (double)gamma[o] / sqrt(var + 1e-5);
    g_bn[bn_off + o] = (float)a;
    g_bn[bn_off + nch + o] = (float)((double)beta[o] - mean * a);
}

// ---------------- 6: layer 2 (x2 = relu(BN1(y1)); y2 = W2 x2 + b2; stats2) ----------------
__global__ void layer2_kernel(const float* __restrict__ w2, const float* __restrict__ b2) {
    __shared__ __align__(16) float ws[64][64];
    __shared__ __align__(16) float xin[64][64];
    __shared__ float ssum[64], ssq[64];
    int tid = threadIdx.x;
    int p0 = blockIdx.x * 64;
    for (int i = tid; i < 4096; i += 256) {
        int o = i >> 6, c = i & 63;
        ws[c][o] = w2[i];
    }
    if (tid < 64) { ssum[tid] = 0.f; ssq[tid] = 0.f; }
    for (int i = tid; i < 4096; i += 256) {
        int p = i >> 6, c = i & 63;
        int inst = p0 + p;
        int g = inst >> 5;
        int b = g >> 10;
        int pt = g_idx[inst];
        float y = g_u[(((size_t)b << 12) + pt) * 64 + c] + g_v[(size_t)g * 64 + c];
        xin[p][c] = fmaxf(fmaf(g_bn[c], y, g_bn[64 + c]), 0.f);
    }
    __syncthreads();
    int wid = tid >> 5, lane = tid & 31, jb = wid * 8;
    float2 bb = ((const float2*)b2)[lane];
    float acc0[8], acc1[8];
#pragma unroll
    for (int j = 0; j < 8; j++) { acc0[j] = bb.x; acc1[j] = bb.y; }
    for (int c = 0; c < 64; c += 4) {
        float2 w0 = ((const float2*)ws[c + 0])[lane];
        float2 w1v = ((const float2*)ws[c + 1])[lane];
        float2 w2v = ((const float2*)ws[c + 2])[lane];
        float2 w3v = ((const float2*)ws[c + 3])[lane];
#pragma unroll
        for (int j = 0; j < 8; j++) {
            float4 h = *(const float4*)&xin[jb + j][c];
            acc0[j] = fmaf(h.x, w0.x, acc0[j]);  acc1[j] = fmaf(h.x, w0.y, acc1[j]);
            acc0[j] = fmaf(h.y, w1v.x, acc0[j]); acc1[j] = fmaf(h.y, w1v.y, acc1[j]);
            acc0[j] = fmaf(h.z, w2v.x, acc0[j]); acc1[j] = fmaf(h.z, w2v.y, acc1[j]);
            acc0[j] = fmaf(h.w, w3v.x, acc0[j]); acc1[j] = fmaf(h.w, w3v.y, acc1[j]);
        }
    }
    float s0 = 0.f, s1 = 0.f, q0 = 0.f, q1 = 0.f;
#pragma unroll
    for (int j = 0; j < 8; j++) {
        float2 st; st.x = acc0[j]; st.y = acc1[j];
        ((float2*)(g_y2 + (size_t)(p0 + jb + j) * 64))[lane] = st;
        s0 += st.x; s1 += st.y;
        q0 = fmaf(st.x, st.x, q0); q1 = fmaf(st.y, st.y, q1);
    }
    atomicAdd(&ssum[2 * lane], s0);     atomicAdd(&ssum[2 * lane + 1], s1);
    atomicAdd(&ssq[2 * lane], q0);      atomicAdd(&ssq[2 * lane + 1], q1);
    __syncthreads();
    if (tid < 64) {
        atomicAdd(&g_stats[128 + tid], (double)ssum[tid]);
        atomicAdd(&g_stats[192 + tid], (double)ssq[tid]);
    }
}

// ---------------- 7: layer 3 (x3 = relu(BN2(y2)); y3 = W3 x3 + b3; stats3; max over k) ----------------
__global__ void layer3_kernel(const float* __restrict__ w3, const float* __restrict__ b3) {
    __shared__ __align__(16) float ws[64][128];
    __shared__ __align__(16) float xin[32][64];
    __shared__ float ssum[128], ssq[128], smax[4][128];
    int tid = threadIdx.x;
    int g = blockIdx.x;
    for (int i = tid; i < 8192; i += 256) {
        int o = i >> 6, c = i & 63;
        ws[c][o] = w3[i];
    }
    if (tid < 128) { ssum[tid] = 0.f; ssq[tid] = 0.f; }
    for (int i = tid; i < 2048; i += 256) {
        int k = i >> 6, c = i & 63;
        float y = g_y2[((size_t)g * 32 + k) * 64 + c];
        xin[k][c] = fmaxf(fmaf(g_bn[128 + c], y, g_bn[192 + c]), 0.f);
    }
    __syncthreads();
    int o2 = tid & 63, pg = tid >> 6, kb = pg * 8;
    float2 bb = ((const float2*)b3)[o2];
    float acc0[8], acc1[8];
#pragma unroll
    for (int j = 0; j < 8; j++) { acc0[j] = bb.x; acc1[j] = bb.y; }
    for (int c = 0; c < 64; c += 4) {
        float2 w0 = ((const float2*)ws[c + 0])[o2];
        float2 w1v = ((const float2*)ws[c + 1])[o2];
        float2 w2v = ((const float2*)ws[c + 2])[o2];
        float2 w3v = ((const float2*)ws[c + 3])[o2];
#pragma unroll
        for (int j = 0; j < 8; j++) {
            float4 h = *(const float4*)&xin[kb + j][c];
            acc0[j] = fmaf(h.x, w0.x, acc0[j]);  acc1[j] = fmaf(h.x, w0.y, acc1[j]);
            acc0[j] = fmaf(h.y, w1v.x, acc0[j]); acc1[j] = fmaf(h.y, w1v.y, acc1[j]);
            acc0[j] = fmaf(h.z, w2v.x, acc0[j]); acc1[j] = fmaf(h.z, w2v.y, acc1[j]);
            acc0[j] = fmaf(h.w, w3v.x, acc0[j]); acc1[j] = fmaf(h.w, w3v.y, acc1[j]);
        }
    }
    float m0 = -1e30f, m1 = -1e30f, s0 = 0.f, s1 = 0.f, q0 = 0.f, q1 = 0.f;
#pragma unroll
    for (int j = 0; j < 8; j++) {
        m0 = fmaxf(m0, acc0[j]); m1 = fmaxf(m1, acc1[j]);
        s0 += acc0[j]; s1 += acc1[j];
        q0 = fmaf(acc0[j], acc0[j], q0); q1 = fmaf(acc1[j], acc1[j], q1);
    }
    smax[pg][2 * o2] = m0; smax[pg][2 * o2 + 1] = m1;
    atomicAdd(&ssum[2 * o2], s0);     atomicAdd(&ssum[2 * o2 + 1], s1);
    atomicAdd(&ssq[2 * o2], q0);      atomicAdd(&ssq[2 * o2 + 1], q1);
    __syncthreads();
    if (tid < 128) {
        float mm = fmaxf(fmaxf(smax[0][tid], smax[1][tid]),
                         fmaxf(smax[2][tid], smax[3][tid]));
        g_ymax[(size_t)g * 128 + tid] = mm;
        atomicAdd(&g_stats[256 + tid], (double)ssum[tid]);
        atomicAdd(&g_stats[384 + tid], (double)ssq[tid]);
    }
}

// ---------------- 8: finalize new_points = relu(BN3(max-pooled y3)) ----------------
__global__ void finalize_kernel(float* __restrict__ out) {
    int i = blockIdx.x * 256 + threadIdx.x;   // 2,097,152
    int o = i & 127;
    out[BB * SS * 3 + i] = fmaxf(fmaf(g_bn[256 + o], g_ymax[i], g_bn[384 + o]), 0.f);
}

extern "C" void kernel_launch(void* const* d_in, const int* in_sizes, int n_in,
                              void* d_out, int out_size) {
    const float* xyz   = (const float*)d_in[0];
    const float* pts   = (const float*)d_in[1];
    const float* w1    = (const float*)d_in[2];
    const float* b1    = (const float*)d_in[3];
    const float* g1    = (const float*)d_in[4];
    const float* beta1 = (const float*)d_in[5];
    const float* w2    = (const float*)d_in[6];
    const float* b2    = (const float*)d_in[7];
    const float* g2    = (const float*)d_in[8];
    const float* beta2 = (const float*)d_in[9];
    const float* w3    = (const float*)d_in[10];
    const float* b3    = (const float*)d_in[11];
    const float* g3    = (const float*)d_in[12];
    const float* beta3 = (const float*)d_in[13];
    float* out = (float*)d_out;

    zero_stats_kernel<<<1, 512>>>();
    fps_kernel<<<BB, 512>>>(xyz, out);                    // new_xyz -> out[0 : 49152)
    u_kernel<<<(BB * NN) / 64, 256>>>(xyz, pts, w1);
    v_kernel<<<(BB * SS * 64) / 256, 256>>>(out, w1, b1);
    ballq_kernel<<<(BB * SS) / 8, 256>>>(xyz, out);
    stats1_kernel<<<(BB * SS * KK) / 256, 256>>>();
    bnp_kernel<<<1, 128>>>(g1, beta1, 64, 0, 0);
    layer2_kernel<<<(BB * SS * KK) / 64, 256>>>(w2, b2);
    bnp_kernel<<<1, 128>>>(g2, beta2, 64, 128, 128);
    layer3_kernel<<<BB * SS, 256>>>(w3, b3);
    bnp_kernel<<<1, 128>>>(g3, beta3, 128, 256, 256);
    finalize_kernel<<<(BB * SS * 128) / 256, 256>>>(out);
}

// round 4
// speedup vs baseline: 1.2193x; 1.2193x over previous
#include <cuda_runtime.h>
#include <cstdint>

#define BB 16
#define NN 4096
#define SS 1024
#define KK 32
#define C1 67
#define CNT_BN 524288.0

typedef unsigned long long ull;

// ---------------- device scratch (no allocation allowed) ----------------
__device__ __align__(16) float  g_u[BB * NN * 64];              // 16.8 MB
__device__ __align__(16) float  g_v[BB * SS * 64];              // 4.2 MB
__device__            int       g_idx[BB * SS * KK];            // 2 MB
__device__ __align__(16) float  g_y2[(size_t)BB * SS * KK * 64];// 134 MB
__device__ __align__(16) float  g_ymax[BB * SS * 128];          // 8.4 MB
__device__            double    g_stats[512];  // L1: sum@0 sq@64 | L2: 128/192 | L3: 256/384
__device__            float     g_bn[512];     // a1@0 c1@64 | a2@128 c2@192 | a3@256 c3@384
__device__ __align__(16) ull    g_w1d[C1 * 64];                 // dup-packed W1^T
__device__ __align__(16) ull    g_w2d[64 * 64];                 // dup-packed W2^T
__device__ __align__(16) ull    g_w3d[64 * 128];                // dup-packed W3^T

// ---------------- f32x2 helpers ----------------
__device__ __forceinline__ ull fma2(ull a, ull b, ull c) {
    ull d;
    asm("fma.rn.f32x2 %0, %1, %2, %3;" : "=l"(d) : "l"(a), "l"(b), "l"(c));
    return d;
}
__device__ __forceinline__ ull pk(float a, float b) {
    ull r;
    asm("mov.b64 %0, {%1, %2};" : "=l"(r) : "f"(a), "f"(b));
    return r;
}
__device__ __forceinline__ void upk(ull v, float& a, float& b) {
    asm("mov.b64 {%0, %1}, %2;" : "=f"(a), "=f"(b) : "l"(v));
}

// ---------------- 0: zero stats + build duplicated transposed weights ----------------
__global__ void prep_kernel(const float* __restrict__ w1, const float* __restrict__ w2,
                            const float* __restrict__ w3) {
    int i = blockIdx.x * 256 + threadIdx.x;          // 0..8191
    if (i < 512) g_stats[i] = 0.0;
    if (i < C1 * 64) {
        int c = i >> 6, o = i & 63;
        float w = w1[o * C1 + c];
        g_w1d[i] = pk(w, w);
    }
    if (i < 64 * 64) {
        int c = i >> 6, o = i & 63;
        float w = w2[o * 64 + c];
        g_w2d[i] = pk(w, w);
    }
    if (i < 64 * 128) {
        int c = i >> 7, o = i & 127;
        float w = w3[o * 64 + c];
        g_w3d[i] = pk(w, w);
    }
}

// ---------------- 1: farthest point sampling (bit-exact vs reference) ----------------
__global__ void fps_kernel(const float* __restrict__ xyz, float* __restrict__ out_xyz) {
    int b = blockIdx.x;
    int tid = threadIdx.x;
    int lane = tid & 31, wid = tid >> 5;
    __shared__ float sc[3];
    __shared__ unsigned smax[16];
    __shared__ int sidx[16];

    const float* xb = xyz + (size_t)b * NN * 3;
    float px[8], py[8], pz[8], dist[8];
    int base = tid * 8;
#pragma unroll
    for (int j = 0; j < 8; j++) {
        px[j] = xb[(base + j) * 3 + 0];
        py[j] = xb[(base + j) * 3 + 1];
        pz[j] = xb[(base + j) * 3 + 2];
        dist[j] = 1e10f;
    }
    if (tid == 0) {
        sc[0] = xb[0]; sc[1] = xb[1]; sc[2] = xb[2];
        float* op = out_xyz + (size_t)b * SS * 3;
        op[0] = xb[0]; op[1] = xb[1]; op[2] = xb[2];
    }
    __syncthreads();

    for (int i = 0; i < SS - 1; i++) {
        float cx = sc[0], cy = sc[1], cz = sc[2];
        float lmax = -1.0f; int lidx = 0;
#pragma unroll
        for (int j = 0; j < 8; j++) {
            float dx = __fsub_rn(px[j], cx);
            float dy = __fsub_rn(py[j], cy);
            float dz = __fsub_rn(pz[j], cz);
            float d = __fadd_rn(__fadd_rn(__fmul_rn(dx, dx), __fmul_rn(dy, dy)),
                                __fmul_rn(dz, dz));
            float nd = fminf(dist[j], d);
            dist[j] = nd;
            if (nd > lmax) { lmax = nd; lidx = base + j; }   // first-index tie-break
        }
        unsigned mb = __float_as_uint(lmax);
        unsigned wm = __reduce_max_sync(0xffffffffu, mb);
        int cand = (mb == wm) ? lidx : 0x7fffffff;
        int wi = __reduce_min_sync(0xffffffffu, cand);
        if (lane == 0) { smax[wid] = wm; sidx[wid] = wi; }
        __syncthreads();
        if (wid == 0) {
            unsigned vb = (lane < 16) ? smax[lane] : 0u;
            int vi = (lane < 16) ? sidx[lane] : 0x7fffffff;
            unsigned m2 = __reduce_max_sync(0xffffffffu, vb);
            int c2 = (vb == m2) ? vi : 0x7fffffff;
            int far = __reduce_min_sync(0xffffffffu, c2);
            if (lane == 0) {
                const float* cp = xb + (size_t)far * 3;
                float nx = cp[0], ny = cp[1], nz = cp[2];
                sc[0] = nx; sc[1] = ny; sc[2] = nz;
                float* op = out_xyz + ((size_t)b * SS + i + 1) * 3;
                op[0] = nx; op[1] = ny; op[2] = nz;
            }
        }
        __syncthreads();
    }
}

// ---------------- 2: u = W1 * [xyz; feat]   (f32x2, 128 points/block) ----------------
#define XST1 130
__global__ __launch_bounds__(256) void u_kernel(const float* __restrict__ xyz,
                                                const float* __restrict__ pts) {
    __shared__ float xin[C1 * XST1];
    int tid = threadIdx.x;
    int p0 = blockIdx.x * 128;
    for (int i = tid; i < 68 * 128; i += 256) {
        int p = i / 68, c = i % 68;
        if (c < C1) {
            float v = (c < 3) ? xyz[(size_t)(p0 + p) * 3 + c]
                              : pts[(size_t)(p0 + p) * 64 + (c - 3)];
            xin[c * XST1 + p] = v;
        }
    }
    __syncthreads();
    int wid = tid >> 5, lane = tid & 31;
    int P = wid * 16;
    ull acc0[8], acc1[8];
#pragma unroll
    for (int t = 0; t < 8; t++) { acc0[t] = 0ull; acc1[t] = 0ull; }
    for (int c = 0; c < C1; c++) {
        ulonglong2 wv = ((const ulonglong2*)(g_w1d + c * 64))[lane];
        const float* xr = xin + c * XST1 + P;
#pragma unroll
        for (int t = 0; t < 8; t++) {
            ull h = *(const ull*)(xr + 2 * t);
            acc0[t] = fma2(h, wv.x, acc0[t]);
            acc1[t] = fma2(h, wv.y, acc1[t]);
        }
    }
#pragma unroll
    for (int t = 0; t < 8; t++) {
        float a0l, a0h, a1l, a1h;
        upk(acc0[t], a0l, a0h);
        upk(acc1[t], a1l, a1h);
        int p = p0 + P + 2 * t;
        float2 s0; s0.x = a0l; s0.y = a1l;
        float2 s1; s1.x = a0h; s1.y = a1h;
        ((float2*)(g_u + (size_t)p * 64))[lane] = s0;
        ((float2*)(g_u + (size_t)(p + 1) * 64))[lane] = s1;
    }
}

// ---------------- 3: v = b1 - W1[:, :3] * c ----------------
__global__ void v_kernel(const float* __restrict__ newxyz, const float* __restrict__ w1,
                         const float* __restrict__ b1) {
    int i = blockIdx.x * 256 + threadIdx.x;
    int o = i & 63, g = i >> 6;
    const float* c = newxyz + (size_t)g * 3;
    const float* wr = w1 + (size_t)o * C1;
    g_v[i] = b1[o] - (wr[0] * c[0] + wr[1] * c[1] + wr[2] * c[2]);
}

// ---------------- 4: ball query (warp per centroid) ----------------
__global__ void ballq_kernel(const float* __restrict__ xyz, const float* __restrict__ newxyz) {
    int gw = blockIdx.x * 8 + (threadIdx.x >> 5);
    int lane = threadIdx.x & 31;
    int b = gw >> 10;
    const float* cp = newxyz + (size_t)gw * 3;
    float sx = cp[0], sy = cp[1], sz = cp[2];
    float sn = __fadd_rn(__fadd_rn(__fmul_rn(sx, sx), __fmul_rn(sy, sy)), __fmul_rn(sz, sz));
    const float* xb = xyz + (size_t)b * NN * 3;
    const float R2 = (float)(0.2 * 0.2);
    int cnt = 0, first = -1;
    int* op = g_idx + (size_t)gw * KK;
    for (int basep = 0; basep < NN && cnt < KK; basep += 32) {
        int n = basep + lane;
        float nx = xb[n * 3 + 0], ny = xb[n * 3 + 1], nz = xb[n * 3 + 2];
        float dn = __fadd_rn(__fadd_rn(__fmul_rn(nx, nx), __fmul_rn(ny, ny)), __fmul_rn(nz, nz));
        float dt = __fadd_rn(__fadd_rn(__fmul_rn(sx, nx), __fmul_rn(sy, ny)), __fmul_rn(sz, nz));
        float sqr = __fadd_rn(__fadd_rn(__fmul_rn(-2.0f, dt), sn), dn);
        bool ok = !(sqr > R2);
        unsigned bal = __ballot_sync(0xffffffffu, ok);
        if (first < 0 && bal) first = basep + (__ffs(bal) - 1);
        int pos = cnt + __popc(bal & ((1u << lane) - 1u));
        if (ok && pos < KK) op[pos] = n;
        cnt += __popc(bal);
    }
    for (int s = cnt + lane; s < KK; s += 32) op[s] = first;
}

// ---------------- 5: BN1 statistics over y1 = u[idx] + v ----------------
__global__ void stats1_kernel() {
    __shared__ float red[2][4][64];
    int tid = threadIdx.x;
    int o = tid & 63, q = tid >> 6;
    int inst0 = blockIdx.x * 256 + q * 64;
    float s = 0.f, ss = 0.f;
    for (int ii = 0; ii < 64; ii++) {
        int inst = inst0 + ii;
        int g = inst >> 5;
        int b = g >> 10;
        int pt = g_idx[inst];
        float y = g_u[(((size_t)b << 12) + pt) * 64 + o] + g_v[(size_t)g * 64 + o];
        s += y;
        ss = fmaf(y, y, ss);
    }
    red[0][q][o] = s; red[1][q][o] = ss;
    __syncthreads();
    if (tid < 64) {
        double ds = (double)red[0][0][tid] + red[0][1][tid] + red[0][2][tid] + red[0][3][tid];
        double dq = (double)red[1][0][tid] + red[1][1][tid] + red[1][2][tid] + red[1][3][tid];
        atomicAdd(&g_stats[0 + tid], ds);
        atomicAdd(&g_stats[64 + tid], dq);
    }
}

// ---------------- BN params ----------------
__global__ void bnp_kernel(const float* __restrict__ gamma, const float* __restrict__ beta,
                           int nch, int stats_off, int bn_off) {
    int o = threadIdx.x;
    if (o >= nch) return;
    double mean = g_stats[stats_off + o] / CNT_BN;
    double var = g_stats[stats_off + nch + o] / CNT_BN - mean * mean;
    double a = (double)gamma[o] / sqrt(var + 1e-5);
    g_bn[bn_off + o] = (float)a;
    g_bn[bn_off + nch + o] = (float)((double)beta[o] - mean * a);
}

// ---------------- 6: layer 2 (f32x2, 128 positions/block) ----------------
#define XST2 130
__global__ __launch_bounds__(256) void layer2_kernel(const float* __restrict__ b2) {
    __shared__ float xin[64 * XST2];
    __shared__ float ssum[64], ssq[64];
    int tid = threadIdx.x;
    int p0 = blockIdx.x * 128;
    if (tid < 64) { ssum[tid] = 0.f; ssq[tid] = 0.f; }
    for (int i = tid; i < 128 * 64; i += 256) {
        int p = i >> 6, c = i & 63;
        int inst = p0 + p;
        int g = inst >> 5;
        int b = g >> 10;
        int pt = g_idx[inst];
        float y = g_u[(((size_t)b << 12) + pt) * 64 + c] + g_v[(size_t)g * 64 + c];
        xin[c * XST2 + p] = fmaxf(fmaf(g_bn[c], y, g_bn[64 + c]), 0.f);
    }
    __syncthreads();
    int wid = tid >> 5, lane = tid & 31;
    int P = wid * 16;
    float2 bb = ((const float2*)b2)[lane];
    ull bi0 = pk(bb.x, bb.x), bi1 = pk(bb.y, bb.y);
    ull acc0[8], acc1[8];
#pragma unroll
    for (int t = 0; t < 8; t++) { acc0[t] = bi0; acc1[t] = bi1; }
    for (int c = 0; c < 64; c++) {
        ulonglong2 wv = ((const ulonglong2*)(g_w2d + c * 64))[lane];
        const float* xr = xin + c * XST2 + P;
#pragma unroll
        for (int t = 0; t < 8; t++) {
            ull h = *(const ull*)(xr + 2 * t);
            acc0[t] = fma2(h, wv.x, acc0[t]);
            acc1[t] = fma2(h, wv.y, acc1[t]);
        }
    }
    float s0 = 0.f, s1 = 0.f, q0 = 0.f, q1 = 0.f;
#pragma unroll
    for (int t = 0; t < 8; t++) {
        float a0l, a0h, a1l, a1h;
        upk(acc0[t], a0l, a0h);
        upk(acc1[t], a1l, a1h);
        int p = p0 + P + 2 * t;
        float2 s0v; s0v.x = a0l; s0v.y = a1l;
        float2 s1v; s1v.x = a0h; s1v.y = a1h;
        ((float2*)(g_y2 + (size_t)p * 64))[lane] = s0v;
        ((float2*)(g_y2 + (size_t)(p + 1) * 64))[lane] = s1v;
        s0 += a0l + a0h; s1 += a1l + a1h;
        q0 = fmaf(a0l, a0l, q0); q0 = fmaf(a0h, a0h, q0);
        q1 = fmaf(a1l, a1l, q1); q1 = fmaf(a1h, a1h, q1);
    }
    atomicAdd(&ssum[2 * lane], s0);     atomicAdd(&ssum[2 * lane + 1], s1);
    atomicAdd(&ssq[2 * lane], q0);      atomicAdd(&ssq[2 * lane + 1], q1);
    __syncthreads();
    if (tid < 64) {
        atomicAdd(&g_stats[128 + tid], (double)ssum[tid]);
        atomicAdd(&g_stats[192 + tid], (double)ssq[tid]);
    }
}

// ---------------- 7: layer 3 (f32x2, 64 positions = 2 groups/block, 4 ch/lane) ----------------
#define XST3 66
__global__ __launch_bounds__(256) void layer3_kernel(const float* __restrict__ b3) {
    __shared__ float xin[64 * XST3];
    __shared__ float ssum[128], ssq[128], smax[8][128];
    int tid = threadIdx.x;
    int p0 = blockIdx.x * 64;
    if (tid < 128) { ssum[tid] = 0.f; ssq[tid] = 0.f; }
    for (int i = tid; i < 64 * 64; i += 256) {
        int p = i >> 6, c = i & 63;
        float y = g_y2[(size_t)(p0 + p) * 64 + c];
        xin[c * XST3 + p] = fmaxf(fmaf(g_bn[128 + c], y, g_bn[192 + c]), 0.f);
    }
    __syncthreads();
    int wid = tid >> 5, lane = tid & 31;
    int P = wid * 8;                                  // 8 positions per warp (4 pairs)
    float4 bb = ((const float4*)b3)[lane];            // 4 out channels per lane
    ull acc[4][4];
#pragma unroll
    for (int t = 0; t < 4; t++) {
        acc[0][t] = pk(bb.x, bb.x);
        acc[1][t] = pk(bb.y, bb.y);
        acc[2][t] = pk(bb.z, bb.z);
        acc[3][t] = pk(bb.w, bb.w);
    }
    for (int c = 0; c < 64; c++) {
        const ulonglong2* wr = (const ulonglong2*)(g_w3d + c * 128);
        ulonglong2 wa = wr[2 * lane];
        ulonglong2 wb = wr[2 * lane + 1];
        const float* xr = xin + c * XST3 + P;
#pragma unroll
        for (int t = 0; t < 4; t++) {
            ull h = *(const ull*)(xr + 2 * t);
            acc[0][t] = fma2(h, wa.x, acc[0][t]);
            acc[1][t] = fma2(h, wa.y, acc[1][t]);
            acc[2][t] = fma2(h, wb.x, acc[2][t]);
            acc[3][t] = fma2(h, wb.y, acc[3][t]);
        }
    }
#pragma unroll
    for (int ch = 0; ch < 4; ch++) {
        float m = -1e30f, s = 0.f, q = 0.f;
#pragma unroll
        for (int t = 0; t < 4; t++) {
            float lo, hi;
            upk(acc[ch][t], lo, hi);
            m = fmaxf(m, fmaxf(lo, hi));
            s += lo + hi;
            q = fmaf(lo, lo, q); q = fmaf(hi, hi, q);
        }
        int o = 4 * lane + ch;
        smax[wid][o] = m;
        atomicAdd(&ssum[o], s);
        atomicAdd(&ssq[o], q);
    }
    __syncthreads();
    if (tid < 128) {
        float mm = fmaxf(fmaxf(smax[0][tid], smax[1][tid]),
                         fmaxf(smax[2][tid], smax[3][tid]));
        g_ymax[((size_t)blockIdx.x * 2) * 128 + tid] = mm;
        atomicAdd(&g_stats[256 + tid], (double)ssum[tid]);
        atomicAdd(&g_stats[384 + tid], (double)ssq[tid]);
    } else {
        int o = tid - 128;
        float mm = fmaxf(fmaxf(smax[4][o], smax[5][o]),
                         fmaxf(smax[6][o], smax[7][o]));
        g_ymax[((size_t)blockIdx.x * 2 + 1) * 128 + o] = mm;
    }
}

// ---------------- 8: finalize new_points = relu(BN3(max-pooled y3)) ----------------
__global__ void finalize_kernel(float* __restrict__ out) {
    int i = blockIdx.x * 256 + threadIdx.x;
    int o = i & 127;
    out[BB * SS * 3 + i] = fmaxf(fmaf(g_bn[256 + o], g_ymax[i], g_bn[384 + o]), 0.f);
}

extern "C" void kernel_launch(void* const* d_in, const int* in_sizes, int n_in,
                              void* d_out, int out_size) {
    const float* xyz   = (const float*)d_in[0];
    const float* pts   = (const float*)d_in[1];
    const float* w1    = (const float*)d_in[2];
    const float* b1    = (const float*)d_in[3];
    const float* g1    = (const float*)d_in[4];
    const float* beta1 = (const float*)d_in[5];
    const float* w2    = (const float*)d_in[6];
    const float* b2    = (const float*)d_in[7];
    const float* g2    = (const float*)d_in[8];
    const float* beta2 = (const float*)d_in[9];
    const float* w3    = (const float*)d_in[10];
    const float* b3    = (const float*)d_in[11];
    const float* g3    = (const float*)d_in[12];
    const float* beta3 = (const float*)d_in[13];
    float* out = (float*)d_out;

    prep_kernel<<<32, 256>>>(w1, w2, w3);
    fps_kernel<<<BB, 512>>>(xyz, out);                    // new_xyz -> out[0 : 49152)
    u_kernel<<<(BB * NN) / 128, 256>>>(xyz, pts);
    v_kernel<<<(BB * SS * 64) / 256, 256>>>(out, w1, b1);
    ballq_kernel<<<(BB * SS) / 8, 256>>>(xyz, out);
    stats1_kernel<<<(BB * SS * KK) / 256, 256>>>();
    bnp_kernel<<<1, 128>>>(g1, beta1, 64, 0, 0);
    layer2_kernel<<<(BB * SS * KK) / 128, 256>>>(b2);
    bnp_kernel<<<1, 128>>>(g2, beta2, 64, 128, 128);
    layer3_kernel<<<(BB * SS * KK) / 64, 256>>>(b3);
    bnp_kernel<<<1, 128>>>(g3, beta3, 128, 256, 256);
    finalize_kernel<<<(BB * SS * 128) / 256, 256>>>(out);
}

// round 5
// speedup vs baseline: 1.2677x; 1.0397x over previous
#include <cuda_runtime.h>
#include <cstdint>

#define BB 16
#define NN 4096
#define SS 1024
#define KK 32
#define C1 67
#define CNT_BN 524288.0

typedef unsigned long long ull;

// ---------------- device scratch (no allocation allowed) ----------------
__device__ __align__(16) float  g_u[BB * NN * 64];              // 16.8 MB
__device__ __align__(16) float  g_v[BB * SS * 64];              // 4.2 MB
__device__            int       g_idx[BB * SS * KK];            // 2 MB
__device__ __align__(16) float  g_y2[(size_t)BB * SS * KK * 64];// 134 MB
__device__ __align__(16) float  g_ymax[BB * SS * 128];          // 8.4 MB
__device__            double    g_stats[512];  // L1: sum@0 sq@64 | L2: 128/192 | L3: 256/384
__device__            float     g_bn[512];     // a1@0 c1@64 | a2@128 c2@192 | a3@256 c3@384
__device__ __align__(16) ull    g_w1d[C1 * 64];                 // dup-packed W1^T
__device__ __align__(16) ull    g_w2d[64 * 64];                 // dup-packed W2^T
__device__ __align__(16) ull    g_w3d[64 * 128];                // dup-packed W3^T

// ---------------- f32x2 helpers ----------------
__device__ __forceinline__ ull fma2(ull a, ull b, ull c) {
    ull d;
    asm("fma.rn.f32x2 %0, %1, %2, %3;" : "=l"(d) : "l"(a), "l"(b), "l"(c));
    return d;
}
__device__ __forceinline__ ull add2(ull a, ull b) {
    ull d;
    asm("add.rn.f32x2 %0, %1, %2;" : "=l"(d) : "l"(a), "l"(b));
    return d;
}
__device__ __forceinline__ ull mul2(ull a, ull b) {
    ull d;
    asm("mul.rn.f32x2 %0, %1, %2;" : "=l"(d) : "l"(a), "l"(b));
    return d;
}
__device__ __forceinline__ ull pk(float a, float b) {
    ull r;
    asm("mov.b64 %0, {%1, %2};" : "=l"(r) : "f"(a), "f"(b));
    return r;
}
__device__ __forceinline__ void upk(ull v, float& a, float& b) {
    asm("mov.b64 {%0, %1}, %2;" : "=f"(a), "=f"(b) : "l"(v));
}

// ---------------- 0: zero stats + build duplicated transposed weights ----------------
__global__ void prep_kernel(const float* __restrict__ w1, const float* __restrict__ w2,
                            const float* __restrict__ w3) {
    int i = blockIdx.x * 256 + threadIdx.x;          // 0..8191
    if (i < 512) g_stats[i] = 0.0;
    if (i < C1 * 64) {
        int c = i >> 6, o = i & 63;
        float w = w1[o * C1 + c];
        g_w1d[i] = pk(w, w);
    }
    if (i < 64 * 64) {
        int c = i >> 6, o = i & 63;
        float w = w2[o * 64 + c];
        g_w2d[i] = pk(w, w);
    }
    if (i < 64 * 128) {
        int c = i >> 7, o = i & 127;
        float w = w3[o * 64 + c];
        g_w3d[i] = pk(w, w);
    }
}

// ---------------- 1: farthest point sampling (f32x2 distance; bit-exact selection) ----------------
__global__ void fps_kernel(const float* __restrict__ xyz, float* __restrict__ out_xyz) {
    int b = blockIdx.x;
    int tid = threadIdx.x;
    int lane = tid & 31, wid = tid >> 5;
    __shared__ float sc[3];
    __shared__ unsigned smax[16];
    __shared__ int sidx[16];

    const float* xb = xyz + (size_t)b * NN * 3;
    ull px[4], py[4], pz[4];
    float dist[8];
    int base = tid * 8;
#pragma unroll
    for (int t = 0; t < 4; t++) {
        int j0 = base + 2 * t, j1 = j0 + 1;
        px[t] = pk(xb[j0 * 3 + 0], xb[j1 * 3 + 0]);
        py[t] = pk(xb[j0 * 3 + 1], xb[j1 * 3 + 1]);
        pz[t] = pk(xb[j0 * 3 + 2], xb[j1 * 3 + 2]);
        dist[2 * t] = 1e10f;
        dist[2 * t + 1] = 1e10f;
    }
    if (tid == 0) {
        sc[0] = xb[0]; sc[1] = xb[1]; sc[2] = xb[2];
        float* op = out_xyz + (size_t)b * SS * 3;
        op[0] = xb[0]; op[1] = xb[1]; op[2] = xb[2];
    }
    __syncthreads();

    for (int i = 0; i < SS - 1; i++) {
        // negated-centroid packs: add(x, -c) is bit-identical to sub(x, c)
        ull ncx = pk(-sc[0], -sc[0]);
        ull ncy = pk(-sc[1], -sc[1]);
        ull ncz = pk(-sc[2], -sc[2]);
        float lmax = -1.0f; int lidx = 0;
#pragma unroll
        for (int t = 0; t < 4; t++) {
            ull dx = add2(px[t], ncx);
            ull dy = add2(py[t], ncy);
            ull dz = add2(pz[t], ncz);
            // ((dx*dx + dy*dy) + dz*dz)  -- same assoc as reference, per lane
            ull s = add2(add2(mul2(dx, dx), mul2(dy, dy)), mul2(dz, dz));
            float slo, shi;
            upk(s, slo, shi);
            float d0 = fminf(dist[2 * t], slo);
            float d1 = fminf(dist[2 * t + 1], shi);
            dist[2 * t] = d0;
            dist[2 * t + 1] = d1;
            if (d0 > lmax) { lmax = d0; lidx = base + 2 * t; }       // ascending order:
            if (d1 > lmax) { lmax = d1; lidx = base + 2 * t + 1; }   // first-index tie-break
        }
        unsigned mb = __float_as_uint(lmax);                 // dist >= 0 -> bit-monotone
        unsigned wm = __reduce_max_sync(0xffffffffu, mb);
        int cand = (mb == wm) ? lidx : 0x7fffffff;
        int wi = __reduce_min_sync(0xffffffffu, cand);
        if (lane == 0) { smax[wid] = wm; sidx[wid] = wi; }
        __syncthreads();
        if (wid == 0) {
            unsigned vb = (lane < 16) ? smax[lane] : 0u;
            int vi = (lane < 16) ? sidx[lane] : 0x7fffffff;
            unsigned m2 = __reduce_max_sync(0xffffffffu, vb);
            int c2 = (vb == m2) ? vi : 0x7fffffff;
            int far = __reduce_min_sync(0xffffffffu, c2);
            if (lane == 0) {
                const float* cp = xb + (size_t)far * 3;
                float nx = cp[0], ny = cp[1], nz = cp[2];
                sc[0] = nx; sc[1] = ny; sc[2] = nz;
                float* op = out_xyz + ((size_t)b * SS + i + 1) * 3;
                op[0] = nx; op[1] = ny; op[2] = nz;
            }
        }
        __syncthreads();
    }
}

// ---------------- 2: u = W1 * [xyz; feat]   (f32x2, 128 points/block) ----------------
#define XST1 130
__global__ __launch_bounds__(256) void u_kernel(const float* __restrict__ xyz,
                                                const float* __restrict__ pts) {
    __shared__ float xin[C1 * XST1];
    int tid = threadIdx.x;
    int p0 = blockIdx.x * 128;
    for (int i = tid; i < 68 * 128; i += 256) {
        int p = i / 68, c = i % 68;
        if (c < C1) {
            float v = (c < 3) ? xyz[(size_t)(p0 + p) * 3 + c]
                              : pts[(size_t)(p0 + p) * 64 + (c - 3)];
            xin[c * XST1 + p] = v;
        }
    }
    __syncthreads();
    int wid = tid >> 5, lane = tid & 31;
    int P = wid * 16;
    ull acc0[8], acc1[8];
#pragma unroll
    for (int t = 0; t < 8; t++) { acc0[t] = 0ull; acc1[t] = 0ull; }
    for (int c = 0; c < C1; c++) {
        ulonglong2 wv = ((const ulonglong2*)(g_w1d + c * 64))[lane];
        const float* xr = xin + c * XST1 + P;
#pragma unroll
        for (int t = 0; t < 8; t++) {
            ull h = *(const ull*)(xr + 2 * t);
            acc0[t] = fma2(h, wv.x, acc0[t]);
            acc1[t] = fma2(h, wv.y, acc1[t]);
        }
    }
#pragma unroll
    for (int t = 0; t < 8; t++) {
        float a0l, a0h, a1l, a1h;
        upk(acc0[t], a0l, a0h);
        upk(acc1[t], a1l, a1h);
        int p = p0 + P + 2 * t;
        float2 s0; s0.x = a0l; s0.y = a1l;
        float2 s1; s1.x = a0h; s1.y = a1h;
        ((float2*)(g_u + (size_t)p * 64))[lane] = s0;
        ((float2*)(g_u + (size_t)(p + 1) * 64))[lane] = s1;
    }
}

// ---------------- 3: v = b1 - W1[:, :3] * c ----------------
__global__ void v_kernel(const float* __restrict__ newxyz, const float* __restrict__ w1,
                         const float* __restrict__ b1) {
    int i = blockIdx.x * 256 + threadIdx.x;
    int o = i & 63, g = i >> 6;
    const float* c = newxyz + (size_t)g * 3;
    const float* wr = w1 + (size_t)o * C1;
    g_v[i] = b1[o] - (wr[0] * c[0] + wr[1] * c[1] + wr[2] * c[2]);
}

// ---------------- 4: ball query (warp per centroid) ----------------
__global__ void ballq_kernel(const float* __restrict__ xyz, const float* __restrict__ newxyz) {
    int gw = blockIdx.x * 8 + (threadIdx.x >> 5);
    int lane = threadIdx.x & 31;
    int b = gw >> 10;
    const float* cp = newxyz + (size_t)gw * 3;
    float sx = cp[0], sy = cp[1], sz = cp[2];
    float sn = __fadd_rn(__fadd_rn(__fmul_rn(sx, sx), __fmul_rn(sy, sy)), __fmul_rn(sz, sz));
    const float* xb = xyz + (size_t)b * NN * 3;
    const float R2 = (float)(0.2 * 0.2);
    int cnt = 0, first = -1;
    int* op = g_idx + (size_t)gw * KK;
    for (int basep = 0; basep < NN && cnt < KK; basep += 32) {
        int n = basep + lane;
        float nx = xb[n * 3 + 0], ny = xb[n * 3 + 1], nz = xb[n * 3 + 2];
        float dn = __fadd_rn(__fadd_rn(__fmul_rn(nx, nx), __fmul_rn(ny, ny)), __fmul_rn(nz, nz));
        float dt = __fadd_rn(__fadd_rn(__fmul_rn(sx, nx), __fmul_rn(sy, ny)), __fmul_rn(sz, nz));
        float sqr = __fadd_rn(__fadd_rn(__fmul_rn(-2.0f, dt), sn), dn);
        bool ok = !(sqr > R2);
        unsigned bal = __ballot_sync(0xffffffffu, ok);
        if (first < 0 && bal) first = basep + (__ffs(bal) - 1);
        int pos = cnt + __popc(bal & ((1u << lane) - 1u));
        if (ok && pos < KK) op[pos] = n;
        cnt += __popc(bal);
    }
    for (int s = cnt + lane; s < KK; s += 32) op[s] = first;
}

// ---------------- 5: BN1 statistics over y1 = u[idx] + v  (float2 channels, v hoisted) ----------------
__global__ void stats1_kernel() {
    __shared__ float red[2][8][64];
    int tid = threadIdx.x;
    int o2 = tid & 31;          // channel pair
    int q = tid >> 5;           // 0..7
    int inst0 = blockIdx.x * 256 + q * 32;      // 32-aligned -> same group g for all 32 insts
    int g = inst0 >> 5;
    int b = g >> 10;
    float2 v = ((const float2*)(g_v + (size_t)g * 64))[o2];
    float s0 = 0.f, s1 = 0.f, q0 = 0.f, q1 = 0.f;
#pragma unroll 4
    for (int ii = 0; ii < 32; ii++) {
        int pt = g_idx[inst0 + ii];
        float2 u = ((const float2*)(g_u + (((size_t)b << 12) + pt) * 64))[o2];
        float y0 = u.x + v.x, y1 = u.y + v.y;
        s0 += y0; s1 += y1;
        q0 = fmaf(y0, y0, q0); q1 = fmaf(y1, y1, q1);
    }
    red[0][q][2 * o2] = s0; red[0][q][2 * o2 + 1] = s1;
    red[1][q][2 * o2] = q0; red[1][q][2 * o2 + 1] = q1;
    __syncthreads();
    if (tid < 64) {
        double ds = 0.0, dq = 0.0;
#pragma unroll
        for (int r = 0; r < 8; r++) { ds += red[0][r][tid]; dq += red[1][r][tid]; }
        atomicAdd(&g_stats[0 + tid], ds);
        atomicAdd(&g_stats[64 + tid], dq);
    }
}

// ---------------- BN params ----------------
__global__ void bnp_kernel(const float* __restrict__ gamma, const float* __restrict__ beta,
                           int nch, int stats_off, int bn_off) {
    int o = threadIdx.x;
    if (o >= nch) return;
    double mean = g_stats[stats_off + o] / CNT_BN;
    double var = g_stats[stats_off + nch + o] / CNT_BN - mean * mean;
    double a = (double)gamma[o] / sqrt(var + 1e-5);
    g_bn[bn_off + o] = (float)a;
    g_bn[bn_off + nch + o] = (float)((double)beta[o] - mean * a);
}

// ---------------- 6: layer 2 (f32x2, 128 positions/block) ----------------
#define XST2 130
__global__ __launch_bounds__(256) void layer2_kernel(const float* __restrict__ b2) {
    __shared__ float xin[64 * XST2];
    __shared__ float ssum[64], ssq[64];
    int tid = threadIdx.x;
    int p0 = blockIdx.x * 128;
    if (tid < 64) { ssum[tid] = 0.f; ssq[tid] = 0.f; }
    for (int i = tid; i < 128 * 64; i += 256) {
        int p = i >> 6, c = i & 63;
        int inst = p0 + p;
        int g = inst >> 5;
        int b = g >> 10;
        int pt = g_idx[inst];
        float y = g_u[(((size_t)b << 12) + pt) * 64 + c] + g_v[(size_t)g * 64 + c];
        xin[c * XST2 + p] = fmaxf(fmaf(g_bn[c], y, g_bn[64 + c]), 0.f);
    }
    __syncthreads();
    int wid = tid >> 5, lane = tid & 31;
    int P = wid * 16;
    float2 bb = ((const float2*)b2)[lane];
    ull bi0 = pk(bb.x, bb.x), bi1 = pk(bb.y, bb.y);
    ull acc0[8], acc1[8];
#pragma unroll
    for (int t = 0; t < 8; t++) { acc0[t] = bi0; acc1[t] = bi1; }
    for (int c = 0; c < 64; c++) {
        ulonglong2 wv = ((const ulonglong2*)(g_w2d + c * 64))[lane];
        const float* xr = xin + c * XST2 + P;
#pragma unroll
        for (int t = 0; t < 8; t++) {
            ull h = *(const ull*)(xr + 2 * t);
            acc0[t] = fma2(h, wv.x, acc0[t]);
            acc1[t] = fma2(h, wv.y, acc1[t]);
        }
    }
    float s0 = 0.f, s1 = 0.f, q0 = 0.f, q1 = 0.f;
#pragma unroll
    for (int t = 0; t < 8; t++) {
        float a0l, a0h, a1l, a1h;
        upk(acc0[t], a0l, a0h);
        upk(acc1[t], a1l, a1h);
        int p = p0 + P + 2 * t;
        float2 s0v; s0v.x = a0l; s0v.y = a1l;
        float2 s1v; s1v.x = a0h; s1v.y = a1h;
        ((float2*)(g_y2 + (size_t)p * 64))[lane] = s0v;
        ((float2*)(g_y2 + (size_t)(p + 1) * 64))[lane] = s1v;
        s0 += a0l + a0h; s1 += a1l + a1h;
        q0 = fmaf(a0l, a0l, q0); q0 = fmaf(a0h, a0h, q0);
        q1 = fmaf(a1l, a1l, q1); q1 = fmaf(a1h, a1h, q1);
    }
    atomicAdd(&ssum[2 * lane], s0);     atomicAdd(&ssum[2 * lane + 1], s1);
    atomicAdd(&ssq[2 * lane], q0);      atomicAdd(&ssq[2 * lane + 1], q1);
    __syncthreads();
    if (tid < 64) {
        atomicAdd(&g_stats[128 + tid], (double)ssum[tid]);
        atomicAdd(&g_stats[192 + tid], (double)ssq[tid]);
    }
}

// ---------------- 7: layer 3 (f32x2, 64 positions = 2 groups/block, 4 ch/lane) ----------------
#define XST3 66
__global__ __launch_bounds__(256) void layer3_kernel(const float* __restrict__ b3) {
    __shared__ float xin[64 * XST3];
    __shared__ float ssum[128], ssq[128], smax[8][128];
    int tid = threadIdx.x;
    int p0 = blockIdx.x * 64;
    if (tid < 128) { ssum[tid] = 0.f; ssq[tid] = 0.f; }
    for (int i = tid; i < 64 * 64; i += 256) {
        int p = i >> 6, c = i & 63;
        float y = g_y2[(size_t)(p0 + p) * 64 + c];
        xin[c * XST3 + p] = fmaxf(fmaf(g_bn[128 + c], y, g_bn[192 + c]), 0.f);
    }
    __syncthreads();
    int wid = tid >> 5, lane = tid & 31;
    int P = wid * 8;                                  // 8 positions per warp (4 pairs)
    float4 bb = ((const float4*)b3)[lane];            // 4 out channels per lane
    ull acc[4][4];
#pragma unroll
    for (int t = 0; t < 4; t++) {
        acc[0][t] = pk(bb.x, bb.x);
        acc[1][t] = pk(bb.y, bb.y);
        acc[2][t] = pk(bb.z, bb.z);
        acc[3][t] = pk(bb.w, bb.w);
    }
    for (int c = 0; c < 64; c++) {
        const ulonglong2* wr = (const ulonglong2*)(g_w3d + c * 128);
        ulonglong2 wa = wr[2 * lane];
        ulonglong2 wb = wr[2 * lane + 1];
        const float* xr = xin + c * XST3 + P;
#pragma unroll
        for (int t = 0; t < 4; t++) {
            ull h = *(const ull*)(xr + 2 * t);
            acc[0][t] = fma2(h, wa.x, acc[0][t]);
            acc[1][t] = fma2(h, wa.y, acc[1][t]);
            acc[2][t] = fma2(h, wb.x, acc[2][t]);
            acc[3][t] = fma2(h, wb.y, acc[3][t]);
        }
    }
#pragma unroll
    for (int ch = 0; ch < 4; ch++) {
        float m = -1e30f, s = 0.f, q = 0.f;
#pragma unroll
        for (int t = 0; t < 4; t++) {
            float lo, hi;
            upk(acc[ch][t], lo, hi);
            m = fmaxf(m, fmaxf(lo, hi));
            s += lo + hi;
            q = fmaf(lo, lo, q); q = fmaf(hi, hi, q);
        }
        int o = 4 * lane + ch;
        smax[wid][o] = m;
        atomicAdd(&ssum[o], s);
        atomicAdd(&ssq[o], q);
    }
    __syncthreads();
    if (tid < 128) {
        float mm = fmaxf(fmaxf(smax[0][tid], smax[1][tid]),
                         fmaxf(smax[2][tid], smax[3][tid]));
        g_ymax[((size_t)blockIdx.x * 2) * 128 + tid] = mm;
        atomicAdd(&g_stats[256 + tid], (double)ssum[tid]);
        atomicAdd(&g_stats[384 + tid], (double)ssq[tid]);
    } else {
        int o = tid - 128;
        float mm = fmaxf(fmaxf(smax[4][o], smax[5][o]),
                         fmaxf(smax[6][o], smax[7][o]));
        g_ymax[((size_t)blockIdx.x * 2 + 1) * 128 + o] = mm;
    }
}

// ---------------- 8: finalize new_points = relu(BN3(max-pooled y3)) ----------------
__global__ void finalize_kernel(float* __restrict__ out) {
    int i = blockIdx.x * 256 + threadIdx.x;
    int o = i & 127;
    out[BB * SS * 3 + i] = fmaxf(fmaf(g_bn[256 + o], g_ymax[i], g_bn[384 + o]), 0.f);
}

extern "C" void kernel_launch(void* const* d_in, const int* in_sizes, int n_in,
                              void* d_out, int out_size) {
    const float* xyz   = (const float*)d_in[0];
    const float* pts   = (const float*)d_in[1];
    const float* w1    = (const float*)d_in[2];
    const float* b1    = (const float*)d_in[3];
    const float* g1    = (const float*)d_in[4];
    const float* beta1 = (const float*)d_in[5];
    const float* w2    = (const float*)d_in[6];
    const float* b2    = (const float*)d_in[7];
    const float* g2    = (const float*)d_in[8];
    const float* beta2 = (const float*)d_in[9];
    const float* w3    = (const float*)d_in[10];
    const float* b3    = (const float*)d_in[11];
    const float* g3    = (const float*)d_in[12];
    const float* beta3 = (const float*)d_in[13];
    float* out = (float*)d_out;

    prep_kernel<<<32, 256>>>(w1, w2, w3);
    fps_kernel<<<BB, 512>>>(xyz, out);                    // new_xyz -> out[0 : 49152)
    u_kernel<<<(BB * NN) / 128, 256>>>(xyz, pts);
    v_kernel<<<(BB * SS * 64) / 256, 256>>>(out, w1, b1);
    ballq_kernel<<<(BB * SS) / 8, 256>>>(xyz, out);
    stats1_kernel<<<(BB * SS * KK) / 256, 256>>>();
    bnp_kernel<<<1, 128>>>(g1, beta1, 64, 0, 0);
    layer2_kernel<<<(BB * SS * KK) / 128, 256>>>(b2);
    bnp_kernel<<<1, 128>>>(g2, beta2, 64, 128, 128);
    layer3_kernel<<<(BB * SS * KK) / 64, 256>>>(b3);
    bnp_kernel<<<1, 128>>>(g3, beta3, 128, 256, 256);
    finalize_kernel<<<(BB * SS * 128) / 256, 256>>>(out);
}

// round 7
// speedup vs baseline: 1.5603x; 1.2308x over previous
#include <cuda_runtime.h>
#include <cstdint>

#define BB 16
#define NN 4096
#define SS 1024
#define KK 32
#define C1 67
#define CNT_BN 524288.0

typedef unsigned long long ull;

// ---------------- device scratch (no allocation allowed) ----------------
__device__ __align__(16) float  g_u[BB * NN * 64];              // 16.8 MB
__device__ __align__(16) float  g_v[BB * SS * 64];              // 4.2 MB
__device__            int       g_idx[BB * SS * KK];            // 2 MB
__device__ __align__(16) float  g_y2[(size_t)BB * SS * KK * 64];// 134 MB
__device__ __align__(16) float  g_ymax[BB * SS * 128];          // 8.4 MB
__device__            double    g_stats[512];  // L1: sum@0 sq@64 | L2: 128/192 | L3: 256/384
__device__            float     g_bn[512];     // a1@0 c1@64 | a2@128 c2@192 | a3@256 c3@384
__device__ __align__(16) ull    g_w1d[C1 * 64];                 // dup-packed W1^T
__device__ __align__(16) ull    g_w2d[64 * 64];                 // dup-packed W2^T
__device__ __align__(16) ull    g_w3d[64 * 128];                // dup-packed W3^T

// ---------------- f32x2 helpers ----------------
__device__ __forceinline__ ull fma2(ull a, ull b, ull c) {
    ull d;
    asm("fma.rn.f32x2 %0, %1, %2, %3;" : "=l"(d) : "l"(a), "l"(b), "l"(c));
    return d;
}
__device__ __forceinline__ ull add2(ull a, ull b) {
    ull d;
    asm("add.rn.f32x2 %0, %1, %2;" : "=l"(d) : "l"(a), "l"(b));
    return d;
}
__device__ __forceinline__ ull mul2(ull a, ull b) {
    ull d;
    asm("mul.rn.f32x2 %0, %1, %2;" : "=l"(d) : "l"(a), "l"(b));
    return d;
}
__device__ __forceinline__ ull pk(float a, float b) {
    ull r;
    asm("mov.b64 %0, {%1, %2};" : "=l"(r) : "f"(a), "f"(b));
    return r;
}
__device__ __forceinline__ void upk(ull v, float& a, float& b) {
    asm("mov.b64 {%0, %1}, %2;" : "=f"(a), "=f"(b) : "l"(v));
}

// ---------------- 0: zero stats + build duplicated transposed weights ----------------
__global__ void prep_kernel(const float* __restrict__ w1, const float* __restrict__ w2,
                            const float* __restrict__ w3) {
    int i = blockIdx.x * 256 + threadIdx.x;          // 0..8191
    if (i < 512) g_stats[i] = 0.0;
    if (i < C1 * 64) {
        int c = i >> 6, o = i & 63;
        float w = w1[o * C1 + c];
        g_w1d[i] = pk(w, w);
    }
    if (i < 64 * 64) {
        int c = i >> 6, o = i & 63;
        float w = w2[o * 64 + c];
        g_w2d[i] = pk(w, w);
    }
    if (i < 64 * 128) {
        int c = i >> 7, o = i & 127;
        float w = w3[o * 64 + c];
        g_w3d[i] = pk(w, w);
    }
}

// ---------------- 1: FPS — single barrier/iter, replicated reduction, bit-exact ----------------
__global__ void fps_kernel(const float* __restrict__ xyz, float* __restrict__ out_xyz) {
    int b = blockIdx.x;
    int tid = threadIdx.x;
    int lane = tid & 31, wid = tid >> 5;
    __shared__ unsigned smaxb[2][16];
    __shared__ int sidxv[2][16];

    const float* xb = xyz + (size_t)b * NN * 3;
    ull px[4], py[4], pz[4];
    float dist[8];
    int base = tid * 8;
#pragma unroll
    for (int t = 0; t < 4; t++) {
        int j0 = base + 2 * t, j1 = j0 + 1;
        px[t] = pk(xb[j0 * 3 + 0], xb[j1 * 3 + 0]);
        py[t] = pk(xb[j0 * 3 + 1], xb[j1 * 3 + 1]);
        pz[t] = pk(xb[j0 * 3 + 2], xb[j1 * 3 + 2]);
        dist[2 * t] = 1e10f;
        dist[2 * t + 1] = 1e10f;
    }
    float cx = xb[0], cy = xb[1], cz = xb[2];       // broadcast load, all threads
    if (tid == 0) {
        float* op = out_xyz + (size_t)b * SS * 3;
        op[0] = cx; op[1] = cy; op[2] = cz;
    }

    for (int i = 0; i < SS - 1; i++) {
        // negated-centroid packs: add(x, -c) is bit-identical to sub(x, c)
        ull ncx = pk(-cx, -cx);
        ull ncy = pk(-cy, -cy);
        ull ncz = pk(-cz, -cz);
        float lmax = -1.0f; int lidx = 0;
#pragma unroll
        for (int t = 0; t < 4; t++) {
            ull dx = add2(px[t], ncx);
            ull dy = add2(py[t], ncy);
            ull dz = add2(pz[t], ncz);
            // ((dx*dx + dy*dy) + dz*dz) -- same assoc as reference, per lane
            ull s = add2(add2(mul2(dx, dx), mul2(dy, dy)), mul2(dz, dz));
            float slo, shi;
            upk(s, slo, shi);
            float d0 = fminf(dist[2 * t], slo);
            float d1 = fminf(dist[2 * t + 1], shi);
            dist[2 * t] = d0;
            dist[2 * t + 1] = d1;
            if (d0 > lmax) { lmax = d0; lidx = base + 2 * t; }       // ascending order:
            if (d1 > lmax) { lmax = d1; lidx = base + 2 * t + 1; }   // first-index tie-break
        }
        unsigned mb = __float_as_uint(lmax);                 // dist >= 0 -> bit-monotone
        unsigned wm = __reduce_max_sync(0xffffffffu, mb);
        int cand = (mb == wm) ? lidx : 0x7fffffff;
        int wi = __reduce_min_sync(0xffffffffu, cand);
        int par = i & 1;                                     // parity double-buffer
        if (lane == 0) { smaxb[par][wid] = wm; sidxv[par][wid] = wi; }
        __syncthreads();
        // replicated block-level reduction in EVERY warp (identical result per warp)
        unsigned vb = (lane < 16) ? smaxb[par][lane] : 0u;
        int vi = (lane < 16) ? sidxv[par][lane] : 0x7fffffff;
        unsigned m2 = __reduce_max_sync(0xffffffffu, vb);
        int c2 = (vb == m2) ? vi : 0x7fffffff;
        int far = __reduce_min_sync(0xffffffffu, c2);
        const float* cp = xb + (size_t)far * 3;              // uniform addr -> broadcast
        cx = cp[0]; cy = cp[1]; cz = cp[2];
        if (tid == 0) {
            float* op = out_xyz + ((size_t)b * SS + i + 1) * 3;
            op[0] = cx; op[1] = cy; op[2] = cz;
        }
    }
}

// ---------------- 2: u = W1 * [xyz; feat]   (f32x2, 128 points/block) ----------------
#define XST1 132
__global__ __launch_bounds__(256) void u_kernel(const float* __restrict__ xyz,
                                                const float* __restrict__ pts) {
    __shared__ float xin[C1 * XST1];
    int tid = threadIdx.x;
    int p0 = blockIdx.x * 128;
    for (int i = tid; i < 68 * 128; i += 256) {
        int p = i / 68, c = i % 68;
        if (c < C1) {
            float v = (c < 3) ? xyz[(size_t)(p0 + p) * 3 + c]
                              : pts[(size_t)(p0 + p) * 64 + (c - 3)];
            xin[c * XST1 + p] = v;
        }
    }
    __syncthreads();
    int wid = tid >> 5, lane = tid & 31;
    int P = wid * 16;
    ull acc0[8], acc1[8];
#pragma unroll
    for (int t = 0; t < 8; t++) { acc0[t] = 0ull; acc1[t] = 0ull; }
    for (int c = 0; c < C1; c++) {
        ulonglong2 wv = ((const ulonglong2*)(g_w1d + c * 64))[lane];
        const float* xr = xin + c * XST1 + P;
#pragma unroll
        for (int t2 = 0; t2 < 4; t2++) {
            ulonglong2 hh = *(const ulonglong2*)(xr + 4 * t2);
            acc0[2 * t2]     = fma2(hh.x, wv.x, acc0[2 * t2]);
            acc1[2 * t2]     = fma2(hh.x, wv.y, acc1[2 * t2]);
            acc0[2 * t2 + 1] = fma2(hh.y, wv.x, acc0[2 * t2 + 1]);
            acc1[2 * t2 + 1] = fma2(hh.y, wv.y, acc1[2 * t2 + 1]);
        }
    }
#pragma unroll
    for (int t = 0; t < 8; t++) {
        float a0l, a0h, a1l, a1h;
        upk(acc0[t], a0l, a0h);
        upk(acc1[t], a1l, a1h);
        int p = p0 + P + 2 * t;
        float2 s0; s0.x = a0l; s0.y = a1l;
        float2 s1; s1.x = a0h; s1.y = a1h;
        ((float2*)(g_u + (size_t)p * 64))[lane] = s0;
        ((float2*)(g_u + (size_t)(p + 1) * 64))[lane] = s1;
    }
}

// ---------------- 3: v = b1 - W1[:, :3] * c ----------------
__global__ void v_kernel(const float* __restrict__ newxyz, const float* __restrict__ w1,
                         const float* __restrict__ b1) {
    int i = blockIdx.x * 256 + threadIdx.x;
    int o = i & 63, g = i >> 6;
    const float* c = newxyz + (size_t)g * 3;
    const float* wr = w1 + (size_t)o * C1;
    g_v[i] = b1[o] - (wr[0] * c[0] + wr[1] * c[1] + wr[2] * c[2]);
}

// ---------------- 4: ball query (warp per centroid) ----------------
__global__ void ballq_kernel(const float* __restrict__ xyz, const float* __restrict__ newxyz) {
    int gw = blockIdx.x * 8 + (threadIdx.x >> 5);
    int lane = threadIdx.x & 31;
    int b = gw >> 10;
    const float* cp = newxyz + (size_t)gw * 3;
    float sx = cp[0], sy = cp[1], sz = cp[2];
    float sn = __fadd_rn(__fadd_rn(__fmul_rn(sx, sx), __fmul_rn(sy, sy)), __fmul_rn(sz, sz));
    const float* xb = xyz + (size_t)b * NN * 3;
    const float R2 = (float)(0.2 * 0.2);
    int cnt = 0, first = -1;
    int* op = g_idx + (size_t)gw * KK;
    for (int basep = 0; basep < NN && cnt < KK; basep += 32) {
        int n = basep + lane;
        float nx = xb[n * 3 + 0], ny = xb[n * 3 + 1], nz = xb[n * 3 + 2];
        float dn = __fadd_rn(__fadd_rn(__fmul_rn(nx, nx), __fmul_rn(ny, ny)), __fmul_rn(nz, nz));
        float dt = __fadd_rn(__fadd_rn(__fmul_rn(sx, nx), __fmul_rn(sy, ny)), __fmul_rn(sz, nz));
        float sqr = __fadd_rn(__fadd_rn(__fmul_rn(-2.0f, dt), sn), dn);
        bool ok = !(sqr > R2);
        unsigned bal = __ballot_sync(0xffffffffu, ok);
        if (first < 0 && bal) first = basep + (__ffs(bal) - 1);
        int pos = cnt + __popc(bal & ((1u << lane) - 1u));
        if (ok && pos < KK) op[pos] = n;
        cnt += __popc(bal);
    }
    for (int s = cnt + lane; s < KK; s += 32) op[s] = first;
}

// ---------------- 5: BN1 statistics over y1 = u[idx] + v  (float2 channels, v hoisted) ----------------
__global__ void stats1_kernel() {
    __shared__ float red[2][8][64];
    int tid = threadIdx.x;
    int o2 = tid & 31;          // channel pair
    int q = tid >> 5;           // 0..7
    int inst0 = blockIdx.x * 256 + q * 32;      // 32-aligned -> same group g for all 32 insts
    int g = inst0 >> 5;
    int b = g >> 10;
    float2 v = ((const float2*)(g_v + (size_t)g * 64))[o2];
    float s0 = 0.f, s1 = 0.f, q0 = 0.f, q1 = 0.f;
#pragma unroll 4
    for (int ii = 0; ii < 32; ii++) {
        int pt = g_idx[inst0 + ii];
        float2 u = ((const float2*)(g_u + (((size_t)b << 12) + pt) * 64))[o2];
        float y0 = u.x + v.x, y1 = u.y + v.y;
        s0 += y0; s1 += y1;
        q0 = fmaf(y0, y0, q0); q1 = fmaf(y1, y1, q1);
    }
    red[0][q][2 * o2] = s0; red[0][q][2 * o2 + 1] = s1;
    red[1][q][2 * o2] = q0; red[1][q][2 * o2 + 1] = q1;
    __syncthreads();
    if (tid < 64) {
        double ds = 0.0, dq = 0.0;
#pragma unroll
        for (int r = 0; r < 8; r++) { ds += red[0][r][tid]; dq += red[1][r][tid]; }
        atomicAdd(&g_stats[0 + tid], ds);
        atomicAdd(&g_stats[64 + tid], dq);
    }
}

// ---------------- BN params ----------------
__global__ void bnp_kernel(const float* __restrict__ gamma, const float* __restrict__ beta,
                           int nch, int stats_off, int bn_off) {
    int o = threadIdx.x;
    if (o >= nch) return;
    double mean = g_stats[stats_off + o] / CNT_BN;
    double var = g_stats[stats_off + nch + o] / CNT_BN - mean * mean;
    double a = (double)gamma[o] / sqrt(var + 1e-5);
    g_bn[bn_off + o] = (float)a;
    g_bn[bn_off + nch + o] = (float)((double)beta[o] - mean * a);
}

// ---------------- 6: layer 2 (f32x2, 128 positions/block, LDS.128 activations) ----------------
#define XST2 132
__global__ __launch_bounds__(256) void layer2_kernel(const float* __restrict__ b2) {
    __shared__ float xin[64 * XST2];
    __shared__ float ssum[64], ssq[64];
    int tid = threadIdx.x;
    int p0 = blockIdx.x * 128;
    if (tid < 64) { ssum[tid] = 0.f; ssq[tid] = 0.f; }
    for (int i = tid; i < 128 * 64; i += 256) {
        int p = i >> 6, c = i & 63;
        int inst = p0 + p;
        int g = inst >> 5;
        int b = g >> 10;
        int pt = g_idx[inst];
        float y = g_u[(((size_t)b << 12) + pt) * 64 + c] + g_v[(size_t)g * 64 + c];
        xin[c * XST2 + p] = fmaxf(fmaf(g_bn[c], y, g_bn[64 + c]), 0.f);
    }
    __syncthreads();
    int wid = tid >> 5, lane = tid & 31;
    int P = wid * 16;
    float2 bb = ((const float2*)b2)[lane];
    ull bi0 = pk(bb.x, bb.x), bi1 = pk(bb.y, bb.y);
    ull acc0[8], acc1[8];
#pragma unroll
    for (int t = 0; t < 8; t++) { acc0[t] = bi0; acc1[t] = bi1; }
    for (int c = 0; c < 64; c++) {
        ulonglong2 wv = ((const ulonglong2*)(g_w2d + c * 64))[lane];
        const float* xr = xin + c * XST2 + P;
#pragma unroll
        for (int t2 = 0; t2 < 4; t2++) {
            ulonglong2 hh = *(const ulonglong2*)(xr + 4 * t2);
            acc0[2 * t2]     = fma2(hh.x, wv.x, acc0[2 * t2]);
            acc1[2 * t2]     = fma2(hh.x, wv.y, acc1[2 * t2]);
            acc0[2 * t2 + 1] = fma2(hh.y, wv.x, acc0[2 * t2 + 1]);
            acc1[2 * t2 + 1] = fma2(hh.y, wv.y, acc1[2 * t2 + 1]);
        }
    }
    float s0 = 0.f, s1 = 0.f, q0 = 0.f, q1 = 0.f;
#pragma unroll
    for (int t = 0; t < 8; t++) {
        float a0l, a0h, a1l, a1h;
        upk(acc0[t], a0l, a0h);
        upk(acc1[t], a1l, a1h);
        int p = p0 + P + 2 * t;
        float2 s0v; s0v.x = a0l; s0v.y = a1l;
        float2 s1v; s1v.x = a0h; s1v.y = a1h;
        ((float2*)(g_y2 + (size_t)p * 64))[lane] = s0v;
        ((float2*)(g_y2 + (size_t)(p + 1) * 64))[lane] = s1v;
        s0 += a0l + a0h; s1 += a1l + a1h;
        q0 = fmaf(a0l, a0l, q0); q0 = fmaf(a0h, a0h, q0);
        q1 = fmaf(a1l, a1l, q1); q1 = fmaf(a1h, a1h, q1);
    }
    atomicAdd(&ssum[2 * lane], s0);     atomicAdd(&ssum[2 * lane + 1], s1);
    atomicAdd(&ssq[2 * lane], q0);      atomicAdd(&ssq[2 * lane + 1], q1);
    __syncthreads();
    if (tid < 64) {
        atomicAdd(&g_stats[128 + tid], (double)ssum[tid]);
        atomicAdd(&g_stats[192 + tid], (double)ssq[tid]);
    }
}

// ---------------- 7: layer 3 (f32x2, 128 positions = 4 groups/block, 16 pos x 4 ch per warp) ----------------
#define XST3 132
__global__ __launch_bounds__(256) void layer3_kernel(const float* __restrict__ b3) {
    __shared__ float xin[64 * XST3];
    __shared__ float ssum[128], ssq[128], smax[8][128];
    int tid = threadIdx.x;
    int p0 = blockIdx.x * 128;
    if (tid < 128) { ssum[tid] = 0.f; ssq[tid] = 0.f; }
    for (int i = tid; i < 128 * 64; i += 256) {
        int p = i >> 6, c = i & 63;
        float y = g_y2[(size_t)(p0 + p) * 64 + c];
        xin[c * XST3 + p] = fmaxf(fmaf(g_bn[128 + c], y, g_bn[192 + c]), 0.f);
    }
    __syncthreads();
    int wid = tid >> 5, lane = tid & 31;
    int P = wid * 16;                                 // 16 positions per warp
    float4 bb = ((const float4*)b3)[lane];            // 4 out channels per lane
    ull acc[4][8];
#pragma unroll
    for (int t = 0; t < 8; t++) {
        acc[0][t] = pk(bb.x, bb.x);
        acc[1][t] = pk(bb.y, bb.y);
        acc[2][t] = pk(bb.z, bb.z);
        acc[3][t] = pk(bb.w, bb.w);
    }
    for (int c = 0; c < 64; c++) {
        const ulonglong2* wr = (const ulonglong2*)(g_w3d + c * 128);
        ulonglong2 wa = wr[2 * lane];
        ulonglong2 wb = wr[2 * lane + 1];
        const float* xr = xin + c * XST3 + P;
#pragma unroll
        for (int t2 = 0; t2 < 4; t2++) {
            ulonglong2 hh = *(const ulonglong2*)(xr + 4 * t2);
            acc[0][2 * t2]     = fma2(hh.x, wa.x, acc[0][2 * t2]);
            acc[1][2 * t2]     = fma2(hh.x, wa.y, acc[1][2 * t2]);
            acc[2][2 * t2]     = fma2(hh.x, wb.x, acc[2][2 * t2]);
            acc[3][2 * t2]     = fma2(hh.x, wb.y, acc[3][2 * t2]);
            acc[0][2 * t2 + 1] = fma2(hh.y, wa.x, acc[0][2 * t2 + 1]);
            acc[1][2 * t2 + 1] = fma2(hh.y, wa.y, acc[1][2 * t2 + 1]);
            acc[2][2 * t2 + 1] = fma2(hh.y, wb.x, acc[2][2 * t2 + 1]);
            acc[3][2 * t2 + 1] = fma2(hh.y, wb.y, acc[3][2 * t2 + 1]);
        }
    }
#pragma unroll
    for (int ch = 0; ch < 4; ch++) {
        float m = -1e30f, s = 0.f, q = 0.f;
#pragma unroll
        for (int t = 0; t < 8; t++) {
            float lo, hi;
            upk(acc[ch][t], lo, hi);
            m = fmaxf(m, fmaxf(lo, hi));
            s += lo + hi;
            q = fmaf(lo, lo, q); q = fmaf(hi, hi, q);
        }
        int o = 4 * lane + ch;
        smax[wid][o] = m;
        atomicAdd(&ssum[o], s);
        atomicAdd(&ssq[o], q);
    }
    __syncthreads();
    // 4 groups per block; group gi is covered by warps {2gi, 2gi+1}
    {
        int o = tid & 127;
        int g0 = tid >> 7;                            // 0..1
#pragma unroll
        for (int gi0 = 0; gi0 < 2; gi0++) {
            int gi = g0 + 2 * gi0;
            float mm = fmaxf(smax[2 * gi][o], smax[2 * gi + 1][o]);
            g_ymax[((size_t)blockIdx.x * 4 + gi) * 128 + o] = mm;
        }
    }
    if (tid < 128) {
        atomicAdd(&g_stats[256 + tid], (double)ssum[tid]);
        atomicAdd(&g_stats[384 + tid], (double)ssq[tid]);
    }
}

// ---------------- 8: finalize new_points = relu(BN3(max-pooled y3)) ----------------
__global__ void finalize_kernel(float* __restrict__ out) {
    int i = blockIdx.x * 256 + threadIdx.x;
    int o = i & 127;
    out[BB * SS * 3 + i] = fmaxf(fmaf(g_bn[256 + o], g_ymax[i], g_bn[384 + o]), 0.f);
}

extern "C" void kernel_launch(void* const* d_in, const int* in_sizes, int n_in,
                              void* d_out, int out_size) {
    const float* xyz   = (const float*)d_in[0];
    const float* pts   = (const float*)d_in[1];
    const float* w1    = (const float*)d_in[2];
    const float* b1    = (const float*)d_in[3];
    const float* g1    = (const float*)d_in[4];
    const float* beta1 = (const float*)d_in[5];
    const float* w2    = (const float*)d_in[6];
    const float* b2    = (const float*)d_in[7];
    const float* g2    = (const float*)d_in[8];
    const float* beta2 = (const float*)d_in[9];
    const float* w3    = (const float*)d_in[10];
    const float* b3    = (const float*)d_in[11];
    const float* g3    = (const float*)d_in[12];
    const float* beta3 = (const float*)d_in[13];
    float* out = (float*)d_out;

    prep_kernel<<<32, 256>>>(w1, w2, w3);
    fps_kernel<<<BB, 512>>>(xyz, out);                    // new_xyz -> out[0 : 49152)
    u_kernel<<<(BB * NN) / 128, 256>>>(xyz, pts);
    v_kernel<<<(BB * SS * 64) / 256, 256>>>(out, w1, b1);
    ballq_kernel<<<(BB * SS) / 8, 256>>>(xyz, out);
    stats1_kernel<<<(BB * SS * KK) / 256, 256>>>();
    bnp_kernel<<<1, 128>>>(g1, beta1, 64, 0, 0);
    layer2_kernel<<<(BB * SS * KK) / 128, 256>>>(b2);
    bnp_kernel<<<1, 128>>>(g2, beta2, 64, 128, 128);
    layer3_kernel<<<(BB * SS * KK) / 128, 256>>>(b3);
    bnp_kernel<<<1, 128>>>(g3, beta3, 128, 256, 256);
    finalize_kernel<<<(BB * SS * 128) / 256, 256>>>(out);
}

// round 8
// speedup vs baseline: 1.5748x; 1.0093x over previous
#include <cuda_runtime.h>
#include <cstdint>

#define BB 16
#define NN 4096
#define SS 1024
#define KK 32
#define C1 67
#define CNT_BN 524288.0

typedef unsigned long long ull;

// ---------------- device scratch (no allocation allowed) ----------------
__device__ __align__(16) float  g_u[BB * NN * 64];              // 16.8 MB
__device__ __align__(16) float  g_v[BB * SS * 64];              // 4.2 MB
__device__            int       g_idx[BB * SS * KK];            // 2 MB
__device__ __align__(16) float  g_y2[(size_t)BB * SS * KK * 64];// 134 MB
__device__ __align__(16) float  g_ymax[BB * SS * 128];          // 8.4 MB
__device__            double    g_stats[512];  // L1: sum@0 sq@64 | L2: 128/192 | L3: 256/384
__device__            float     g_bn[512];     // a1@0 c1@64 | a2@128 c2@192 | a3@256 c3@384
__device__ __align__(16) ull    g_w2d[64 * 64];                 // dup-packed W2^T
__device__ __align__(16) ull    g_w3d[64 * 128];                // dup-packed W3^T

// ---------------- f32x2 helpers ----------------
__device__ __forceinline__ ull fma2(ull a, ull b, ull c) {
    ull d;
    asm("fma.rn.f32x2 %0, %1, %2, %3;" : "=l"(d) : "l"(a), "l"(b), "l"(c));
    return d;
}
__device__ __forceinline__ ull add2(ull a, ull b) {
    ull d;
    asm("add.rn.f32x2 %0, %1, %2;" : "=l"(d) : "l"(a), "l"(b));
    return d;
}
__device__ __forceinline__ ull mul2(ull a, ull b) {
    ull d;
    asm("mul.rn.f32x2 %0, %1, %2;" : "=l"(d) : "l"(a), "l"(b));
    return d;
}
__device__ __forceinline__ ull pk(float a, float b) {
    ull r;
    asm("mov.b64 %0, {%1, %2};" : "=l"(r) : "f"(a), "f"(b));
    return r;
}
__device__ __forceinline__ void upk(ull v, float& a, float& b) {
    asm("mov.b64 {%0, %1}, %2;" : "=f"(a), "=f"(b) : "l"(v));
}

// ================= 1: combined FPS + u + prep  =================
// grid 560 x 512 threads, dynamic smem 68.1 KB
//   blocks 0..15   : FPS (one per batch)
//   blocks 16..527 : u = W1 * [xyz; feat], 128 points/block (W1 packed into smem)
//   blocks 528..559: prep (zero stats, dup-pack W2^T / W3^T)
#define XST1 132
#define U_SMEM_BYTES (C1 * 64 * 8 + C1 * XST1 * 4)   // 34304 + 35376 = 69680

__global__ __launch_bounds__(512) void fps_u_kernel(
        const float* __restrict__ xyz, const float* __restrict__ pts,
        const float* __restrict__ w1, const float* __restrict__ w2,
        const float* __restrict__ w3, float* __restrict__ out_xyz) {
    extern __shared__ char dyns[];
    int bid = blockIdx.x;
    int tid = threadIdx.x;
    int lane = tid & 31, wid = tid >> 5;

    if (bid < BB) {
        // ---------------- FPS (bit-exact, single barrier/iter) ----------------
        unsigned* smaxb = (unsigned*)dyns;            // [2][16]
        int* sidxv = (int*)(dyns + 128);              // [2][16]
        int b = bid;
        const float* xb = xyz + (size_t)b * NN * 3;
        ull px[4], py[4], pz[4];
        float dist[8];
        int base = tid * 8;
#pragma unroll
        for (int t = 0; t < 4; t++) {
            int j0 = base + 2 * t, j1 = j0 + 1;
            px[t] = pk(xb[j0 * 3 + 0], xb[j1 * 3 + 0]);
            py[t] = pk(xb[j0 * 3 + 1], xb[j1 * 3 + 1]);
            pz[t] = pk(xb[j0 * 3 + 2], xb[j1 * 3 + 2]);
            dist[2 * t] = 1e10f;
            dist[2 * t + 1] = 1e10f;
        }
        float cx = xb[0], cy = xb[1], cz = xb[2];
        if (tid == 0) {
            float* op = out_xyz + (size_t)b * SS * 3;
            op[0] = cx; op[1] = cy; op[2] = cz;
        }
        for (int i = 0; i < SS - 1; i++) {
            ull ncx = pk(-cx, -cx);
            ull ncy = pk(-cy, -cy);
            ull ncz = pk(-cz, -cz);
            float lmax = -1.0f; int lidx = 0;
#pragma unroll
            for (int t = 0; t < 4; t++) {
                ull dx = add2(px[t], ncx);            // add(x,-c) == sub(x,c) bitwise
                ull dy = add2(py[t], ncy);
                ull dz = add2(pz[t], ncz);
                ull s = add2(add2(mul2(dx, dx), mul2(dy, dy)), mul2(dz, dz));
                float slo, shi;
                upk(s, slo, shi);
                float d0 = fminf(dist[2 * t], slo);
                float d1 = fminf(dist[2 * t + 1], shi);
                dist[2 * t] = d0;
                dist[2 * t + 1] = d1;
                if (d0 > lmax) { lmax = d0; lidx = base + 2 * t; }
                if (d1 > lmax) { lmax = d1; lidx = base + 2 * t + 1; }
            }
            unsigned mb = __float_as_uint(lmax);
            unsigned wm = __reduce_max_sync(0xffffffffu, mb);
            int cand = (mb == wm) ? lidx : 0x7fffffff;
            int wi = __reduce_min_sync(0xffffffffu, cand);
            int par = i & 1;
            if (lane == 0) { smaxb[par * 16 + wid] = wm; sidxv[par * 16 + wid] = wi; }
            __syncthreads();
            unsigned vb = (lane < 16) ? smaxb[par * 16 + lane] : 0u;
            int vi = (lane < 16) ? sidxv[par * 16 + lane] : 0x7fffffff;
            unsigned m2 = __reduce_max_sync(0xffffffffu, vb);
            int c2 = (vb == m2) ? vi : 0x7fffffff;
            int far = __reduce_min_sync(0xffffffffu, c2);
            const float* cp = xb + (size_t)far * 3;
            cx = cp[0]; cy = cp[1]; cz = cp[2];
            if (tid == 0) {
                float* op = out_xyz + ((size_t)b * SS + i + 1) * 3;
                op[0] = cx; op[1] = cy; op[2] = cz;
            }
        }
    } else if (bid < 528) {
        // ---------------- u: 128 points/block, 512 threads ----------------
        ull* wsm = (ull*)dyns;                        // [C1][64] dup-packed
        float* xin = (float*)(dyns + C1 * 64 * 8);    // [C1][XST1] channel-major
        int p0 = (bid - 16) * 128;
        for (int i = tid; i < C1 * 64; i += 512) {
            int c = i >> 6, o = i & 63;
            float w = w1[o * C1 + c];
            wsm[i] = pk(w, w);
        }
        for (int i = tid; i < 68 * 128; i += 512) {
            int p = i / 68, c = i % 68;
            if (c < C1) {
                float v = (c < 3) ? xyz[(size_t)(p0 + p) * 3 + c]
                                  : pts[(size_t)(p0 + p) * 64 + (c - 3)];
                xin[c * XST1 + p] = v;
            }
        }
        __syncthreads();
        int P = wid * 8;                               // 8 positions per warp
        ull a0[4], a1[4];
#pragma unroll
        for (int t = 0; t < 4; t++) { a0[t] = 0ull; a1[t] = 0ull; }
        for (int c = 0; c < C1; c++) {
            ulonglong2 wv = ((const ulonglong2*)(wsm + c * 64))[lane];
            const float* xr = xin + c * XST1 + P;
            ulonglong2 h0 = *(const ulonglong2*)(xr);
            ulonglong2 h1 = *(const ulonglong2*)(xr + 4);
            a0[0] = fma2(h0.x, wv.x, a0[0]); a1[0] = fma2(h0.x, wv.y, a1[0]);
            a0[1] = fma2(h0.y, wv.x, a0[1]); a1[1] = fma2(h0.y, wv.y, a1[1]);
            a0[2] = fma2(h1.x, wv.x, a0[2]); a1[2] = fma2(h1.x, wv.y, a1[2]);
            a0[3] = fma2(h1.y, wv.x, a0[3]); a1[3] = fma2(h1.y, wv.y, a1[3]);
        }
#pragma unroll
        for (int t = 0; t < 4; t++) {
            float a0l, a0h, a1l, a1h;
            upk(a0[t], a0l, a0h);
            upk(a1[t], a1l, a1h);
            int p = p0 + P + 2 * t;
            float2 s0; s0.x = a0l; s0.y = a1l;
            float2 s1; s1.x = a0h; s1.y = a1h;
            ((float2*)(g_u + (size_t)p * 64))[lane] = s0;
            ((float2*)(g_u + (size_t)(p + 1) * 64))[lane] = s1;
        }
    } else {
        // ---------------- prep ----------------
        int i = (bid - 528) * 512 + tid;               // 0..16383
        if (i < 512) g_stats[i] = 0.0;
        if (i < 64 * 64) {
            int c = i >> 6, o = i & 63;
            float w = w2[o * 64 + c];
            g_w2d[i] = pk(w, w);
        }
        if (i < 64 * 128) {
            int c = i >> 7, o = i & 127;
            float w = w3[o * 64 + c];
            g_w3d[i] = pk(w, w);
        }
    }
}

// ---------------- 2: ball query + fused v = b1 - W1[:, :3]*c ----------------
__global__ void ballq_kernel(const float* __restrict__ xyz, const float* __restrict__ newxyz,
                             const float* __restrict__ w1, const float* __restrict__ b1) {
    int gw = blockIdx.x * 8 + (threadIdx.x >> 5);
    int lane = threadIdx.x & 31;
    int b = gw >> 10;
    const float* cp = newxyz + (size_t)gw * 3;
    float sx = cp[0], sy = cp[1], sz = cp[2];
    float sn = __fadd_rn(__fadd_rn(__fmul_rn(sx, sx), __fmul_rn(sy, sy)), __fmul_rn(sz, sz));
    const float* xb = xyz + (size_t)b * NN * 3;
    const float R2 = (float)(0.2 * 0.2);
    int cnt = 0, first = -1;
    int* op = g_idx + (size_t)gw * KK;
    for (int basep = 0; basep < NN && cnt < KK; basep += 32) {
        int n = basep + lane;
        float nx = xb[n * 3 + 0], ny = xb[n * 3 + 1], nz = xb[n * 3 + 2];
        float dn = __fadd_rn(__fadd_rn(__fmul_rn(nx, nx), __fmul_rn(ny, ny)), __fmul_rn(nz, nz));
        float dt = __fadd_rn(__fadd_rn(__fmul_rn(sx, nx), __fmul_rn(sy, ny)), __fmul_rn(sz, nz));
        float sqr = __fadd_rn(__fadd_rn(__fmul_rn(-2.0f, dt), sn), dn);
        bool ok = !(sqr > R2);
        unsigned bal = __ballot_sync(0xffffffffu, ok);
        if (first < 0 && bal) first = basep + (__ffs(bal) - 1);
        int pos = cnt + __popc(bal & ((1u << lane) - 1u));
        if (ok && pos < KK) op[pos] = n;
        cnt += __popc(bal);
    }
    for (int s = cnt + lane; s < KK; s += 32) op[s] = first;
    // fused v: 2 output channels per lane
    int o = 2 * lane;
    const float* wr0 = w1 + (size_t)o * C1;
    const float* wr1 = wr0 + C1;
    float2 res;
    res.x = b1[o]     - (wr0[0] * sx + wr0[1] * sy + wr0[2] * sz);
    res.y = b1[o + 1] - (wr1[0] * sx + wr1[1] * sy + wr1[2] * sz);
    ((float2*)(g_v + (size_t)gw * 64))[lane] = res;
}

// ---------------- 3: BN1 statistics over y1 = u[idx] + v  (f32x2, 4ch/thread) ----------------
__global__ void stats1_kernel() {
    __shared__ float red[2][16][64];
    int tid = threadIdx.x;
    int l16 = tid & 15;          // channel quad: ch 4*l16 .. 4*l16+3
    int strip = tid >> 4;        // 0..15, each strip = one 32-instance group
    int inst0 = blockIdx.x * 512 + strip * 32;
    int g = inst0 >> 5;
    int b = g >> 10;
    ulonglong2 vv = ((const ulonglong2*)(g_v + (size_t)g * 64))[l16];
    ull s0 = 0ull, s1 = 0ull, q0 = 0ull, q1 = 0ull;
#pragma unroll 4
    for (int ii = 0; ii < 32; ii++) {
        int pt = g_idx[inst0 + ii];
        ulonglong2 uu = ((const ulonglong2*)(g_u + (((size_t)b << 12) + pt) * 64))[l16];
        ull y0 = add2(uu.x, vv.x);
        ull y1 = add2(uu.y, vv.y);
        s0 = add2(s0, y0); s1 = add2(s1, y1);
        q0 = fma2(y0, y0, q0); q1 = fma2(y1, y1, q1);
    }
    {
        float a, bq;
        upk(s0, a, bq); red[0][strip][4 * l16 + 0] = a; red[0][strip][4 * l16 + 1] = bq;
        upk(s1, a, bq); red[0][strip][4 * l16 + 2] = a; red[0][strip][4 * l16 + 3] = bq;
        upk(q0, a, bq); red[1][strip][4 * l16 + 0] = a; red[1][strip][4 * l16 + 1] = bq;
        upk(q1, a, bq); red[1][strip][4 * l16 + 2] = a; red[1][strip][4 * l16 + 3] = bq;
    }
    __syncthreads();
    if (tid < 64) {
        double ds = 0.0, dq = 0.0;
#pragma unroll
        for (int r = 0; r < 16; r++) { ds += red[0][r][tid]; dq += red[1][r][tid]; }
        atomicAdd(&g_stats[0 + tid], ds);
        atomicAdd(&g_stats[64 + tid], dq);
    }
}

// ---------------- BN params ----------------
__global__ void bnp_kernel(const float* __restrict__ gamma, const float* __restrict__ beta,
                           int nch, int stats_off, int bn_off) {
    int o = threadIdx.x;
    if (o >= nch) return;
    double mean = g_stats[stats_off + o] / CNT_BN;
    double var = g_stats[stats_off + nch + o] / CNT_BN - mean * mean;
    double a = (double)gamma[o] / sqrt(var + 1e-5);
    g_bn[bn_off + o] = (float)a;
    g_bn[bn_off + nch + o] = (float)((double)beta[o] - mean * a);
}

// ---------------- 4: layer 2 (f32x2, 128 positions/block, LDS.128 activations) ----------------
#define XST2 132
__global__ __launch_bounds__(256) void layer2_kernel(const float* __restrict__ b2) {
    __shared__ float xin[64 * XST2];
    __shared__ float ssum[64], ssq[64];
    int tid = threadIdx.x;
    int p0 = blockIdx.x * 128;
    if (tid < 64) { ssum[tid] = 0.f; ssq[tid] = 0.f; }
    for (int i = tid; i < 128 * 64; i += 256) {
        int p = i >> 6, c = i & 63;
        int inst = p0 + p;
        int g = inst >> 5;
        int b = g >> 10;
        int pt = g_idx[inst];
        float y = g_u[(((size_t)b << 12) + pt) * 64 + c] + g_v[(size_t)g * 64 + c];
        xin[c * XST2 + p] = fmaxf(fmaf(g_bn[c], y, g_bn[64 + c]), 0.f);
    }
    __syncthreads();
    int wid = tid >> 5, lane = tid & 31;
    int P = wid * 16;
    float2 bb = ((const float2*)b2)[lane];
    ull bi0 = pk(bb.x, bb.x), bi1 = pk(bb.y, bb.y);
    ull acc0[8], acc1[8];
#pragma unroll
    for (int t = 0; t < 8; t++) { acc0[t] = bi0; acc1[t] = bi1; }
    for (int c = 0; c < 64; c++) {
        ulonglong2 wv = ((const ulonglong2*)(g_w2d + c * 64))[lane];
        const float* xr = xin + c * XST2 + P;
#pragma unroll
        for (int t2 = 0; t2 < 4; t2++) {
            ulonglong2 hh = *(const ulonglong2*)(xr + 4 * t2);
            acc0[2 * t2]     = fma2(hh.x, wv.x, acc0[2 * t2]);
            acc1[2 * t2]     = fma2(hh.x, wv.y, acc1[2 * t2]);
            acc0[2 * t2 + 1] = fma2(hh.y, wv.x, acc0[2 * t2 + 1]);
            acc1[2 * t2 + 1] = fma2(hh.y, wv.y, acc1[2 * t2 + 1]);
        }
    }
    float s0 = 0.f, s1 = 0.f, q0 = 0.f, q1 = 0.f;
#pragma unroll
    for (int t = 0; t < 8; t++) {
        float a0l, a0h, a1l, a1h;
        upk(acc0[t], a0l, a0h);
        upk(acc1[t], a1l, a1h);
        int p = p0 + P + 2 * t;
        float2 s0v; s0v.x = a0l; s0v.y = a1l;
        float2 s1v; s1v.x = a0h; s1v.y = a1h;
        ((float2*)(g_y2 + (size_t)p * 64))[lane] = s0v;
        ((float2*)(g_y2 + (size_t)(p + 1) * 64))[lane] = s1v;
        s0 += a0l + a0h; s1 += a1l + a1h;
        q0 = fmaf(a0l, a0l, q0); q0 = fmaf(a0h, a0h, q0);
        q1 = fmaf(a1l, a1l, q1); q1 = fmaf(a1h, a1h, q1);
    }
    atomicAdd(&ssum[2 * lane], s0);     atomicAdd(&ssum[2 * lane + 1], s1);
    atomicAdd(&ssq[2 * lane], q0);      atomicAdd(&ssq[2 * lane + 1], q1);
    __syncthreads();
    if (tid < 64) {
        atomicAdd(&g_stats[128 + tid], (double)ssum[tid]);
        atomicAdd(&g_stats[192 + tid], (double)ssq[tid]);
    }
}

// ---------------- 5: layer 3 (f32x2, 128 positions = 4 groups/block) ----------------
#define XST3 132
__global__ __launch_bounds__(256) void layer3_kernel(const float* __restrict__ b3) {
    __shared__ float xin[64 * XST3];
    __shared__ float ssum[128], ssq[128], smax[8][128];
    int tid = threadIdx.x;
    int p0 = blockIdx.x * 128;
    if (tid < 128) { ssum[tid] = 0.f; ssq[tid] = 0.f; }
    for (int i = tid; i < 128 * 64; i += 256) {
        int p = i >> 6, c = i & 63;
        float y = g_y2[(size_t)(p0 + p) * 64 + c];
        xin[c * XST3 + p] = fmaxf(fmaf(g_bn[128 + c], y, g_bn[192 + c]), 0.f);
    }
    __syncthreads();
    int wid = tid >> 5, lane = tid & 31;
    int P = wid * 16;
    float4 bb = ((const float4*)b3)[lane];
    ull acc[4][8];
#pragma unroll
    for (int t = 0; t < 8; t++) {
        acc[0][t] = pk(bb.x, bb.x);
        acc[1][t] = pk(bb.y, bb.y);
        acc[2][t] = pk(bb.z, bb.z);
        acc[3][t] = pk(bb.w, bb.w);
    }
    for (int c = 0; c < 64; c++) {
        const ulonglong2* wr = (const ulonglong2*)(g_w3d + c * 128);
        ulonglong2 wa = wr[2 * lane];
        ulonglong2 wb = wr[2 * lane + 1];
        const float* xr = xin + c * XST3 + P;
#pragma unroll
        for (int t2 = 0; t2 < 4; t2++) {
            ulonglong2 hh = *(const ulonglong2*)(xr + 4 * t2);
            acc[0][2 * t2]     = fma2(hh.x, wa.x, acc[0][2 * t2]);
            acc[1][2 * t2]     = fma2(hh.x, wa.y, acc[1][2 * t2]);
            acc[2][2 * t2]     = fma2(hh.x, wb.x, acc[2][2 * t2]);
            acc[3][2 * t2]     = fma2(hh.x, wb.y, acc[3][2 * t2]);
            acc[0][2 * t2 + 1] = fma2(hh.y, wa.x, acc[0][2 * t2 + 1]);
            acc[1][2 * t2 + 1] = fma2(hh.y, wa.y, acc[1][2 * t2 + 1]);
            acc[2][2 * t2 + 1] = fma2(hh.y, wb.x, acc[2][2 * t2 + 1]);
            acc[3][2 * t2 + 1] = fma2(hh.y, wb.y, acc[3][2 * t2 + 1]);
        }
    }
#pragma unroll
    for (int ch = 0; ch < 4; ch++) {
        float m = -1e30f, s = 0.f, q = 0.f;
#pragma unroll
        for (int t = 0; t < 8; t++) {
            float lo, hi;
            upk(acc[ch][t], lo, hi);
            m = fmaxf(m, fmaxf(lo, hi));
            s += lo + hi;
            q = fmaf(lo, lo, q); q = fmaf(hi, hi, q);
        }
        int o = 4 * lane + ch;
        smax[wid][o] = m;
        atomicAdd(&ssum[o], s);
        atomicAdd(&ssq[o], q);
    }
    __syncthreads();
    {
        int o = tid & 127;
        int g0 = tid >> 7;
#pragma unroll
        for (int gi0 = 0; gi0 < 2; gi0++) {
            int gi = g0 + 2 * gi0;
            float mm = fmaxf(smax[2 * gi][o], smax[2 * gi + 1][o]);
            g_ymax[((size_t)blockIdx.x * 4 + gi) * 128 + o] = mm;
        }
    }
    if (tid < 128) {
        atomicAdd(&g_stats[256 + tid], (double)ssum[tid]);
        atomicAdd(&g_stats[384 + tid], (double)ssq[tid]);
    }
}

// ---------------- 6: finalize new_points = relu(BN3(max-pooled y3)) ----------------
__global__ void finalize_kernel(float* __restrict__ out) {
    int i = blockIdx.x * 256 + threadIdx.x;
    int o = i & 127;
    out[BB * SS * 3 + i] = fmaxf(fmaf(g_bn[256 + o], g_ymax[i], g_bn[384 + o]), 0.f);
}

extern "C" void kernel_launch(void* const* d_in, const int* in_sizes, int n_in,
                              void* d_out, int out_size) {
    const float* xyz   = (const float*)d_in[0];
    const float* pts   = (const float*)d_in[1];
    const float* w1    = (const float*)d_in[2];
    const float* b1    = (const float*)d_in[3];
    const float* g1    = (const float*)d_in[4];
    const float* beta1 = (const float*)d_in[5];
    const float* w2    = (const float*)d_in[6];
    const float* b2    = (const float*)d_in[7];
    const float* g2    = (const float*)d_in[8];
    const float* beta2 = (const float*)d_in[9];
    const float* w3    = (const float*)d_in[10];
    const float* b3    = (const float*)d_in[11];
    const float* g3    = (const float*)d_in[12];
    const float* beta3 = (const float*)d_in[13];
    float* out = (float*)d_out;

    cudaFuncSetAttribute(fps_u_kernel, cudaFuncAttributeMaxDynamicSharedMemorySize,
                         U_SMEM_BYTES + 16);
    fps_u_kernel<<<560, 512, U_SMEM_BYTES + 16>>>(xyz, pts, w1, w2, w3, out);
    ballq_kernel<<<(BB * SS) / 8, 256>>>(xyz, out, w1, b1);
    stats1_kernel<<<(BB * SS * KK) / 512, 256>>>();
    bnp_kernel<<<1, 128>>>(g1, beta1, 64, 0, 0);
    layer2_kernel<<<(BB * SS * KK) / 128, 256>>>(b2);
    bnp_kernel<<<1, 128>>>(g2, beta2, 64, 128, 128);
    layer3_kernel<<<(BB * SS * KK) / 128, 256>>>(b3);
    bnp_kernel<<<1, 128>>>(g3, beta3, 128, 256, 256);
    finalize_kernel<<<(BB * SS * 128) / 256, 256>>>(out);
}

// round 9
// speedup vs baseline: 1.6488x; 1.0470x over previous
#include <cuda_runtime.h>
#include <cstdint>

#define BB 16
#define NN 4096
#define SS 1024
#define KK 32
#define C1 67
#define CNT_BN 524288.0

typedef unsigned long long ull;

// ---------------- device scratch (no allocation allowed) ----------------
__device__ __align__(16) float  g_u[BB * NN * 64];              // 16.8 MB
__device__ __align__(16) float  g_v[BB * SS * 64];              // 4.2 MB
__device__            int       g_idx[BB * SS * KK];            // 2 MB
__device__ __align__(16) float  g_y2[(size_t)BB * SS * KK * 64];// 134 MB
__device__ __align__(16) float  g_ymax[BB * SS * 128];          // 8.4 MB
__device__            double    g_stats[512];  // L1: sum@0 sq@64 | L2: 128/192 | L3: 256/384
__device__            float     g_bn[512];     // a1@0 c1@64 | a2@128 c2@192 | a3@256 c3@384
__device__ __align__(16) ull    g_w2d[64 * 64];                 // dup-packed W2^T
__device__ __align__(16) ull    g_w3d[64 * 128];                // dup-packed W3^T
__device__            int       g_cnt1 = 0, g_cnt2 = 0, g_cnt3 = 0;  // last-block tickets

// ---------------- f32x2 helpers ----------------
__device__ __forceinline__ ull fma2(ull a, ull b, ull c) {
    ull d;
    asm("fma.rn.f32x2 %0, %1, %2, %3;" : "=l"(d) : "l"(a), "l"(b), "l"(c));
    return d;
}
__device__ __forceinline__ ull add2(ull a, ull b) {
    ull d;
    asm("add.rn.f32x2 %0, %1, %2;" : "=l"(d) : "l"(a), "l"(b));
    return d;
}
__device__ __forceinline__ ull mul2(ull a, ull b) {
    ull d;
    asm("mul.rn.f32x2 %0, %1, %2;" : "=l"(d) : "l"(a), "l"(b));
    return d;
}
__device__ __forceinline__ ull pk(float a, float b) {
    ull r;
    asm("mov.b64 %0, {%1, %2};" : "=l"(r) : "f"(a), "f"(b));
    return r;
}
__device__ __forceinline__ void upk(ull v, float& a, float& b) {
    asm("mov.b64 {%0, %1}, %2;" : "=f"(a), "=f"(b) : "l"(v));
}

// ---------------- BN param fold (runs in last block of producer kernel) ----------------
__device__ __forceinline__ void bnp_tail(const float* gamma, const float* beta,
                                         int nch, int stats_off, int bn_off, int tid) {
    if (tid < nch) {
        volatile double* vs = g_stats;               // read-through to L2 (atomics' home)
        double mean = vs[stats_off + tid] / CNT_BN;
        double var = vs[stats_off + nch + tid] / CNT_BN - mean * mean;
        double a = (double)gamma[tid] / sqrt(var + 1e-5);
        g_bn[bn_off + tid] = (float)a;
        g_bn[bn_off + nch + tid] = (float)((double)beta[tid] - mean * a);
    }
}

// ================= 1: combined FPS + u + prep  =================
// grid 560 x 512 threads, dynamic smem 116 KB (forces 1 block/SM -> FPS exclusivity)
//   blocks 0..15   : FPS (one per batch)
//   blocks 16..527 : u = W1 * [xyz; feat], 128 points/block (W1 packed into smem)
//   blocks 528..559: prep (zero stats, dup-pack W2^T / W3^T)
#define XST1 132
#define U_SMEM_BYTES (116 * 1024)                    // > 228KB/2 -> exactly 1 block/SM

__global__ __launch_bounds__(512) void fps_u_kernel(
        const float* __restrict__ xyz, const float* __restrict__ pts,
        const float* __restrict__ w1, const float* __restrict__ w2,
        const float* __restrict__ w3, float* __restrict__ out_xyz) {
    extern __shared__ char dyns[];
    int bid = blockIdx.x;
    int tid = threadIdx.x;
    int lane = tid & 31, wid = tid >> 5;

    if (bid < BB) {
        // ---------------- FPS (bit-exact, single barrier/iter) ----------------
        unsigned* smaxb = (unsigned*)dyns;            // [2][16]
        int* sidxv = (int*)(dyns + 128);              // [2][16]
        int b = bid;
        const float* xb = xyz + (size_t)b * NN * 3;
        ull px[4], py[4], pz[4];
        float dist[8];
        int base = tid * 8;
#pragma unroll
        for (int t = 0; t < 4; t++) {
            int j0 = base + 2 * t, j1 = j0 + 1;
            px[t] = pk(xb[j0 * 3 + 0], xb[j1 * 3 + 0]);
            py[t] = pk(xb[j0 * 3 + 1], xb[j1 * 3 + 1]);
            pz[t] = pk(xb[j0 * 3 + 2], xb[j1 * 3 + 2]);
            dist[2 * t] = 1e10f;
            dist[2 * t + 1] = 1e10f;
        }
        float cx = xb[0], cy = xb[1], cz = xb[2];
        if (tid == 0) {
            float* op = out_xyz + (size_t)b * SS * 3;
            op[0] = cx; op[1] = cy; op[2] = cz;
        }
        for (int i = 0; i < SS - 1; i++) {
            ull ncx = pk(-cx, -cx);
            ull ncy = pk(-cy, -cy);
            ull ncz = pk(-cz, -cz);
            float lmax = -1.0f; int lidx = 0;
#pragma unroll
            for (int t = 0; t < 4; t++) {
                ull dx = add2(px[t], ncx);            // add(x,-c) == sub(x,c) bitwise
                ull dy = add2(py[t], ncy);
                ull dz = add2(pz[t], ncz);
                ull s = add2(add2(mul2(dx, dx), mul2(dy, dy)), mul2(dz, dz));
                float slo, shi;
                upk(s, slo, shi);
                float d0 = fminf(dist[2 * t], slo);
                float d1 = fminf(dist[2 * t + 1], shi);
                dist[2 * t] = d0;
                dist[2 * t + 1] = d1;
                if (d0 > lmax) { lmax = d0; lidx = base + 2 * t; }
                if (d1 > lmax) { lmax = d1; lidx = base + 2 * t + 1; }
            }
            unsigned mb = __float_as_uint(lmax);
            unsigned wm = __reduce_max_sync(0xffffffffu, mb);
            int cand = (mb == wm) ? lidx : 0x7fffffff;
            int wi = __reduce_min_sync(0xffffffffu, cand);
            int par = i & 1;
            if (lane == 0) { smaxb[par * 16 + wid] = wm; sidxv[par * 16 + wid] = wi; }
            __syncthreads();
            unsigned vb = (lane < 16) ? smaxb[par * 16 + lane] : 0u;
            int vi = (lane < 16) ? sidxv[par * 16 + lane] : 0x7fffffff;
            unsigned m2 = __reduce_max_sync(0xffffffffu, vb);
            int c2 = (vb == m2) ? vi : 0x7fffffff;
            int far = __reduce_min_sync(0xffffffffu, c2);
            const float* cp = xb + (size_t)far * 3;
            cx = cp[0]; cy = cp[1]; cz = cp[2];
            if (tid == 0) {
                float* op = out_xyz + ((size_t)b * SS + i + 1) * 3;
                op[0] = cx; op[1] = cy; op[2] = cz;
            }
        }
    } else if (bid < 528) {
        // ---------------- u: 128 points/block, 512 threads ----------------
        ull* wsm = (ull*)dyns;                        // [C1][64] dup-packed
        float* xin = (float*)(dyns + C1 * 64 * 8);    // [C1][XST1] channel-major
        int p0 = (bid - 16) * 128;
        for (int i = tid; i < C1 * 64; i += 512) {
            int c = i >> 6, o = i & 63;
            float w = w1[o * C1 + c];
            wsm[i] = pk(w, w);
        }
        for (int i = tid; i < 68 * 128; i += 512) {
            int p = i / 68, c = i % 68;
            if (c < C1) {
                float v = (c < 3) ? xyz[(size_t)(p0 + p) * 3 + c]
                                  : pts[(size_t)(p0 + p) * 64 + (c - 3)];
                xin[c * XST1 + p] = v;
            }
        }
        __syncthreads();
        int P = wid * 8;                               // 8 positions per warp
        ull a0[4], a1[4];
#pragma unroll
        for (int t = 0; t < 4; t++) { a0[t] = 0ull; a1[t] = 0ull; }
        for (int c = 0; c < C1; c++) {
            ulonglong2 wv = ((const ulonglong2*)(wsm + c * 64))[lane];
            const float* xr = xin + c * XST1 + P;
            ulonglong2 h0 = *(const ulonglong2*)(xr);
            ulonglong2 h1 = *(const ulonglong2*)(xr + 4);
            a0[0] = fma2(h0.x, wv.x, a0[0]); a1[0] = fma2(h0.x, wv.y, a1[0]);
            a0[1] = fma2(h0.y, wv.x, a0[1]); a1[1] = fma2(h0.y, wv.y, a1[1]);
            a0[2] = fma2(h1.x, wv.x, a0[2]); a1[2] = fma2(h1.x, wv.y, a1[2]);
            a0[3] = fma2(h1.y, wv.x, a0[3]); a1[3] = fma2(h1.y, wv.y, a1[3]);
        }
#pragma unroll
        for (int t = 0; t < 4; t++) {
            float a0l, a0h, a1l, a1h;
            upk(a0[t], a0l, a0h);
            upk(a1[t], a1l, a1h);
            int p = p0 + P + 2 * t;
            float2 s0; s0.x = a0l; s0.y = a1l;
            float2 s1; s1.x = a0h; s1.y = a1h;
            ((float2*)(g_u + (size_t)p * 64))[lane] = s0;
            ((float2*)(g_u + (size_t)(p + 1) * 64))[lane] = s1;
        }
    } else {
        // ---------------- prep ----------------
        int i = (bid - 528) * 512 + tid;               // 0..16383
        if (i < 512) g_stats[i] = 0.0;
        if (i < 64 * 64) {
            int c = i >> 6, o = i & 63;
            float w = w2[o * 64 + c];
            g_w2d[i] = pk(w, w);
        }
        if (i < 64 * 128) {
            int c = i >> 7, o = i & 127;
            float w = w3[o * 64 + c];
            g_w3d[i] = pk(w, w);
        }
    }
}

// ---------------- 2: ball query + fused v = b1 - W1[:, :3]*c ----------------
__global__ void ballq_kernel(const float* __restrict__ xyz, const float* __restrict__ newxyz,
                             const float* __restrict__ w1, const float* __restrict__ b1) {
    int gw = blockIdx.x * 8 + (threadIdx.x >> 5);
    int lane = threadIdx.x & 31;
    int b = gw >> 10;
    const float* cp = newxyz + (size_t)gw * 3;
    float sx = cp[0], sy = cp[1], sz = cp[2];
    float sn = __fadd_rn(__fadd_rn(__fmul_rn(sx, sx), __fmul_rn(sy, sy)), __fmul_rn(sz, sz));
    const float* xb = xyz + (size_t)b * NN * 3;
    const float R2 = (float)(0.2 * 0.2);
    int cnt = 0, first = -1;
    int* op = g_idx + (size_t)gw * KK;
    for (int basep = 0; basep < NN && cnt < KK; basep += 32) {
        int n = basep + lane;
        float nx = xb[n * 3 + 0], ny = xb[n * 3 + 1], nz = xb[n * 3 + 2];
        float dn = __fadd_rn(__fadd_rn(__fmul_rn(nx, nx), __fmul_rn(ny, ny)), __fmul_rn(nz, nz));
        float dt = __fadd_rn(__fadd_rn(__fmul_rn(sx, nx), __fmul_rn(sy, ny)), __fmul_rn(sz, nz));
        float sqr = __fadd_rn(__fadd_rn(__fmul_rn(-2.0f, dt), sn), dn);
        bool ok = !(sqr > R2);
        unsigned bal = __ballot_sync(0xffffffffu, ok);
        if (first < 0 && bal) first = basep + (__ffs(bal) - 1);
        int pos = cnt + __popc(bal & ((1u << lane) - 1u));
        if (ok && pos < KK) op[pos] = n;
        cnt += __popc(bal);
    }
    for (int s = cnt + lane; s < KK; s += 32) op[s] = first;
    // fused v: 2 output channels per lane
    int o = 2 * lane;
    const float* wr0 = w1 + (size_t)o * C1;
    const float* wr1 = wr0 + C1;
    float2 res;
    res.x = b1[o]     - (wr0[0] * sx + wr0[1] * sy + wr0[2] * sz);
    res.y = b1[o + 1] - (wr1[0] * sx + wr1[1] * sy + wr1[2] * sz);
    ((float2*)(g_v + (size_t)gw * 64))[lane] = res;
}

// ---------------- 3: BN1 statistics over y1 = u[idx] + v  (f32x2) + bnp1 tail ----------------
#define STATS1_GRID ((BB * SS * KK) / 512)
__global__ void stats1_kernel(const float* __restrict__ g1, const float* __restrict__ beta1) {
    __shared__ float red[2][16][64];
    __shared__ int slast;
    int tid = threadIdx.x;
    int l16 = tid & 15;          // channel quad: ch 4*l16 .. 4*l16+3
    int strip = tid >> 4;        // 0..15, each strip = one 32-instance group
    int inst0 = blockIdx.x * 512 + strip * 32;
    int g = inst0 >> 5;
    int b = g >> 10;
    ulonglong2 vv = ((const ulonglong2*)(g_v + (size_t)g * 64))[l16];
    ull s0 = 0ull, s1 = 0ull, q0 = 0ull, q1 = 0ull;
#pragma unroll 4
    for (int ii = 0; ii < 32; ii++) {
        int pt = g_idx[inst0 + ii];
        ulonglong2 uu = ((const ulonglong2*)(g_u + (((size_t)b << 12) + pt) * 64))[l16];
        ull y0 = add2(uu.x, vv.x);
        ull y1 = add2(uu.y, vv.y);
        s0 = add2(s0, y0); s1 = add2(s1, y1);
        q0 = fma2(y0, y0, q0); q1 = fma2(y1, y1, q1);
    }
    {
        float a, bq;
        upk(s0, a, bq); red[0][strip][4 * l16 + 0] = a; red[0][strip][4 * l16 + 1] = bq;
        upk(s1, a, bq); red[0][strip][4 * l16 + 2] = a; red[0][strip][4 * l16 + 3] = bq;
        upk(q0, a, bq); red[1][strip][4 * l16 + 0] = a; red[1][strip][4 * l16 + 1] = bq;
        upk(q1, a, bq); red[1][strip][4 * l16 + 2] = a; red[1][strip][4 * l16 + 3] = bq;
    }
    __syncthreads();
    if (tid < 64) {
        double ds = 0.0, dq = 0.0;
#pragma unroll
        for (int r = 0; r < 16; r++) { ds += red[0][r][tid]; dq += red[1][r][tid]; }
        atomicAdd(&g_stats[0 + tid], ds);
        atomicAdd(&g_stats[64 + tid], dq);
    }
    __threadfence();
    __syncthreads();
    if (tid == 0) slast = (atomicAdd(&g_cnt1, 1) == STATS1_GRID - 1);
    __syncthreads();
    if (slast) {
        bnp_tail(g1, beta1, 64, 0, 0, tid);
        if (tid == 0) g_cnt1 = 0;                    // reset for graph replay
    }
}

// ---------------- 4: layer 2 (f32x2) + bnp2 tail ----------------
#define XST2 132
#define L2_GRID ((BB * SS * KK) / 128)
__global__ __launch_bounds__(256) void layer2_kernel(const float* __restrict__ b2,
                                                     const float* __restrict__ g2,
                                                     const float* __restrict__ beta2) {
    __shared__ float xin[64 * XST2];
    __shared__ float ssum[64], ssq[64];
    __shared__ int slast;
    int tid = threadIdx.x;
    int p0 = blockIdx.x * 128;
    if (tid < 64) { ssum[tid] = 0.f; ssq[tid] = 0.f; }
    for (int i = tid; i < 128 * 64; i += 256) {
        int p = i >> 6, c = i & 63;
        int inst = p0 + p;
        int g = inst >> 5;
        int b = g >> 10;
        int pt = g_idx[inst];
        float y = g_u[(((size_t)b << 12) + pt) * 64 + c] + g_v[(size_t)g * 64 + c];
        xin[c * XST2 + p] = fmaxf(fmaf(g_bn[c], y, g_bn[64 + c]), 0.f);
    }
    __syncthreads();
    int wid = tid >> 5, lane = tid & 31;
    int P = wid * 16;
    float2 bb = ((const float2*)b2)[lane];
    ull bi0 = pk(bb.x, bb.x), bi1 = pk(bb.y, bb.y);
    ull acc0[8], acc1[8];
#pragma unroll
    for (int t = 0; t < 8; t++) { acc0[t] = bi0; acc1[t] = bi1; }
    for (int c = 0; c < 64; c++) {
        ulonglong2 wv = ((const ulonglong2*)(g_w2d + c * 64))[lane];
        const float* xr = xin + c * XST2 + P;
#pragma unroll
        for (int t2 = 0; t2 < 4; t2++) {
            ulonglong2 hh = *(const ulonglong2*)(xr + 4 * t2);
            acc0[2 * t2]     = fma2(hh.x, wv.x, acc0[2 * t2]);
            acc1[2 * t2]     = fma2(hh.x, wv.y, acc1[2 * t2]);
            acc0[2 * t2 + 1] = fma2(hh.y, wv.x, acc0[2 * t2 + 1]);
            acc1[2 * t2 + 1] = fma2(hh.y, wv.y, acc1[2 * t2 + 1]);
        }
    }
    float s0 = 0.f, s1 = 0.f, q0 = 0.f, q1 = 0.f;
#pragma unroll
    for (int t = 0; t < 8; t++) {
        float a0l, a0h, a1l, a1h;
        upk(acc0[t], a0l, a0h);
        upk(acc1[t], a1l, a1h);
        int p = p0 + P + 2 * t;
        float2 s0v; s0v.x = a0l; s0v.y = a1l;
        float2 s1v; s1v.x = a0h; s1v.y = a1h;
        ((float2*)(g_y2 + (size_t)p * 64))[lane] = s0v;
        ((float2*)(g_y2 + (size_t)(p + 1) * 64))[lane] = s1v;
        s0 += a0l + a0h; s1 += a1l + a1h;
        q0 = fmaf(a0l, a0l, q0); q0 = fmaf(a0h, a0h, q0);
        q1 = fmaf(a1l, a1l, q1); q1 = fmaf(a1h, a1h, q1);
    }
    atomicAdd(&ssum[2 * lane], s0);     atomicAdd(&ssum[2 * lane + 1], s1);
    atomicAdd(&ssq[2 * lane], q0);      atomicAdd(&ssq[2 * lane + 1], q1);
    __syncthreads();
    if (tid < 64) {
        atomicAdd(&g_stats[128 + tid], (double)ssum[tid]);
        atomicAdd(&g_stats[192 + tid], (double)ssq[tid]);
    }
    __threadfence();
    __syncthreads();
    if (tid == 0) slast = (atomicAdd(&g_cnt2, 1) == L2_GRID - 1);
    __syncthreads();
    if (slast) {
        bnp_tail(g2, beta2, 64, 128, 128, tid);
        if (tid == 0) g_cnt2 = 0;
    }
}

// ---------------- 5: layer 3 (f32x2) + bnp3 tail ----------------
#define XST3 132
#define L3_GRID ((BB * SS * KK) / 128)
__global__ __launch_bounds__(256) void layer3_kernel(const float* __restrict__ b3,
                                                     const float* __restrict__ g3,
                                                     const float* __restrict__ beta3) {
    __shared__ float xin[64 * XST3];
    __shared__ float ssum[128], ssq[128], smax[8][128];
    __shared__ int slast;
    int tid = threadIdx.x;
    int p0 = blockIdx.x * 128;
    if (tid < 128) { ssum[tid] = 0.f; ssq[tid] = 0.f; }
    for (int i = tid; i < 128 * 64; i += 256) {
        int p = i >> 6, c = i & 63;
        float y = g_y2[(size_t)(p0 + p) * 64 + c];
        xin[c * XST3 + p] = fmaxf(fmaf(g_bn[128 + c], y, g_bn[192 + c]), 0.f);
    }
    __syncthreads();
    int wid = tid >> 5, lane = tid & 31;
    int P = wid * 16;
    float4 bb = ((const float4*)b3)[lane];
    ull acc[4][8];
#pragma unroll
    for (int t = 0; t < 8; t++) {
        acc[0][t] = pk(bb.x, bb.x);
        acc[1][t] = pk(bb.y, bb.y);
        acc[2][t] = pk(bb.z, bb.z);
        acc[3][t] = pk(bb.w, bb.w);
    }
    for (int c = 0; c < 64; c++) {
        const ulonglong2* wr = (const ulonglong2*)(g_w3d + c * 128);
        ulonglong2 wa = wr[2 * lane];
        ulonglong2 wb = wr[2 * lane + 1];
        const float* xr = xin + c * XST3 + P;
#pragma unroll
        for (int t2 = 0; t2 < 4; t2++) {
            ulonglong2 hh = *(const ulonglong2*)(xr + 4 * t2);
            acc[0][2 * t2]     = fma2(hh.x, wa.x, acc[0][2 * t2]);
            acc[1][2 * t2]     = fma2(hh.x, wa.y, acc[1][2 * t2]);
            acc[2][2 * t2]     = fma2(hh.x, wb.x, acc[2][2 * t2]);
            acc[3][2 * t2]     = fma2(hh.x, wb.y, acc[3][2 * t2]);
            acc[0][2 * t2 + 1] = fma2(hh.y, wa.x, acc[0][2 * t2 + 1]);
            acc[1][2 * t2 + 1] = fma2(hh.y, wa.y, acc[1][2 * t2 + 1]);
            acc[2][2 * t2 + 1] = fma2(hh.y, wb.x, acc[2][2 * t2 + 1]);
            acc[3][2 * t2 + 1] = fma2(hh.y, wb.y, acc[3][2 * t2 + 1]);
        }
    }
#pragma unroll
    for (int ch = 0; ch < 4; ch++) {
        float m = -1e30f, s = 0.f, q = 0.f;
#pragma unroll
        for (int t = 0; t < 8; t++) {
            float lo, hi;
            upk(acc[ch][t], lo, hi);
            m = fmaxf(m, fmaxf(lo, hi));
            s += lo + hi;
            q = fmaf(lo, lo, q); q = fmaf(hi, hi, q);
        }
        int o = 4 * lane + ch;
        smax[wid][o] = m;
        atomicAdd(&ssum[o], s);
        atomicAdd(&ssq[o], q);
    }
    __syncthreads();
    {
        int o = tid & 127;
        int g0 = tid >> 7;
#pragma unroll
        for (int gi0 = 0; gi0 < 2; gi0++) {
            int gi = g0 + 2 * gi0;
            float mm = fmaxf(smax[2 * gi][o], smax[2 * gi + 1][o]);
            g_ymax[((size_t)blockIdx.x * 4 + gi) * 128 + o] = mm;
        }
    }
    if (tid < 128) {
        atomicAdd(&g_stats[256 + tid], (double)ssum[tid]);
        atomicAdd(&g_stats[384 + tid], (double)ssq[tid]);
    }
    __threadfence();
    __syncthreads();
    if (tid == 0) slast = (atomicAdd(&g_cnt3, 1) == L3_GRID - 1);
    __syncthreads();
    if (slast) {
        bnp_tail(g3, beta3, 128, 256, 256, tid);
        if (tid == 0) g_cnt3 = 0;
    }
}

// ---------------- 6: finalize new_points = relu(BN3(max-pooled y3)) ----------------
__global__ void finalize_kernel(float* __restrict__ out) {
    int i = blockIdx.x * 256 + threadIdx.x;
    int o = i & 127;
    out[BB * SS * 3 + i] = fmaxf(fmaf(g_bn[256 + o], g_ymax[i], g_bn[384 + o]), 0.f);
}

extern "C" void kernel_launch(void* const* d_in, const int* in_sizes, int n_in,
                              void* d_out, int out_size) {
    const float* xyz   = (const float*)d_in[0];
    const float* pts   = (const float*)d_in[1];
    const float* w1    = (const float*)d_in[2];
    const float* b1    = (const float*)d_in[3];
    const float* g1    = (const float*)d_in[4];
    const float* beta1 = (const float*)d_in[5];
    const float* w2    = (const float*)d_in[6];
    const float* b2    = (const float*)d_in[7];
    const float* g2    = (const float*)d_in[8];
    const float* beta2 = (const float*)d_in[9];
    const float* w3    = (const float*)d_in[10];
    const float* b3    = (const float*)d_in[11];
    const float* g3    = (const float*)d_in[12];
    const float* beta3 = (const float*)d_in[13];
    float* out = (float*)d_out;

    cudaFuncSetAttribute(fps_u_kernel, cudaFuncAttributeMaxDynamicSharedMemorySize,
                         U_SMEM_BYTES);
    fps_u_kernel<<<560, 512, U_SMEM_BYTES>>>(xyz, pts, w1, w2, w3, out);
    ballq_kernel<<<(BB * SS) / 8, 256>>>(xyz, out, w1, b1);
    stats1_kernel<<<STATS1_GRID, 256>>>(g1, beta1);
    layer2_kernel<<<L2_GRID, 256>>>(b2, g2, beta2);
    layer3_kernel<<<L3_GRID, 256>>>(b3, g3, beta3);
    finalize_kernel<<<(BB * SS * 128) / 256, 256>>>(out);
}

// round 11
// speedup vs baseline: 1.6826x; 1.0206x over previous
#include <cuda_runtime.h>
#include <cstdint>

#define BB 16
#define NN 4096
#define SS 1024
#define KK 32
#define C1 67
#define CNT_BN 524288.0

typedef unsigned long long ull;

// ---------------- device scratch (no allocation allowed) ----------------
__device__ __align__(16) float  g_u[BB * NN * 64];              // 16.8 MB
__device__ __align__(16) float  g_v[BB * SS * 64];              // 4.2 MB
__device__            int       g_idx[BB * SS * KK];            // 2 MB
__device__ __align__(16) float  g_y2[(size_t)BB * SS * KK * 64];// 134 MB
__device__ __align__(16) float  g_ymax[BB * SS * 128];          // 8.4 MB
__device__            double    g_stats[512];  // L1: sum@0 sq@64 | L2: 128/192 | L3: 256/384
__device__            float     g_bn[512];     // a1@0 c1@64 | a2@128 c2@192 | a3@256 c3@384
__device__ __align__(16) ull    g_w2d[64 * 64];                 // dup-packed W2^T
__device__ __align__(16) ull    g_w3d[64 * 128];                // dup-packed W3^T
__device__            int       g_cnt1 = 0, g_cnt2 = 0, g_cnt3 = 0;  // last-block tickets

// ---------------- f32x2 helpers ----------------
__device__ __forceinline__ ull fma2(ull a, ull b, ull c) {
    ull d;
    asm("fma.rn.f32x2 %0, %1, %2, %3;" : "=l"(d) : "l"(a), "l"(b), "l"(c));
    return d;
}
__device__ __forceinline__ ull add2(ull a, ull b) {
    ull d;
    asm("add.rn.f32x2 %0, %1, %2;" : "=l"(d) : "l"(a), "l"(b));
    return d;
}
__device__ __forceinline__ ull mul2(ull a, ull b) {
    ull d;
    asm("mul.rn.f32x2 %0, %1, %2;" : "=l"(d) : "l"(a), "l"(b));
    return d;
}
__device__ __forceinline__ ull pk(float a, float b) {
    ull r;
    asm("mov.b64 %0, {%1, %2};" : "=l"(r) : "f"(a), "f"(b));
    return r;
}
__device__ __forceinline__ void upk(ull v, float& a, float& b) {
    asm("mov.b64 {%0, %1}, %2;" : "=f"(a), "=f"(b) : "l"(v));
}

// ---------------- BN param fold (runs in last block of producer kernel) ----------------
__device__ __forceinline__ void bnp_tail(const float* gamma, const float* beta,
                                         int nch, int stats_off, int bn_off, int tid) {
    if (tid < nch) {
        volatile double* vs = g_stats;               // read-through to L2 (atomics' home)
        double mean = vs[stats_off + tid] / CNT_BN;
        double var = vs[stats_off + nch + tid] / CNT_BN - mean * mean;
        double a = (double)gamma[tid] / sqrt(var + 1e-5);
        g_bn[bn_off + tid] = (float)a;
        g_bn[bn_off + nch + tid] = (float)((double)beta[tid] - mean * a);
    }
}

// ================= 1: combined FPS + u + prep  =================
// grid 560 x 512 threads, dynamic smem 116 KB (forces 1 block/SM -> FPS exclusivity)
#define XST1 132
#define U_SMEM_BYTES (116 * 1024)                    // > 228KB/2 -> exactly 1 block/SM

__global__ __launch_bounds__(512) void fps_u_kernel(
        const float* __restrict__ xyz, const float* __restrict__ pts,
        const float* __restrict__ w1, const float* __restrict__ w2,
        const float* __restrict__ w3, float* __restrict__ out_xyz) {
    extern __shared__ char dyns[];
    int bid = blockIdx.x;
    int tid = threadIdx.x;
    int lane = tid & 31, wid = tid >> 5;

    if (bid < BB) {
        // ---------------- FPS (bit-exact, single barrier/iter) ----------------
        unsigned* smaxb = (unsigned*)dyns;            // [2][16]
        int* sidxv = (int*)(dyns + 128);              // [2][16]
        int b = bid;
        const float* xb = xyz + (size_t)b * NN * 3;
        ull px[4], py[4], pz[4];
        float dist[8];
        int base = tid * 8;
#pragma unroll
        for (int t = 0; t < 4; t++) {
            int j0 = base + 2 * t, j1 = j0 + 1;
            px[t] = pk(xb[j0 * 3 + 0], xb[j1 * 3 + 0]);
            py[t] = pk(xb[j0 * 3 + 1], xb[j1 * 3 + 1]);
            pz[t] = pk(xb[j0 * 3 + 2], xb[j1 * 3 + 2]);
            dist[2 * t] = 1e10f;
            dist[2 * t + 1] = 1e10f;
        }
        float cx = xb[0], cy = xb[1], cz = xb[2];
        if (tid == 0) {
            float* op = out_xyz + (size_t)b * SS * 3;
            op[0] = cx; op[1] = cy; op[2] = cz;
        }
        for (int i = 0; i < SS - 1; i++) {
            ull ncx = pk(-cx, -cx);
            ull ncy = pk(-cy, -cy);
            ull ncz = pk(-cz, -cz);
            float lmax = -1.0f; int lidx = 0;
#pragma unroll
            for (int t = 0; t < 4; t++) {
                ull dx = add2(px[t], ncx);            // add(x,-c) == sub(x,c) bitwise
                ull dy = add2(py[t], ncy);
                ull dz = add2(pz[t], ncz);
                ull s = add2(add2(mul2(dx, dx), mul2(dy, dy)), mul2(dz, dz));
                float slo, shi;
                upk(s, slo, shi);
                float d0 = fminf(dist[2 * t], slo);
                float d1 = fminf(dist[2 * t + 1], shi);
                dist[2 * t] = d0;
                dist[2 * t + 1] = d1;
                if (d0 > lmax) { lmax = d0; lidx = base + 2 * t; }
                if (d1 > lmax) { lmax = d1; lidx = base + 2 * t + 1; }
            }
            unsigned mb = __float_as_uint(lmax);
            unsigned wm = __reduce_max_sync(0xffffffffu, mb);
            int cand = (mb == wm) ? lidx : 0x7fffffff;
            int wi = __reduce_min_sync(0xffffffffu, cand);
            int par = i & 1;
            if (lane == 0) { smaxb[par * 16 + wid] = wm; sidxv[par * 16 + wid] = wi; }
            __syncthreads();
            unsigned vb = (lane < 16) ? smaxb[par * 16 + lane] : 0u;
            int vi = (lane < 16) ? sidxv[par * 16 + lane] : 0x7fffffff;
            unsigned m2 = __reduce_max_sync(0xffffffffu, vb);
            int c2 = (vb == m2) ? vi : 0x7fffffff;
            int far = __reduce_min_sync(0xffffffffu, c2);
            const float* cp = xb + (size_t)far * 3;
            cx = cp[0]; cy = cp[1]; cz = cp[2];
            if (tid == 0) {
                float* op = out_xyz + ((size_t)b * SS + i + 1) * 3;
                op[0] = cx; op[1] = cy; op[2] = cz;
            }
        }
    } else if (bid < 528) {
        // ---------------- u: 128 points/block, 512 threads ----------------
        ull* wsm = (ull*)dyns;                        // [C1][64] dup-packed
        float* xin = (float*)(dyns + C1 * 64 * 8);    // [C1][XST1] channel-major
        int p0 = (bid - 16) * 128;
        for (int i = tid; i < C1 * 64; i += 512) {
            int c = i >> 6, o = i & 63;
            float w = w1[o * C1 + c];
            wsm[i] = pk(w, w);
        }
        for (int i = tid; i < 68 * 128; i += 512) {
            int p = i / 68, c = i % 68;
            if (c < C1) {
                float v = (c < 3) ? xyz[(size_t)(p0 + p) * 3 + c]
                                  : pts[(size_t)(p0 + p) * 64 + (c - 3)];
                xin[c * XST1 + p] = v;
            }
        }
        __syncthreads();
        int P = wid * 8;                               // 8 positions per warp
        ull a0[4], a1[4];
#pragma unroll
        for (int t = 0; t < 4; t++) { a0[t] = 0ull; a1[t] = 0ull; }
        for (int c = 0; c < C1; c++) {
            ulonglong2 wv = ((const ulonglong2*)(wsm + c * 64))[lane];
            const float* xr = xin + c * XST1 + P;
            ulonglong2 h0 = *(const ulonglong2*)(xr);
            ulonglong2 h1 = *(const ulonglong2*)(xr + 4);
            a0[0] = fma2(h0.x, wv.x, a0[0]); a1[0] = fma2(h0.x, wv.y, a1[0]);
            a0[1] = fma2(h0.y, wv.x, a0[1]); a1[1] = fma2(h0.y, wv.y, a1[1]);
            a0[2] = fma2(h1.x, wv.x, a0[2]); a1[2] = fma2(h1.x, wv.y, a1[2]);
            a0[3] = fma2(h1.y, wv.x, a0[3]); a1[3] = fma2(h1.y, wv.y, a1[3]);
        }
#pragma unroll
        for (int t = 0; t < 4; t++) {
            float a0l, a0h, a1l, a1h;
            upk(a0[t], a0l, a0h);
            upk(a1[t], a1l, a1h);
            int p = p0 + P + 2 * t;
            float2 s0; s0.x = a0l; s0.y = a1l;
            float2 s1; s1.x = a0h; s1.y = a1h;
            ((float2*)(g_u + (size_t)p * 64))[lane] = s0;
            ((float2*)(g_u + (size_t)(p + 1) * 64))[lane] = s1;
        }
    } else {
        // ---------------- prep ----------------
        int i = (bid - 528) * 512 + tid;               // 0..16383
        if (i < 512) g_stats[i] = 0.0;
        if (i < 64 * 64) {
            int c = i >> 6, o = i & 63;
            float w = w2[o * 64 + c];
            g_w2d[i] = pk(w, w);
        }
        if (i < 64 * 128) {
            int c = i >> 7, o = i & 127;
            float w = w3[o * 64 + c];
            g_w3d[i] = pk(w, w);
        }
    }
}

// ---------------- 2: ball query + fused v + fused BN1 stats + bnp1 tail ----------------
#define BQ_GRID ((BB * SS) / 8)
__global__ __launch_bounds__(256) void ballq_stats_kernel(
        const float* __restrict__ xyz, const float* __restrict__ newxyz,
        const float* __restrict__ w1, const float* __restrict__ b1,
        const float* __restrict__ g1, const float* __restrict__ beta1) {
    __shared__ float red[2][8][64];
    __shared__ int slast;
    int wid = threadIdx.x >> 5;
    int gw = blockIdx.x * 8 + wid;
    int lane = threadIdx.x & 31;
    int b = gw >> 10;
    const float* cp = newxyz + (size_t)gw * 3;
    float sx = cp[0], sy = cp[1], sz = cp[2];
    float sn = __fadd_rn(__fadd_rn(__fmul_rn(sx, sx), __fmul_rn(sy, sy)), __fmul_rn(sz, sz));
    const float* xb = xyz + (size_t)b * NN * 3;
    const float R2 = (float)(0.2 * 0.2);
    int cnt = 0, first = -1;
    int* op = g_idx + (size_t)gw * KK;
    for (int basep = 0; basep < NN && cnt < KK; basep += 32) {
        int n = basep + lane;
        float nx = xb[n * 3 + 0], ny = xb[n * 3 + 1], nz = xb[n * 3 + 2];
        float dn = __fadd_rn(__fadd_rn(__fmul_rn(nx, nx), __fmul_rn(ny, ny)), __fmul_rn(nz, nz));
        float dt = __fadd_rn(__fadd_rn(__fmul_rn(sx, nx), __fmul_rn(sy, ny)), __fmul_rn(sz, nz));
        float sqr = __fadd_rn(__fadd_rn(__fmul_rn(-2.0f, dt), sn), dn);
        bool ok = !(sqr > R2);
        unsigned bal = __ballot_sync(0xffffffffu, ok);
        if (first < 0 && bal) first = basep + (__ffs(bal) - 1);
        int pos = cnt + __popc(bal & ((1u << lane) - 1u));
        if (ok && pos < KK) op[pos] = n;
        cnt += __popc(bal);
    }
    for (int s = cnt + lane; s < KK; s += 32) op[s] = first;
    // fused v: 2 output channels per lane
    int o = 2 * lane;
    const float* wr0 = w1 + (size_t)o * C1;
    const float* wr1 = wr0 + C1;
    float2 vv;
    vv.x = b1[o]     - (wr0[0] * sx + wr0[1] * sy + wr0[2] * sz);
    vv.y = b1[o + 1] - (wr1[0] * sx + wr1[1] * sy + wr1[2] * sz);
    ((float2*)(g_v + (size_t)gw * 64))[lane] = vv;
    // fused BN1 stats for this group: indices via shfl (no g_idx re-gather pass)
    __syncwarp();
    int idxv = op[lane];                              // warp's 32 indices, one per lane
    const float* ub = g_u + (((size_t)b) << 12) * 64;
    float s0 = 0.f, s1 = 0.f, q0 = 0.f, q1 = 0.f;
#pragma unroll 4
    for (int k = 0; k < KK; k++) {
        int pt = __shfl_sync(0xffffffffu, idxv, k);
        float2 u = ((const float2*)(ub + (size_t)pt * 64))[lane];
        float y0 = u.x + vv.x, y1 = u.y + vv.y;
        s0 += y0; s1 += y1;
        q0 = fmaf(y0, y0, q0); q1 = fmaf(y1, y1, q1);
    }
    red[0][wid][2 * lane] = s0; red[0][wid][2 * lane + 1] = s1;
    red[1][wid][2 * lane] = q0; red[1][wid][2 * lane + 1] = q1;
    __syncthreads();
    int tid = threadIdx.x;
    if (tid < 64) {
        double ds = 0.0, dq = 0.0;
#pragma unroll
        for (int r = 0; r < 8; r++) { ds += red[0][r][tid]; dq += red[1][r][tid]; }
        atomicAdd(&g_stats[0 + tid], ds);
        atomicAdd(&g_stats[64 + tid], dq);
    }
    __threadfence();
    __syncthreads();
    if (tid == 0) slast = (atomicAdd(&g_cnt1, 1) == BQ_GRID - 1);
    __syncthreads();
    if (slast) {
        bnp_tail(g1, beta1, 64, 0, 0, tid);
        if (tid == 0) g_cnt1 = 0;                    // reset for graph replay
    }
}

// ---------------- 3: layer 2 (f32x2) + bnp2 tail  (4 blocks/SM forced) ----------------
#define XST2 132
#define L2_GRID ((BB * SS * KK) / 128)
__global__ __launch_bounds__(256, 4) void layer2_kernel(const float* __restrict__ b2,
                                                        const float* __restrict__ g2,
                                                        const float* __restrict__ beta2) {
    __shared__ float xin[64 * XST2];
    __shared__ float ssum[64], ssq[64];
    __shared__ int slast;
    int tid = threadIdx.x;
    int p0 = blockIdx.x * 128;
    if (tid < 64) { ssum[tid] = 0.f; ssq[tid] = 0.f; }
    for (int i = tid; i < 128 * 64; i += 256) {
        int p = i >> 6, c = i & 63;
        int inst = p0 + p;
        int g = inst >> 5;
        int b = g >> 10;
        int pt = g_idx[inst];
        float y = g_u[(((size_t)b << 12) + pt) * 64 + c] + g_v[(size_t)g * 64 + c];
        xin[c * XST2 + p] = fmaxf(fmaf(g_bn[c], y, g_bn[64 + c]), 0.f);
    }
    __syncthreads();
    int wid = tid >> 5, lane = tid & 31;
    int P = wid * 16;
    float2 bb = ((const float2*)b2)[lane];
    ull bi0 = pk(bb.x, bb.x), bi1 = pk(bb.y, bb.y);
    ull acc0[8], acc1[8];
#pragma unroll
    for (int t = 0; t < 8; t++) { acc0[t] = bi0; acc1[t] = bi1; }
    for (int c = 0; c < 64; c++) {
        ulonglong2 wv = ((const ulonglong2*)(g_w2d + c * 64))[lane];
        const float* xr = xin + c * XST2 + P;
#pragma unroll
        for (int t2 = 0; t2 < 4; t2++) {
            ulonglong2 hh = *(const ulonglong2*)(xr + 4 * t2);
            acc0[2 * t2]     = fma2(hh.x, wv.x, acc0[2 * t2]);
            acc1[2 * t2]     = fma2(hh.x, wv.y, acc1[2 * t2]);
            acc0[2 * t2 + 1] = fma2(hh.y, wv.x, acc0[2 * t2 + 1]);
            acc1[2 * t2 + 1] = fma2(hh.y, wv.y, acc1[2 * t2 + 1]);
        }
    }
    float s0 = 0.f, s1 = 0.f, q0 = 0.f, q1 = 0.f;
#pragma unroll
    for (int t = 0; t < 8; t++) {
        float a0l, a0h, a1l, a1h;
        upk(acc0[t], a0l, a0h);
        upk(acc1[t], a1l, a1h);
        int p = p0 + P + 2 * t;
        float2 s0v; s0v.x = a0l; s0v.y = a1l;
        float2 s1v; s1v.x = a0h; s1v.y = a1h;
        ((float2*)(g_y2 + (size_t)p * 64))[lane] = s0v;
        ((float2*)(g_y2 + (size_t)(p + 1) * 64))[lane] = s1v;
        s0 += a0l + a0h; s1 += a1l + a1h;
        q0 = fmaf(a0l, a0l, q0); q0 = fmaf(a0h, a0h, q0);
        q1 = fmaf(a1l, a1l, q1); q1 = fmaf(a1h, a1h, q1);
    }
    atomicAdd(&ssum[2 * lane], s0);     atomicAdd(&ssum[2 * lane + 1], s1);
    atomicAdd(&ssq[2 * lane], q0);      atomicAdd(&ssq[2 * lane + 1], q1);
    __syncthreads();
    if (tid < 64) {
        atomicAdd(&g_stats[128 + tid], (double)ssum[tid]);
        atomicAdd(&g_stats[192 + tid], (double)ssq[tid]);
    }
    __threadfence();
    __syncthreads();
    if (tid == 0) slast = (atomicAdd(&g_cnt2, 1) == L2_GRID - 1);
    __syncthreads();
    if (slast) {
        bnp_tail(g2, beta2, 64, 128, 128, tid);
        if (tid == 0) g_cnt2 = 0;
    }
}

// ---------------- 4: layer 3 (f32x2) + bnp3 tail ----------------
#define XST3 132
#define L3_GRID ((BB * SS * KK) / 128)
__global__ __launch_bounds__(256) void layer3_kernel(const float* __restrict__ b3,
                                                     const float* __restrict__ g3,
                                                     const float* __restrict__ beta3) {
    __shared__ float xin[64 * XST3];
    __shared__ float ssum[128], ssq[128], smax[8][128];
    __shared__ int slast;
    int tid = threadIdx.x;
    int p0 = blockIdx.x * 128;
    if (tid < 128) { ssum[tid] = 0.f; ssq[tid] = 0.f; }
    for (int i = tid; i < 128 * 64; i += 256) {
        int p = i >> 6, c = i & 63;
        float y = g_y2[(size_t)(p0 + p) * 64 + c];
        xin[c * XST3 + p] = fmaxf(fmaf(g_bn[128 + c], y, g_bn[192 + c]), 0.f);
    }
    __syncthreads();
    int wid = tid >> 5, lane = tid & 31;
    int P = wid * 16;
    float4 bb = ((const float4*)b3)[lane];
    ull acc[4][8];
#pragma unroll
    for (int t = 0; t < 8; t++) {
        acc[0][t] = pk(bb.x, bb.x);
        acc[1][t] = pk(bb.y, bb.y);
        acc[2][t] = pk(bb.z, bb.z);
        acc[3][t] = pk(bb.w, bb.w);
    }
    for (int c = 0; c < 64; c++) {
        const ulonglong2* wr = (const ulonglong2*)(g_w3d + c * 128);
        ulonglong2 wa = wr[2 * lane];
        ulonglong2 wb = wr[2 * lane + 1];
        const float* xr = xin + c * XST3 + P;
#pragma unroll
        for (int t2 = 0; t2 < 4; t2++) {
            ulonglong2 hh = *(const ulonglong2*)(xr + 4 * t2);
            acc[0][2 * t2]     = fma2(hh.x, wa.x, acc[0][2 * t2]);
            acc[1][2 * t2]     = fma2(hh.x, wa.y, acc[1][2 * t2]);
            acc[2][2 * t2]     = fma2(hh.x, wb.x, acc[2][2 * t2]);
            acc[3][2 * t2]     = fma2(hh.x, wb.y, acc[3][2 * t2]);
            acc[0][2 * t2 + 1] = fma2(hh.y, wa.x, acc[0][2 * t2 + 1]);
            acc[1][2 * t2 + 1] = fma2(hh.y, wa.y, acc[1][2 * t2 + 1]);
            acc[2][2 * t2 + 1] = fma2(hh.y, wb.x, acc[2][2 * t2 + 1]);
            acc[3][2 * t2 + 1] = fma2(hh.y, wb.y, acc[3][2 * t2 + 1]);
        }
    }
#pragma unroll
    for (int ch = 0; ch < 4; ch++) {
        float m = -1e30f, s = 0.f, q = 0.f;
#pragma unroll
        for (int t = 0; t < 8; t++) {
            float lo, hi;
            upk(acc[ch][t], lo, hi);
            m = fmaxf(m, fmaxf(lo, hi));
            s += lo + hi;
            q = fmaf(lo, lo, q); q = fmaf(hi, hi, q);
        }
        int o = 4 * lane + ch;
        smax[wid][o] = m;
        atomicAdd(&ssum[o], s);
        atomicAdd(&ssq[o], q);
    }
    __syncthreads();
    {
        int o = tid & 127;
        int g0 = tid >> 7;
#pragma unroll
        for (int gi0 = 0; gi0 < 2; gi0++) {
            int gi = g0 + 2 * gi0;
            float mm = fmaxf(smax[2 * gi][o], smax[2 * gi + 1][o]);
            g_ymax[((size_t)blockIdx.x * 4 + gi) * 128 + o] = mm;
        }
    }
    if (tid < 128) {
        atomicAdd(&g_stats[256 + tid], (double)ssum[tid]);
        atomicAdd(&g_stats[384 + tid], (double)ssq[tid]);
    }
    __threadfence();
    __syncthreads();
    if (tid == 0) slast = (atomicAdd(&g_cnt3, 1) == L3_GRID - 1);
    __syncthreads();
    if (slast) {
        bnp_tail(g3, beta3, 128, 256, 256, tid);
        if (tid == 0) g_cnt3 = 0;
    }
}

// ---------------- 5: finalize new_points = relu(BN3(max-pooled y3)) ----------------
__global__ void finalize_kernel(float* __restrict__ out) {
    int i = blockIdx.x * 256 + threadIdx.x;
    int o = i & 127;
    out[BB * SS * 3 + i] = fmaxf(fmaf(g_bn[256 + o], g_ymax[i], g_bn[384 + o]), 0.f);
}

extern "C" void kernel_launch(void* const* d_in, const int* in_sizes, int n_in,
                              void* d_out, int out_size) {
    const float* xyz   = (const float*)d_in[0];
    const float* pts   = (const float*)d_in[1];
    const float* w1    = (const float*)d_in[2];
    const float* b1    = (const float*)d_in[3];
    const float* g1    = (const float*)d_in[4];
    const float* beta1 = (const float*)d_in[5];
    const float* w2    = (const float*)d_in[6];
    const float* b2    = (const float*)d_in[7];
    const float* g2    = (const float*)d_in[8];
    const float* beta2 = (const float*)d_in[9];
    const float* w3    = (const float*)d_in[10];
    const float* b3    = (const float*)d_in[11];
    const float* g3    = (const float*)d_in[12];
    const float* beta3 = (const float*)d_in[13];
    float* out = (float*)d_out;

    cudaFuncSetAttribute(fps_u_kernel, cudaFuncAttributeMaxDynamicSharedMemorySize,
                         U_SMEM_BYTES);
    fps_u_kernel<<<560, 512, U_SMEM_BYTES>>>(xyz, pts, w1, w2, w3, out);
    ballq_stats_kernel<<<BQ_GRID, 256>>>(xyz, out, w1, b1, g1, beta1);
    layer2_kernel<<<L2_GRID, 256>>>(b2, g2, beta2);
    layer3_kernel<<<L3_GRID, 256>>>(b3, g3, beta3);
    finalize_kernel<<<(BB * SS * 128) / 256, 256>>>(out);
}

// round 12
// speedup vs baseline: 1.7809x; 1.0584x over previous
#include <cuda_runtime.h>
#include <cstdint>

#define BB 16
#define NN 4096
#define SS 1024
#define KK 32
#define C1 67
#define CNT_BN 524288.0

typedef unsigned long long ull;

// ---------------- device scratch (no allocation allowed) ----------------
__device__ __align__(16) float  g_u[BB * NN * 64];              // 16.8 MB
__device__ __align__(16) float  g_v[BB * SS * 64];              // 4.2 MB
__device__            int       g_idx[BB * SS * KK];            // 2 MB
__device__ __align__(16) float  g_y2[(size_t)BB * SS * KK * 64];// 134 MB
__device__ __align__(16) float  g_ymax[BB * SS * 128];          // 8.4 MB
__device__            double    g_stats[512];  // L1: sum@0 sq@64 | L2: 128/192 | L3: 256/384
__device__            float     g_bn[512];     // a1@0 c1@64 | a2@128 c2@192 | a3@256 c3@384
__device__ __align__(16) ull    g_w2d[64 * 64];                 // dup-packed W2^T
__device__ __align__(16) ull    g_w3d[64 * 128];                // dup-packed W3^T
__device__            int       g_cnt1 = 0, g_cnt2 = 0, g_cnt3 = 0;  // last-block tickets

// ---------------- f32x2 helpers ----------------
__device__ __forceinline__ ull fma2(ull a, ull b, ull c) {
    ull d;
    asm("fma.rn.f32x2 %0, %1, %2, %3;" : "=l"(d) : "l"(a), "l"(b), "l"(c));
    return d;
}
__device__ __forceinline__ ull add2(ull a, ull b) {
    ull d;
    asm("add.rn.f32x2 %0, %1, %2;" : "=l"(d) : "l"(a), "l"(b));
    return d;
}
__device__ __forceinline__ ull mul2(ull a, ull b) {
    ull d;
    asm("mul.rn.f32x2 %0, %1, %2;" : "=l"(d) : "l"(a), "l"(b));
    return d;
}
__device__ __forceinline__ ull pk(float a, float b) {
    ull r;
    asm("mov.b64 %0, {%1, %2};" : "=l"(r) : "f"(a), "f"(b));
    return r;
}
__device__ __forceinline__ void upk(ull v, float& a, float& b) {
    asm("mov.b64 {%0, %1}, %2;" : "=f"(a), "=f"(b) : "l"(v));
}

// ---------------- BN param fold (runs in last block of producer kernel) ----------------
__device__ __forceinline__ void bnp_tail(const float* gamma, const float* beta,
                                         int nch, int stats_off, int bn_off, int tid) {
    if (tid < nch) {
        volatile double* vs = g_stats;               // read-through to L2 (atomics' home)
        double mean = vs[stats_off + tid] / CNT_BN;
        double var = vs[stats_off + nch + tid] / CNT_BN - mean * mean;
        double a = (double)gamma[tid] / sqrt(var + 1e-5);
        g_bn[bn_off + tid] = (float)a;
        g_bn[bn_off + nch + tid] = (float)((double)beta[tid] - mean * a);
    }
}

// ================= 1: combined FPS + u + prep  =================
// grid 560 x 512 threads, dynamic smem 116 KB (forces 1 block/SM -> FPS exclusivity)
#define XST1 132
#define U_SMEM_BYTES (116 * 1024)                    // > 228KB/2 -> exactly 1 block/SM

__global__ __launch_bounds__(512) void fps_u_kernel(
        const float* __restrict__ xyz, const float* __restrict__ pts,
        const float* __restrict__ w1, const float* __restrict__ w2,
        const float* __restrict__ w3, float* __restrict__ out_xyz) {
    extern __shared__ char dyns[];
    int bid = blockIdx.x;
    int tid = threadIdx.x;
    int lane = tid & 31, wid = tid >> 5;

    if (bid < BB) {
        // ---------------- FPS (bit-exact, single barrier/iter) ----------------
        unsigned* smaxb = (unsigned*)dyns;            // [2][16]
        int* sidxv = (int*)(dyns + 128);              // [2][16]
        int b = bid;
        const float* xb = xyz + (size_t)b * NN * 3;
        ull px[4], py[4], pz[4];
        float dist[8];
        int base = tid * 8;
#pragma unroll
        for (int t = 0; t < 4; t++) {
            int j0 = base + 2 * t, j1 = j0 + 1;
            px[t] = pk(xb[j0 * 3 + 0], xb[j1 * 3 + 0]);
            py[t] = pk(xb[j0 * 3 + 1], xb[j1 * 3 + 1]);
            pz[t] = pk(xb[j0 * 3 + 2], xb[j1 * 3 + 2]);
            dist[2 * t] = 1e10f;
            dist[2 * t + 1] = 1e10f;
        }
        float cx = xb[0], cy = xb[1], cz = xb[2];
        if (tid == 0) {
            float* op = out_xyz + (size_t)b * SS * 3;
            op[0] = cx; op[1] = cy; op[2] = cz;
        }
        for (int i = 0; i < SS - 1; i++) {
            ull ncx = pk(-cx, -cx);
            ull ncy = pk(-cy, -cy);
            ull ncz = pk(-cz, -cz);
            float lmax = -1.0f; int lidx = 0;
#pragma unroll
            for (int t = 0; t < 4; t++) {
                ull dx = add2(px[t], ncx);            // add(x,-c) == sub(x,c) bitwise
                ull dy = add2(py[t], ncy);
                ull dz = add2(pz[t], ncz);
                ull s = add2(add2(mul2(dx, dx), mul2(dy, dy)), mul2(dz, dz));
                float slo, shi;
                upk(s, slo, shi);
                float d0 = fminf(dist[2 * t], slo);
                float d1 = fminf(dist[2 * t + 1], shi);
                dist[2 * t] = d0;
                dist[2 * t + 1] = d1;
                if (d0 > lmax) { lmax = d0; lidx = base + 2 * t; }
                if (d1 > lmax) { lmax = d1; lidx = base + 2 * t + 1; }
            }
            unsigned mb = __float_as_uint(lmax);
            unsigned wm = __reduce_max_sync(0xffffffffu, mb);
            int cand = (mb == wm) ? lidx : 0x7fffffff;
            int wi = __reduce_min_sync(0xffffffffu, cand);
            int par = i & 1;
            if (lane == 0) { smaxb[par * 16 + wid] = wm; sidxv[par * 16 + wid] = wi; }
            __syncthreads();
            unsigned vb = (lane < 16) ? smaxb[par * 16 + lane] : 0u;
            int vi = (lane < 16) ? sidxv[par * 16 + lane] : 0x7fffffff;
            unsigned m2 = __reduce_max_sync(0xffffffffu, vb);
            int c2 = (vb == m2) ? vi : 0x7fffffff;
            int far = __reduce_min_sync(0xffffffffu, c2);
            const float* cp = xb + (size_t)far * 3;
            cx = cp[0]; cy = cp[1]; cz = cp[2];
            if (tid == 0) {
                float* op = out_xyz + ((size_t)b * SS + i + 1) * 3;
                op[0] = cx; op[1] = cy; op[2] = cz;
            }
        }
    } else if (bid < 528) {
        // ---------------- u: 128 points/block, 512 threads ----------------
        ull* wsm = (ull*)dyns;                        // [C1][64] dup-packed
        float* xin = (float*)(dyns + C1 * 64 * 8);    // [C1][XST1] channel-major
        int p0 = (bid - 16) * 128;
        for (int i = tid; i < C1 * 64; i += 512) {
            int c = i >> 6, o = i & 63;
            float w = w1[o * C1 + c];
            wsm[i] = pk(w, w);
        }
        for (int i = tid; i < 68 * 128; i += 512) {
            int p = i / 68, c = i % 68;
            if (c < C1) {
                float v = (c < 3) ? xyz[(size_t)(p0 + p) * 3 + c]
                                  : pts[(size_t)(p0 + p) * 64 + (c - 3)];
                xin[c * XST1 + p] = v;
            }
        }
        __syncthreads();
        int P = wid * 8;                               // 8 positions per warp
        ull a0[4], a1[4];
#pragma unroll
        for (int t = 0; t < 4; t++) { a0[t] = 0ull; a1[t] = 0ull; }
        for (int c = 0; c < C1; c++) {
            ulonglong2 wv = ((const ulonglong2*)(wsm + c * 64))[lane];
            const float* xr = xin + c * XST1 + P;
            ulonglong2 h0 = *(const ulonglong2*)(xr);
            ulonglong2 h1 = *(const ulonglong2*)(xr + 4);
            a0[0] = fma2(h0.x, wv.x, a0[0]); a1[0] = fma2(h0.x, wv.y, a1[0]);
            a0[1] = fma2(h0.y, wv.x, a0[1]); a1[1] = fma2(h0.y, wv.y, a1[1]);
            a0[2] = fma2(h1.x, wv.x, a0[2]); a1[2] = fma2(h1.x, wv.y, a1[2]);
            a0[3] = fma2(h1.y, wv.x, a0[3]); a1[3] = fma2(h1.y, wv.y, a1[3]);
        }
#pragma unroll
        for (int t = 0; t < 4; t++) {
            float a0l, a0h, a1l, a1h;
            upk(a0[t], a0l, a0h);
            upk(a1[t], a1l, a1h);
            int p = p0 + P + 2 * t;
            float2 s0; s0.x = a0l; s0.y = a1l;
            float2 s1; s1.x = a0h; s1.y = a1h;
            ((float2*)(g_u + (size_t)p * 64))[lane] = s0;
            ((float2*)(g_u + (size_t)(p + 1) * 64))[lane] = s1;
        }
    } else {
        // ---------------- prep ----------------
        int i = (bid - 528) * 512 + tid;               // 0..16383
        if (i < 512) g_stats[i] = 0.0;
        if (i < 64 * 64) {
            int c = i >> 6, o = i & 63;
            float w = w2[o * 64 + c];
            g_w2d[i] = pk(w, w);
        }
        if (i < 64 * 128) {
            int c = i >> 7, o = i & 127;
            float w = w3[o * 64 + c];
            g_w3d[i] = pk(w, w);
        }
    }
}

// ---------------- 2: ball query + fused v + fused BN1 stats + bnp1 tail ----------------
#define BQ_GRID ((BB * SS) / 8)
__global__ __launch_bounds__(256) void ballq_stats_kernel(
        const float* __restrict__ xyz, const float* __restrict__ newxyz,
        const float* __restrict__ w1, const float* __restrict__ b1,
        const float* __restrict__ g1, const float* __restrict__ beta1) {
    __shared__ float red[2][8][64];
    __shared__ int slast;
    int wid = threadIdx.x >> 5;
    int gw = blockIdx.x * 8 + wid;
    int lane = threadIdx.x & 31;
    int b = gw >> 10;
    const float* cp = newxyz + (size_t)gw * 3;
    float sx = cp[0], sy = cp[1], sz = cp[2];
    float sn = __fadd_rn(__fadd_rn(__fmul_rn(sx, sx), __fmul_rn(sy, sy)), __fmul_rn(sz, sz));
    const float* xb = xyz + (size_t)b * NN * 3;
    const float R2 = (float)(0.2 * 0.2);
    int cnt = 0, first = -1;
    int* op = g_idx + (size_t)gw * KK;
    for (int basep = 0; basep < NN && cnt < KK; basep += 32) {
        int n = basep + lane;
        float nx = xb[n * 3 + 0], ny = xb[n * 3 + 1], nz = xb[n * 3 + 2];
        float dn = __fadd_rn(__fadd_rn(__fmul_rn(nx, nx), __fmul_rn(ny, ny)), __fmul_rn(nz, nz));
        float dt = __fadd_rn(__fadd_rn(__fmul_rn(sx, nx), __fmul_rn(sy, ny)), __fmul_rn(sz, nz));
        float sqr = __fadd_rn(__fadd_rn(__fmul_rn(-2.0f, dt), sn), dn);
        bool ok = !(sqr > R2);
        unsigned bal = __ballot_sync(0xffffffffu, ok);
        if (first < 0 && bal) first = basep + (__ffs(bal) - 1);
        int pos = cnt + __popc(bal & ((1u << lane) - 1u));
        if (ok && pos < KK) op[pos] = n;
        cnt += __popc(bal);
    }
    for (int s = cnt + lane; s < KK; s += 32) op[s] = first;
    // fused v: 2 output channels per lane
    int o = 2 * lane;
    const float* wr0 = w1 + (size_t)o * C1;
    const float* wr1 = wr0 + C1;
    float2 vv;
    vv.x = b1[o]     - (wr0[0] * sx + wr0[1] * sy + wr0[2] * sz);
    vv.y = b1[o + 1] - (wr1[0] * sx + wr1[1] * sy + wr1[2] * sz);
    ((float2*)(g_v + (size_t)gw * 64))[lane] = vv;
    // fused BN1 stats for this group: indices via shfl (no g_idx re-gather pass)
    __syncwarp();
    int idxv = op[lane];                              // warp's 32 indices, one per lane
    const float* ub = g_u + (((size_t)b) << 12) * 64;
    float s0 = 0.f, s1 = 0.f, q0 = 0.f, q1 = 0.f;
#pragma unroll 4
    for (int k = 0; k < KK; k++) {
        int pt = __shfl_sync(0xffffffffu, idxv, k);
        float2 u = ((const float2*)(ub + (size_t)pt * 64))[lane];
        float y0 = u.x + vv.x, y1 = u.y + vv.y;
        s0 += y0; s1 += y1;
        q0 = fmaf(y0, y0, q0); q1 = fmaf(y1, y1, q1);
    }
    red[0][wid][2 * lane] = s0; red[0][wid][2 * lane + 1] = s1;
    red[1][wid][2 * lane] = q0; red[1][wid][2 * lane + 1] = q1;
    __syncthreads();
    int tid = threadIdx.x;
    if (tid < 64) {
        double ds = 0.0, dq = 0.0;
#pragma unroll
        for (int r = 0; r < 8; r++) { ds += red[0][r][tid]; dq += red[1][r][tid]; }
        atomicAdd(&g_stats[0 + tid], ds);
        atomicAdd(&g_stats[64 + tid], dq);
    }
    __threadfence();
    __syncthreads();
    if (tid == 0) slast = (atomicAdd(&g_cnt1, 1) == BQ_GRID - 1);
    __syncthreads();
    if (slast) {
        bnp_tail(g1, beta1, 64, 0, 0, tid);
        if (tid == 0) g_cnt1 = 0;                    // reset for graph replay
    }
}

// ---------------- 3: layer 2 (f32x2) + bnp2 tail  (4 blocks/SM forced) ----------------
#define XST2 132
#define L2_GRID ((BB * SS * KK) / 128)
__global__ __launch_bounds__(256, 4) void layer2_kernel(const float* __restrict__ b2,
                                                        const float* __restrict__ g2,
                                                        const float* __restrict__ beta2) {
    __shared__ float xin[64 * XST2];
    __shared__ float ssum[64], ssq[64];
    __shared__ int slast;
    int tid = threadIdx.x;
    int p0 = blockIdx.x * 128;
    if (tid < 64) { ssum[tid] = 0.f; ssq[tid] = 0.f; }
    for (int i = tid; i < 128 * 64; i += 256) {
        int p = i >> 6, c = i & 63;
        int inst = p0 + p;
        int g = inst >> 5;
        int b = g >> 10;
        int pt = g_idx[inst];
        float y = g_u[(((size_t)b << 12) + pt) * 64 + c] + g_v[(size_t)g * 64 + c];
        xin[c * XST2 + p] = fmaxf(fmaf(g_bn[c], y, g_bn[64 + c]), 0.f);
    }
    __syncthreads();
    int wid = tid >> 5, lane = tid & 31;
    int P = wid * 16;
    float2 bb = ((const float2*)b2)[lane];
    ull bi0 = pk(bb.x, bb.x), bi1 = pk(bb.y, bb.y);
    ull acc0[8], acc1[8];
#pragma unroll
    for (int t = 0; t < 8; t++) { acc0[t] = bi0; acc1[t] = bi1; }
    for (int c = 0; c < 64; c++) {
        ulonglong2 wv = ((const ulonglong2*)(g_w2d + c * 64))[lane];
        const float* xr = xin + c * XST2 + P;
#pragma unroll
        for (int t2 = 0; t2 < 4; t2++) {
            ulonglong2 hh = *(const ulonglong2*)(xr + 4 * t2);
            acc0[2 * t2]     = fma2(hh.x, wv.x, acc0[2 * t2]);
            acc1[2 * t2]     = fma2(hh.x, wv.y, acc1[2 * t2]);
            acc0[2 * t2 + 1] = fma2(hh.y, wv.x, acc0[2 * t2 + 1]);
            acc1[2 * t2 + 1] = fma2(hh.y, wv.y, acc1[2 * t2 + 1]);
        }
    }
    float s0 = 0.f, s1 = 0.f, q0 = 0.f, q1 = 0.f;
#pragma unroll
    for (int t = 0; t < 8; t++) {
        float a0l, a0h, a1l, a1h;
        upk(acc0[t], a0l, a0h);
        upk(acc1[t], a1l, a1h);
        int p = p0 + P + 2 * t;
        float2 s0v; s0v.x = a0l; s0v.y = a1l;
        float2 s1v; s1v.x = a0h; s1v.y = a1h;
        ((float2*)(g_y2 + (size_t)p * 64))[lane] = s0v;
        ((float2*)(g_y2 + (size_t)(p + 1) * 64))[lane] = s1v;
        s0 += a0l + a0h; s1 += a1l + a1h;
        q0 = fmaf(a0l, a0l, q0); q0 = fmaf(a0h, a0h, q0);
        q1 = fmaf(a1l, a1l, q1); q1 = fmaf(a1h, a1h, q1);
    }
    atomicAdd(&ssum[2 * lane], s0);     atomicAdd(&ssum[2 * lane + 1], s1);
    atomicAdd(&ssq[2 * lane], q0);      atomicAdd(&ssq[2 * lane + 1], q1);
    __syncthreads();
    if (tid < 64) {
        atomicAdd(&g_stats[128 + tid], (double)ssum[tid]);
        atomicAdd(&g_stats[192 + tid], (double)ssq[tid]);
    }
    __threadfence();
    __syncthreads();
    if (tid == 0) slast = (atomicAdd(&g_cnt2, 1) == L2_GRID - 1);
    __syncthreads();
    if (slast) {
        bnp_tail(g2, beta2, 64, 128, 128, tid);
        if (tid == 0) g_cnt2 = 0;
    }
}

// ---------------- 4: layer 3 (f32x2, 64 pos/block, 2 ch/lane, 4 blocks/SM) + bnp3 tail ----------------
#define XST3 68
#define L3_GRID ((BB * SS * KK) / 64)
__global__ __launch_bounds__(256, 4) void layer3_kernel(const float* __restrict__ b3,
                                                        const float* __restrict__ g3,
                                                        const float* __restrict__ beta3) {
    __shared__ float xin[64 * XST3];                  // 17.4 KB
    __shared__ float ssum[128], ssq[128], smax[4][128];
    __shared__ int slast;
    int tid = threadIdx.x;
    int p0 = blockIdx.x * 64;
    if (tid < 128) { ssum[tid] = 0.f; ssq[tid] = 0.f; }
    for (int i = tid; i < 64 * 64; i += 256) {
        int p = i >> 6, c = i & 63;
        float y = g_y2[(size_t)(p0 + p) * 64 + c];
        xin[c * XST3 + p] = fmaxf(fmaf(g_bn[128 + c], y, g_bn[192 + c]), 0.f);
    }
    __syncthreads();
    int wid = tid >> 5, lane = tid & 31;
    int strip = wid >> 1;                             // 0..3 (16 positions each)
    int half = wid & 1;                               // channel half
    int P = strip * 16;
    int och = half * 64 + 2 * lane;                   // 2 channels per lane
    float2 bb = ((const float2*)b3)[och >> 1];
    ull acc0[8], acc1[8];
#pragma unroll
    for (int t = 0; t < 8; t++) { acc0[t] = pk(bb.x, bb.x); acc1[t] = pk(bb.y, bb.y); }
    for (int c = 0; c < 64; c++) {
        ulonglong2 wv = *(const ulonglong2*)(g_w3d + c * 128 + och);
        const float* xr = xin + c * XST3 + P;
#pragma unroll
        for (int t2 = 0; t2 < 4; t2++) {
            ulonglong2 hh = *(const ulonglong2*)(xr + 4 * t2);
            acc0[2 * t2]     = fma2(hh.x, wv.x, acc0[2 * t2]);
            acc1[2 * t2]     = fma2(hh.x, wv.y, acc1[2 * t2]);
            acc0[2 * t2 + 1] = fma2(hh.y, wv.x, acc0[2 * t2 + 1]);
            acc1[2 * t2 + 1] = fma2(hh.y, wv.y, acc1[2 * t2 + 1]);
        }
    }
#pragma unroll
    for (int ch = 0; ch < 2; ch++) {
        float m = -1e30f, s = 0.f, q = 0.f;
#pragma unroll
        for (int t = 0; t < 8; t++) {
            float lo, hi;
            upk(ch ? acc1[t] : acc0[t], lo, hi);
            m = fmaxf(m, fmaxf(lo, hi));
            s += lo + hi;
            q = fmaf(lo, lo, q); q = fmaf(hi, hi, q);
        }
        int o = och + ch;
        smax[strip][o] = m;
        atomicAdd(&ssum[o], s);
        atomicAdd(&ssq[o], q);
    }
    __syncthreads();
    // 2 groups per block; group gi covered by strips {2gi, 2gi+1}
    {
        int o = tid & 127;
        int gi = tid >> 7;                            // 0..1
        float mm = fmaxf(smax[2 * gi][o], smax[2 * gi + 1][o]);
        g_ymax[((size_t)blockIdx.x * 2 + gi) * 128 + o] = mm;
    }
    if (tid < 128) {
        atomicAdd(&g_stats[256 + tid], (double)ssum[tid]);
        atomicAdd(&g_stats[384 + tid], (double)ssq[tid]);
    }
    __threadfence();
    __syncthreads();
    if (tid == 0) slast = (atomicAdd(&g_cnt3, 1) == L3_GRID - 1);
    __syncthreads();
    if (slast) {
        bnp_tail(g3, beta3, 128, 256, 256, tid);
        if (tid == 0) g_cnt3 = 0;
    }
}

// ---------------- 5: finalize new_points = relu(BN3(max-pooled y3)) ----------------
__global__ void finalize_kernel(float* __restrict__ out) {
    int i = blockIdx.x * 256 + threadIdx.x;
    int o = i & 127;
    out[BB * SS * 3 + i] = fmaxf(fmaf(g_bn[256 + o], g_ymax[i], g_bn[384 + o]), 0.f);
}

extern "C" void kernel_launch(void* const* d_in, const int* in_sizes, int n_in,
                              void* d_out, int out_size) {
    const float* xyz   = (const float*)d_in[0];
    const float* pts   = (const float*)d_in[1];
    const float* w1    = (const float*)d_in[2];
    const float* b1    = (const float*)d_in[3];
    const float* g1    = (const float*)d_in[4];
    const float* beta1 = (const float*)d_in[5];
    const float* w2    = (const float*)d_in[6];
    const float* b2    = (const float*)d_in[7];
    const float* g2    = (const float*)d_in[8];
    const float* beta2 = (const float*)d_in[9];
    const float* w3    = (const float*)d_in[10];
    const float* b3    = (const float*)d_in[11];
    const float* g3    = (const float*)d_in[12];
    const float* beta3 = (const float*)d_in[13];
    float* out = (float*)d_out;

    cudaFuncSetAttribute(fps_u_kernel, cudaFuncAttributeMaxDynamicSharedMemorySize,
                         U_SMEM_BYTES);
    fps_u_kernel<<<560, 512, U_SMEM_BYTES>>>(xyz, pts, w1, w2, w3, out);
    ballq_stats_kernel<<<BQ_GRID, 256>>>(xyz, out, w1, b1, g1, beta1);
    layer2_kernel<<<L2_GRID, 256>>>(b2, g2, beta2);
    layer3_kernel<<<L3_GRID, 256>>>(b3, g3, beta3);
    finalize_kernel<<<(BB * SS * 128) / 256, 256>>>(out);
}

// round 14
// speedup vs baseline: 1.8529x; 1.0404x over previous
#include <cuda_runtime.h>
#include <cstdint>

#define BB 16
#define NN 4096
#define SS 1024
#define KK 32
#define C1 67
#define CNT_BN 524288.0

typedef unsigned long long ull;

// ---------------- device scratch (no allocation allowed) ----------------
__device__ __align__(16) float  g_u[BB * NN * 64];              // 16.8 MB
__device__ __align__(16) float  g_v[BB * SS * 64];              // 4.2 MB
__device__            int       g_idx[BB * SS * KK];            // 2 MB
__device__ __align__(16) float  g_y2[(size_t)BB * SS * KK * 64];// 134 MB
__device__ __align__(16) float  g_ymax[BB * SS * 128];          // 8.4 MB
__device__            double    g_stats[512];  // L1: sum@0 sq@64 | L2: 128/192 | L3: 256/384
__device__            float     g_bn[512];     // a1@0 c1@64 | a2@128 c2@192 | a3@256 c3@384
__device__ __align__(16) float  g_w2t[64 * 64];                 // transposed W2^T (plain)
__device__ __align__(16) float  g_w3t[64 * 128];                // transposed W3^T (plain)
__device__            int       g_cnt1 = 0, g_cnt2 = 0, g_cnt3 = 0;  // last-block tickets

// ---------------- f32x2 helpers ----------------
__device__ __forceinline__ ull fma2(ull a, ull b, ull c) {
    ull d;
    asm("fma.rn.f32x2 %0, %1, %2, %3;" : "=l"(d) : "l"(a), "l"(b), "l"(c));
    return d;
}
__device__ __forceinline__ ull add2(ull a, ull b) {
    ull d;
    asm("add.rn.f32x2 %0, %1, %2;" : "=l"(d) : "l"(a), "l"(b));
    return d;
}
__device__ __forceinline__ ull mul2(ull a, ull b) {
    ull d;
    asm("mul.rn.f32x2 %0, %1, %2;" : "=l"(d) : "l"(a), "l"(b));
    return d;
}
__device__ __forceinline__ ull pk(float a, float b) {
    ull r;
    asm("mov.b64 %0, {%1, %2};" : "=l"(r) : "f"(a), "f"(b));
    return r;
}
__device__ __forceinline__ void upk(ull v, float& a, float& b) {
    asm("mov.b64 {%0, %1}, %2;" : "=f"(a), "=f"(b) : "l"(v));
}

// ---------------- BN param fold (runs in last block of producer kernel) ----------------
__device__ __forceinline__ void bnp_tail(const float* gamma, const float* beta,
                                         int nch, int stats_off, int bn_off, int tid) {
    if (tid < nch) {
        volatile double* vs = g_stats;               // read-through to L2 (atomics' home)
        double mean = vs[stats_off + tid] / CNT_BN;
        double var = vs[stats_off + nch + tid] / CNT_BN - mean * mean;
        double a = (double)gamma[tid] / sqrt(var + 1e-5);
        g_bn[bn_off + tid] = (float)a;
        g_bn[bn_off + nch + tid] = (float)((double)beta[tid] - mean * a);
    }
}

// ================= 1: combined FPS + u + prep  =================
// grid 560 x 512 threads, dynamic smem 116 KB (forces 1 block/SM -> FPS exclusivity)
#define XST1 132
#define U_SMEM_BYTES (116 * 1024)                    // > 228KB/2 -> exactly 1 block/SM

__global__ __launch_bounds__(512) void fps_u_kernel(
        const float* __restrict__ xyz, const float* __restrict__ pts,
        const float* __restrict__ w1, const float* __restrict__ w2,
        const float* __restrict__ w3, float* __restrict__ out_xyz) {
    extern __shared__ char dyns[];
    int bid = blockIdx.x;
    int tid = threadIdx.x;
    int lane = tid & 31, wid = tid >> 5;

    if (bid < BB) {
        // ---------------- FPS (bit-exact, single barrier/iter) ----------------
        unsigned* smaxb = (unsigned*)dyns;            // [2][16]
        int* sidxv = (int*)(dyns + 128);              // [2][16]
        int b = bid;
        const float* xb = xyz + (size_t)b * NN * 3;
        ull px[4], py[4], pz[4];
        float dist[8];
        int base = tid * 8;
#pragma unroll
        for (int t = 0; t < 4; t++) {
            int j0 = base + 2 * t, j1 = j0 + 1;
            px[t] = pk(xb[j0 * 3 + 0], xb[j1 * 3 + 0]);
            py[t] = pk(xb[j0 * 3 + 1], xb[j1 * 3 + 1]);
            pz[t] = pk(xb[j0 * 3 + 2], xb[j1 * 3 + 2]);
            dist[2 * t] = 1e10f;
            dist[2 * t + 1] = 1e10f;
        }
        float cx = xb[0], cy = xb[1], cz = xb[2];
        if (tid == 0) {
            float* op = out_xyz + (size_t)b * SS * 3;
            op[0] = cx; op[1] = cy; op[2] = cz;
        }
        for (int i = 0; i < SS - 1; i++) {
            ull ncx = pk(-cx, -cx);
            ull ncy = pk(-cy, -cy);
            ull ncz = pk(-cz, -cz);
            float lmax = -1.0f; int lidx = 0;
#pragma unroll
            for (int t = 0; t < 4; t++) {
                ull dx = add2(px[t], ncx);            // add(x,-c) == sub(x,c) bitwise
                ull dy = add2(py[t], ncy);
                ull dz = add2(pz[t], ncz);
                ull s = add2(add2(mul2(dx, dx), mul2(dy, dy)), mul2(dz, dz));
                float slo, shi;
                upk(s, slo, shi);
                float d0 = fminf(dist[2 * t], slo);
                float d1 = fminf(dist[2 * t + 1], shi);
                dist[2 * t] = d0;
                dist[2 * t + 1] = d1;
                if (d0 > lmax) { lmax = d0; lidx = base + 2 * t; }
                if (d1 > lmax) { lmax = d1; lidx = base + 2 * t + 1; }
            }
            unsigned mb = __float_as_uint(lmax);
            unsigned wm = __reduce_max_sync(0xffffffffu, mb);
            int cand = (mb == wm) ? lidx : 0x7fffffff;
            int wi = __reduce_min_sync(0xffffffffu, cand);
            int par = i & 1;
            if (lane == 0) { smaxb[par * 16 + wid] = wm; sidxv[par * 16 + wid] = wi; }
            __syncthreads();
            unsigned vb = (lane < 16) ? smaxb[par * 16 + lane] : 0u;
            int vi = (lane < 16) ? sidxv[par * 16 + lane] : 0x7fffffff;
            unsigned m2 = __reduce_max_sync(0xffffffffu, vb);
            int c2 = (vb == m2) ? vi : 0x7fffffff;
            int far = __reduce_min_sync(0xffffffffu, c2);
            const float* cp = xb + (size_t)far * 3;
            cx = cp[0]; cy = cp[1]; cz = cp[2];
            if (tid == 0) {
                float* op = out_xyz + ((size_t)b * SS + i + 1) * 3;
                op[0] = cx; op[1] = cy; op[2] = cz;
            }
        }
    } else if (bid < 528) {
        // ---------------- u: 128 points/block, 512 threads ----------------
        float* wsm = (float*)dyns;                    // [C1][64] transposed, plain floats
        float* xin = (float*)(dyns + C1 * 64 * 4);    // [C1][XST1] channel-major
        int p0 = (bid - 16) * 128;
        for (int i = tid; i < C1 * 64; i += 512) {
            int c = i >> 6, o = i & 63;
            wsm[i] = w1[o * C1 + c];
        }
        for (int i = tid; i < 68 * 128; i += 512) {
            int p = i / 68, c = i % 68;
            if (c < C1) {
                float v = (c < 3) ? xyz[(size_t)(p0 + p) * 3 + c]
                                  : pts[(size_t)(p0 + p) * 64 + (c - 3)];
                xin[c * XST1 + p] = v;
            }
        }
        __syncthreads();
        int P = wid * 8;                               // 8 positions per warp
        ull a0[4], a1[4];
#pragma unroll
        for (int t = 0; t < 4; t++) { a0[t] = 0ull; a1[t] = 0ull; }
        for (int c = 0; c < C1; c++) {
            float2 wv2 = ((const float2*)(wsm + c * 64))[lane];
            ull wx = pk(wv2.x, wv2.x), wy = pk(wv2.y, wv2.y);
            const float* xr = xin + c * XST1 + P;
            ulonglong2 h0 = *(const ulonglong2*)(xr);
            ulonglong2 h1 = *(const ulonglong2*)(xr + 4);
            a0[0] = fma2(h0.x, wx, a0[0]); a1[0] = fma2(h0.x, wy, a1[0]);
            a0[1] = fma2(h0.y, wx, a0[1]); a1[1] = fma2(h0.y, wy, a1[1]);
            a0[2] = fma2(h1.x, wx, a0[2]); a1[2] = fma2(h1.x, wy, a1[2]);
            a0[3] = fma2(h1.y, wx, a0[3]); a1[3] = fma2(h1.y, wy, a1[3]);
        }
#pragma unroll
        for (int t = 0; t < 4; t++) {
            float a0l, a0h, a1l, a1h;
            upk(a0[t], a0l, a0h);
            upk(a1[t], a1l, a1h);
            int p = p0 + P + 2 * t;
            float2 s0; s0.x = a0l; s0.y = a1l;
            float2 s1; s1.x = a0h; s1.y = a1h;
            ((float2*)(g_u + (size_t)p * 64))[lane] = s0;
            ((float2*)(g_u + (size_t)(p + 1) * 64))[lane] = s1;
        }
    } else {
        // ---------------- prep ----------------
        int i = (bid - 528) * 512 + tid;               // 0..16383
        if (i < 512) g_stats[i] = 0.0;
        if (i < 64 * 64) {
            int c = i >> 6, o = i & 63;
            g_w2t[i] = w2[o * 64 + c];
        }
        if (i < 64 * 128) {
            int c = i >> 7, o = i & 127;
            g_w3t[i] = w3[o * 64 + c];
        }
    }
}

// ---------------- 2: ball query + fused v + fused BN1 stats + bnp1 tail ----------------
#define BQ_GRID ((BB * SS) / 8)
__global__ __launch_bounds__(256) void ballq_stats_kernel(
        const float* __restrict__ xyz, const float* __restrict__ newxyz,
        const float* __restrict__ w1, const float* __restrict__ b1,
        const float* __restrict__ g1, const float* __restrict__ beta1) {
    __shared__ float red[2][8][64];
    __shared__ int slast;
    int wid = threadIdx.x >> 5;
    int gw = blockIdx.x * 8 + wid;
    int lane = threadIdx.x & 31;
    int b = gw >> 10;
    const float* cp = newxyz + (size_t)gw * 3;
    float sx = cp[0], sy = cp[1], sz = cp[2];
    float sn = __fadd_rn(__fadd_rn(__fmul_rn(sx, sx), __fmul_rn(sy, sy)), __fmul_rn(sz, sz));
    const float* xb = xyz + (size_t)b * NN * 3;
    const float R2 = (float)(0.2 * 0.2);
    int cnt = 0, first = -1;
    int* op = g_idx + (size_t)gw * KK;
    for (int basep = 0; basep < NN && cnt < KK; basep += 32) {
        int n = basep + lane;
        float nx = xb[n * 3 + 0], ny = xb[n * 3 + 1], nz = xb[n * 3 + 2];
        float dn = __fadd_rn(__fadd_rn(__fmul_rn(nx, nx), __fmul_rn(ny, ny)), __fmul_rn(nz, nz));
        float dt = __fadd_rn(__fadd_rn(__fmul_rn(sx, nx), __fmul_rn(sy, ny)), __fmul_rn(sz, nz));
        float sqr = __fadd_rn(__fadd_rn(__fmul_rn(-2.0f, dt), sn), dn);
        bool ok = !(sqr > R2);
        unsigned bal = __ballot_sync(0xffffffffu, ok);
        if (first < 0 && bal) first = basep + (__ffs(bal) - 1);
        int pos = cnt + __popc(bal & ((1u << lane) - 1u));
        if (ok && pos < KK) op[pos] = n;
        cnt += __popc(bal);
    }
    for (int s = cnt + lane; s < KK; s += 32) op[s] = first;
    // fused v: 2 output channels per lane
    int o = 2 * lane;
    const float* wr0 = w1 + (size_t)o * C1;
    const float* wr1 = wr0 + C1;
    float2 vv;
    vv.x = b1[o]     - (wr0[0] * sx + wr0[1] * sy + wr0[2] * sz);
    vv.y = b1[o + 1] - (wr1[0] * sx + wr1[1] * sy + wr1[2] * sz);
    ((float2*)(g_v + (size_t)gw * 64))[lane] = vv;
    // fused BN1 stats for this group: indices via shfl (no g_idx re-gather pass)
    __syncwarp();
    int idxv = op[lane];                              // warp's 32 indices, one per lane
    const float* ub = g_u + (((size_t)b) << 12) * 64;
    float s0 = 0.f, s1 = 0.f, q0 = 0.f, q1 = 0.f;
#pragma unroll 4
    for (int k = 0; k < KK; k++) {
        int pt = __shfl_sync(0xffffffffu, idxv, k);
        float2 u = ((const float2*)(ub + (size_t)pt * 64))[lane];
        float y0 = u.x + vv.x, y1 = u.y + vv.y;
        s0 += y0; s1 += y1;
        q0 = fmaf(y0, y0, q0); q1 = fmaf(y1, y1, q1);
    }
    red[0][wid][2 * lane] = s0; red[0][wid][2 * lane + 1] = s1;
    red[1][wid][2 * lane] = q0; red[1][wid][2 * lane + 1] = q1;
    __syncthreads();
    int tid = threadIdx.x;
    if (tid < 64) {
        double ds = 0.0, dq = 0.0;
#pragma unroll
        for (int r = 0; r < 8; r++) { ds += red[0][r][tid]; dq += red[1][r][tid]; }
        atomicAdd(&g_stats[0 + tid], ds);
        atomicAdd(&g_stats[64 + tid], dq);
    }
    __threadfence();
    __syncthreads();
    if (tid == 0) slast = (atomicAdd(&g_cnt1, 1) == BQ_GRID - 1);
    __syncthreads();
    if (slast) {
        bnp_tail(g1, beta1, 64, 0, 0, tid);
        if (tid == 0) g_cnt1 = 0;                    // reset for graph replay
    }
}

// ---------------- 3: layer 2 (f32x2, un-dup'd weights) + bnp2 tail ----------------
#define XST2 132
#define L2_GRID ((BB * SS * KK) / 128)
__global__ __launch_bounds__(256, 4) void layer2_kernel(const float* __restrict__ b2,
                                                        const float* __restrict__ g2,
                                                        const float* __restrict__ beta2) {
    __shared__ float xin[64 * XST2];
    __shared__ float ssum[64], ssq[64];
    __shared__ int slast;
    int tid = threadIdx.x;
    int p0 = blockIdx.x * 128;
    if (tid < 64) { ssum[tid] = 0.f; ssq[tid] = 0.f; }
    for (int i = tid; i < 128 * 64; i += 256) {
        int p = i >> 6, c = i & 63;
        int inst = p0 + p;
        int g = inst >> 5;
        int b = g >> 10;
        int pt = g_idx[inst];
        float y = g_u[(((size_t)b << 12) + pt) * 64 + c] + g_v[(size_t)g * 64 + c];
        xin[c * XST2 + p] = fmaxf(fmaf(g_bn[c], y, g_bn[64 + c]), 0.f);
    }
    __syncthreads();
    int wid = tid >> 5, lane = tid & 31;
    int P = wid * 16;
    float2 bb = ((const float2*)b2)[lane];
    ull bi0 = pk(bb.x, bb.x), bi1 = pk(bb.y, bb.y);
    ull acc0[8], acc1[8];
#pragma unroll
    for (int t = 0; t < 8; t++) { acc0[t] = bi0; acc1[t] = bi1; }
    for (int c = 0; c < 64; c++) {
        float2 wv2 = ((const float2*)(g_w2t + c * 64))[lane];
        ull wx = pk(wv2.x, wv2.x), wy = pk(wv2.y, wv2.y);
        const float* xr = xin + c * XST2 + P;
#pragma unroll
        for (int t2 = 0; t2 < 4; t2++) {
            ulonglong2 hh = *(const ulonglong2*)(xr + 4 * t2);
            acc0[2 * t2]     = fma2(hh.x, wx, acc0[2 * t2]);
            acc1[2 * t2]     = fma2(hh.x, wy, acc1[2 * t2]);
            acc0[2 * t2 + 1] = fma2(hh.y, wx, acc0[2 * t2 + 1]);
            acc1[2 * t2 + 1] = fma2(hh.y, wy, acc1[2 * t2 + 1]);
        }
    }
    float s0 = 0.f, s1 = 0.f, q0 = 0.f, q1 = 0.f;
#pragma unroll
    for (int t = 0; t < 8; t++) {
        float a0l, a0h, a1l, a1h;
        upk(acc0[t], a0l, a0h);
        upk(acc1[t], a1l, a1h);
        int p = p0 + P + 2 * t;
        float2 s0v; s0v.x = a0l; s0v.y = a1l;
        float2 s1v; s1v.x = a0h; s1v.y = a1h;
        ((float2*)(g_y2 + (size_t)p * 64))[lane] = s0v;
        ((float2*)(g_y2 + (size_t)(p + 1) * 64))[lane] = s1v;
        s0 += a0l + a0h; s1 += a1l + a1h;
        q0 = fmaf(a0l, a0l, q0); q0 = fmaf(a0h, a0h, q0);
        q1 = fmaf(a1l, a1l, q1); q1 = fmaf(a1h, a1h, q1);
    }
    atomicAdd(&ssum[2 * lane], s0);     atomicAdd(&ssum[2 * lane + 1], s1);
    atomicAdd(&ssq[2 * lane], q0);      atomicAdd(&ssq[2 * lane + 1], q1);
    __syncthreads();
    if (tid < 64) {
        atomicAdd(&g_stats[128 + tid], (double)ssum[tid]);
        atomicAdd(&g_stats[192 + tid], (double)ssq[tid]);
    }
    __threadfence();
    __syncthreads();
    if (tid == 0) slast = (atomicAdd(&g_cnt2, 1) == L2_GRID - 1);
    __syncthreads();
    if (slast) {
        bnp_tail(g2, beta2, 64, 128, 128, tid);
        if (tid == 0) g_cnt2 = 0;
    }
}

// ---------------- 4: layer 3 (f32x2, un-dup'd weights, 64 pos/block) + bnp3 tail ----------------
#define XST3 68
#define L3_GRID ((BB * SS * KK) / 64)
__global__ __launch_bounds__(256, 4) void layer3_kernel(const float* __restrict__ b3,
                                                        const float* __restrict__ g3,
                                                        const float* __restrict__ beta3) {
    __shared__ float xin[64 * XST3];                  // 17.4 KB
    __shared__ float ssum[128], ssq[128], smax[4][128];
    __shared__ int slast;
    int tid = threadIdx.x;
    int p0 = blockIdx.x * 64;
    if (tid < 128) { ssum[tid] = 0.f; ssq[tid] = 0.f; }
    for (int i = tid; i < 64 * 64; i += 256) {
        int p = i >> 6, c = i & 63;
        float y = g_y2[(size_t)(p0 + p) * 64 + c];
        xin[c * XST3 + p] = fmaxf(fmaf(g_bn[128 + c], y, g_bn[192 + c]), 0.f);
    }
    __syncthreads();
    int wid = tid >> 5, lane = tid & 31;
    int strip = wid >> 1;                             // 0..3 (16 positions each)
    int half = wid & 1;                               // channel half
    int P = strip * 16;
    int och = half * 64 + 2 * lane;                   // 2 channels per lane
    float2 bb = ((const float2*)b3)[och >> 1];
    ull acc0[8], acc1[8];
#pragma unroll
    for (int t = 0; t < 8; t++) { acc0[t] = pk(bb.x, bb.x); acc1[t] = pk(bb.y, bb.y); }
    for (int c = 0; c < 64; c++) {
        float2 wv2 = *(const float2*)(g_w3t + c * 128 + och);
        ull wx = pk(wv2.x, wv2.x), wy = pk(wv2.y, wv2.y);
        const float* xr = xin + c * XST3 + P;
#pragma unroll
        for (int t2 = 0; t2 < 4; t2++) {
            ulonglong2 hh = *(const ulonglong2*)(xr + 4 * t2);
            acc0[2 * t2]     = fma2(hh.x, wx, acc0[2 * t2]);
            acc1[2 * t2]     = fma2(hh.x, wy, acc1[2 * t2]);
            acc0[2 * t2 + 1] = fma2(hh.y, wx, acc0[2 * t2 + 1]);
            acc1[2 * t2 + 1] = fma2(hh.y, wy, acc1[2 * t2 + 1]);
        }
    }
#pragma unroll
    for (int ch = 0; ch < 2; ch++) {
        float m = -1e30f, s = 0.f, q = 0.f;
#pragma unroll
        for (int t = 0; t < 8; t++) {
            float lo, hi;
            upk(ch ? acc1[t] : acc0[t], lo, hi);
            m = fmaxf(m, fmaxf(lo, hi));
            s += lo + hi;
            q = fmaf(lo, lo, q); q = fmaf(hi, hi, q);
        }
        int o = och + ch;
        smax[strip][o] = m;
        atomicAdd(&ssum[o], s);
        atomicAdd(&ssq[o], q);
    }
    __syncthreads();
    // 2 groups per block; group gi covered by strips {2gi, 2gi+1}
    {
        int o = tid & 127;
        int gi = tid >> 7;                            // 0..1
        float mm = fmaxf(smax[2 * gi][o], smax[2 * gi + 1][o]);
        g_ymax[((size_t)blockIdx.x * 2 + gi) * 128 + o] = mm;
    }
    if (tid < 128) {
        atomicAdd(&g_stats[256 + tid], (double)ssum[tid]);
        atomicAdd(&g_stats[384 + tid], (double)ssq[tid]);
    }
    __threadfence();
    __syncthreads();
    if (tid == 0) slast = (atomicAdd(&g_cnt3, 1) == L3_GRID - 1);
    __syncthreads();
    if (slast) {
        bnp_tail(g3, beta3, 128, 256, 256, tid);
        if (tid == 0) g_cnt3 = 0;
    }
}

// ---------------- 5: finalize new_points = relu(BN3(max-pooled y3)) ----------------
__global__ void finalize_kernel(float* __restrict__ out) {
    int i = blockIdx.x * 256 + threadIdx.x;
    int o = i & 127;
    out[BB * SS * 3 + i] = fmaxf(fmaf(g_bn[256 + o], g_ymax[i], g_bn[384 + o]), 0.f);
}

extern "C" void kernel_launch(void* const* d_in, const int* in_sizes, int n_in,
                              void* d_out, int out_size) {
    const float* xyz   = (const float*)d_in[0];
    const float* pts   = (const float*)d_in[1];
    const float* w1    = (const float*)d_in[2];
    const float* b1    = (const float*)d_in[3];
    const float* g1    = (const float*)d_in[4];
    const float* beta1 = (const float*)d_in[5];
    const float* w2    = (const float*)d_in[6];
    const float* b2    = (const float*)d_in[7];
    const float* g2    = (const float*)d_in[8];
    const float* beta2 = (const float*)d_in[9];
    const float* w3    = (const float*)d_in[10];
    const float* b3    = (const float*)d_in[11];
    const float* g3    = (const float*)d_in[12];
    const float* beta3 = (const float*)d_in[13];
    float* out = (float*)d_out;

    cudaFuncSetAttribute(fps_u_kernel, cudaFuncAttributeMaxDynamicSharedMemorySize,
                         U_SMEM_BYTES);
    fps_u_kernel<<<560, 512, U_SMEM_BYTES>>>(xyz, pts, w1, w2, w3, out);
    ballq_stats_kernel<<<BQ_GRID, 256>>>(xyz, out, w1, b1, g1, beta1);
    layer2_kernel<<<L2_GRID, 256>>>(b2, g2, beta2);
    layer3_kernel<<<L3_GRID, 256>>>(b3, g3, beta3);
    finalize_kernel<<<(BB * SS * 128) / 256, 256>>>(out);
}